// round 4
// baseline (speedup 1.0000x reference)
#include <cuda_runtime.h>
#include <cstdint>
#include <cstddef>

// ---------------- static scratch ----------------
__device__ float g_h[4 * 16384 * 256];
__device__ float g_tmp[4 * 16384 * 256];
__device__ float g_out[4 * 16384 * 256];
__device__ float g_esrc[4 * 16384];
__device__ float g_edst[4 * 16384];
__device__ float g_meanp[64 * 8 * 256];

// ---------------- 128x128x8 fp32 GEMM, C = A@B (+bias), double-buffered ----------------
__global__ void __launch_bounds__(256, 2)
sgemm_nn(const float* __restrict__ Ab, const float* __restrict__ Bb,
         float* __restrict__ Cb, const float* __restrict__ biasb,
         int M, int N, int K,
         size_t sA, size_t sB, size_t sC, size_t sBias)
{
    const float* A = Ab + (size_t)blockIdx.z * sA;
    const float* B = Bb + (size_t)blockIdx.z * sB;
    float* C = Cb + (size_t)blockIdx.z * sC;
    const float* bias = biasb ? biasb + (size_t)blockIdx.z * sBias : nullptr;

    __shared__ float As[2][8][128];
    __shared__ float Bs[2][8][128];

    const int tid = threadIdx.x;
    const int row0 = blockIdx.y * 128;
    const int col0 = blockIdx.x * 128;

    const int arow = tid >> 1;
    const int acol = (tid & 1) * 4;
    const int brow = tid >> 5;
    const int bcol = (tid & 31) * 4;

    const int ty = tid >> 4, tx = tid & 15;
    const int r0 = ty * 8, c0 = tx * 8;

    const float* Aptr = A + (size_t)(row0 + arow) * K + acol;
    const float* Bptr = B + (size_t)brow * N + col0 + bcol;

    float acc[8][8];
#pragma unroll
    for (int i = 0; i < 8; i++)
#pragma unroll
        for (int j = 0; j < 8; j++) acc[i][j] = 0.f;

    int buf = 0;
    {
        float4 av = *(const float4*)(Aptr);
        float4 bv = *(const float4*)(Bptr);
        As[0][acol + 0][arow] = av.x; As[0][acol + 1][arow] = av.y;
        As[0][acol + 2][arow] = av.z; As[0][acol + 3][arow] = av.w;
        *(float4*)&Bs[0][brow][bcol] = bv;
    }
    __syncthreads();

    const int nT = K >> 3;
    for (int t = 0; t < nT; ++t) {
        float4 av2, bv2;
        if (t + 1 < nT) {
            av2 = *(const float4*)(Aptr + (t + 1) * 8);
            bv2 = *(const float4*)(Bptr + (size_t)(t + 1) * 8 * N);
        }
#pragma unroll
        for (int kk = 0; kk < 8; kk++) {
            float a[8], b[8];
            *(float4*)(a)     = *(const float4*)&As[buf][kk][r0];
            *(float4*)(a + 4) = *(const float4*)&As[buf][kk][r0 + 4];
            *(float4*)(b)     = *(const float4*)&Bs[buf][kk][c0];
            *(float4*)(b + 4) = *(const float4*)&Bs[buf][kk][c0 + 4];
#pragma unroll
            for (int i = 0; i < 8; i++)
#pragma unroll
                for (int j = 0; j < 8; j++) acc[i][j] += a[i] * b[j];
        }
        if (t + 1 < nT) {
            buf ^= 1;
            As[buf][acol + 0][arow] = av2.x; As[buf][acol + 1][arow] = av2.y;
            As[buf][acol + 2][arow] = av2.z; As[buf][acol + 3][arow] = av2.w;
            *(float4*)&Bs[buf][brow][bcol] = bv2;
            __syncthreads();
        }
    }

#pragma unroll
    for (int i = 0; i < 8; i++) {
        size_t cr = (size_t)(row0 + r0 + i) * N + col0 + c0;
#pragma unroll
        for (int j = 0; j < 8; j++) {
            float v = acc[i][j];
            if (bias) v += bias[col0 + c0 + j];
            C[cr + j] = v;
        }
    }
}

// ---------------- LN over H=256 per row, fused e_src/e_dst GEMVs ----------------
__global__ void __launch_bounds__(256)
ln_esrc_kernel(const float* __restrict__ pre, float* __restrict__ h,
               const float* __restrict__ lng, const float* __restrict__ lnb,
               const float* __restrict__ Watt,
               float* __restrict__ esrc, float* __restrict__ edst)
{
    int w = (blockIdx.x * blockDim.x + threadIdx.x) >> 5;
    int lane = threadIdx.x & 31;
    int hd = w >> 14;
    const float* row = pre + (size_t)w * 256;

    float x[8];
    float s = 0.f;
#pragma unroll
    for (int i = 0; i < 8; i++) { x[i] = row[lane + 32 * i]; s += x[i]; }
#pragma unroll
    for (int off = 16; off > 0; off >>= 1) s += __shfl_xor_sync(0xffffffffu, s, off);
    float mu = s * (1.f / 256.f);

    float v = 0.f;
#pragma unroll
    for (int i = 0; i < 8; i++) { float d = x[i] - mu; v += d * d; }
#pragma unroll
    for (int off = 16; off > 0; off >>= 1) v += __shfl_xor_sync(0xffffffffu, v, off);
    float rstd = rsqrtf(v * (1.f / 256.f) + 1e-5f);

    float es = 0.f, ed = 0.f;
    float* hrow = h + (size_t)w * 256;
#pragma unroll
    for (int i = 0; i < 8; i++) {
        int c = lane + 32 * i;
        float y = (x[i] - mu) * rstd * lng[hd * 256 + c] + lnb[hd * 256 + c];
        hrow[c] = y;
        es += y * Watt[hd * 512 + c];
        ed += y * Watt[hd * 512 + 256 + c];
    }
#pragma unroll
    for (int off = 16; off > 0; off >>= 1) {
        es += __shfl_xor_sync(0xffffffffu, es, off);
        ed += __shfl_xor_sync(0xffffffffu, ed, off);
    }
    if (lane == 0) { esrc[w] = es; edst[w] = ed; }
}

// =====================================================================
// Fused: S = g @ h^T (32-row block), sigmoid in smem, per-warp radix-
// select quantile(0.7), masked leaky-relu softmax, sparse alpha@h.
// A = sigmoid(S) never touches HBM.
// grid (32, 16, 4), block 512, dynamic smem 196608 B.
// =====================================================================
#define FS_SMEM 196608
// smem layout (bytes):
//   [0,      131072) sS  float[32][1024]
//   [131072, 163840) sB  float[16][512]        (GEMM staging)
//   [163840, 196608) sG  float[256][32]        (GEMM staging)
// after GEMM phase (sB/sG dead):
//   [131072, 147456) hist u32 [16 warps][256]
//   [147456, 180224) list u16 [16 warps][1024]
__global__ void __launch_bounds__(512, 1)
attn_fused(const float* __restrict__ g, const float* __restrict__ h,
           const float* __restrict__ esrc, const float* __restrict__ edst,
           const float* __restrict__ batt, float* __restrict__ out)
{
    extern __shared__ char smemraw[];
    float* sS = (float*)smemraw;                      // [32][1024]
    float* sB = (float*)(smemraw + 131072);           // [16][512]
    float* sG = (float*)(smemraw + 163840);           // [256][32]

    const int tid = threadIdx.x;
    const int hd = blockIdx.z, b = blockIdx.y;
    const int i0 = blockIdx.x * 32;
    const int rowidx = hd * 16384 + b * 1024;

    // ---- stage g rows [i0, i0+32) : sG[k][r] ----
    {
        int r = tid >> 4;
        int kb = (tid & 15) * 16;
        const float* gr = g + (size_t)(rowidx + i0 + r) * 256 + kb;
#pragma unroll
        for (int q = 0; q < 4; q++) {
            float4 v = *(const float4*)(gr + q * 4);
            sG[(kb + q * 4 + 0) * 32 + r] = v.x;
            sG[(kb + q * 4 + 1) * 32 + r] = v.y;
            sG[(kb + q * 4 + 2) * 32 + r] = v.z;
            sG[(kb + q * 4 + 3) * 32 + r] = v.w;
        }
    }

    const int tr = tid >> 6;      // 0..7  -> rows tr*4 .. tr*4+3
    const int tc = tid & 63;      // 0..63 -> cols tc*8 .. tc*8+7 (within 512 chunk)

    for (int jc = 0; jc < 1024; jc += 512) {
        float acc[4][8];
#pragma unroll
        for (int i = 0; i < 4; i++)
#pragma unroll
            for (int j = 0; j < 8; j++) acc[i][j] = 0.f;

        for (int k0 = 0; k0 < 256; k0 += 16) {
            __syncthreads();
            // stage h[jc + tid][k0 .. k0+15] -> sB[kk][tid]
            {
                const float* hr = h + (size_t)(rowidx + jc + tid) * 256 + k0;
#pragma unroll
                for (int q = 0; q < 4; q++) {
                    float4 v = *(const float4*)(hr + q * 4);
                    sB[(q * 4 + 0) * 512 + tid] = v.x;
                    sB[(q * 4 + 1) * 512 + tid] = v.y;
                    sB[(q * 4 + 2) * 512 + tid] = v.z;
                    sB[(q * 4 + 3) * 512 + tid] = v.w;
                }
            }
            __syncthreads();
#pragma unroll
            for (int kk = 0; kk < 16; kk++) {
                float a[4], bb[8];
                *(float4*)(a)      = *(const float4*)&sG[(k0 + kk) * 32 + tr * 4];
                *(float4*)(bb)     = *(const float4*)&sB[kk * 512 + tc * 8];
                *(float4*)(bb + 4) = *(const float4*)&sB[kk * 512 + tc * 8 + 4];
#pragma unroll
                for (int i = 0; i < 4; i++)
#pragma unroll
                    for (int j = 0; j < 8; j++) acc[i][j] += a[i] * bb[j];
            }
        }
        // epilogue: A = sigmoid(S) into sS
#pragma unroll
        for (int i = 0; i < 4; i++) {
            float v[8];
#pragma unroll
            for (int j = 0; j < 8; j++) v[j] = 1.f / (1.f + expf(-acc[i][j]));
            float* dst = &sS[(tr * 4 + i) * 1024 + jc + tc * 8];
            *(float4*)(dst)     = make_float4(v[0], v[1], v[2], v[3]);
            *(float4*)(dst + 4) = make_float4(v[4], v[5], v[6], v[7]);
        }
    }
    __syncthreads();   // sS complete; sB/sG now dead

    // ================= attention phase: one warp per row ==============
    const int w = tid >> 5;
    const int lane = tid & 31;
    unsigned int* hist = (unsigned int*)(smemraw + 131072) + w * 256;
    unsigned short* lst = (unsigned short*)(smemraw + 147456) + w * 1024;
    const float fr = 0.7f * 1023.0f - 716.0f;
    const float bb = batt[hd];

    for (int rr = w; rr < 32; rr += 16) {
        const int i_row = i0 + rr;           // row index within L
        float* rowA = sS + rr * 1024;

        // ---- radix select: value at ascending rank 716 ----
        unsigned int prefval = 0u, maskhi = 0u;
        int rank = 716;
#pragma unroll
        for (int shift = 24; shift >= 0; shift -= 8) {
#pragma unroll
            for (int t = 0; t < 8; t++) hist[lane * 8 + t] = 0u;
            __syncwarp();
#pragma unroll
            for (int q = 0; q < 32; q++) {
                unsigned int k = __float_as_uint(rowA[q * 32 + lane]);
                if ((k & maskhi) == prefval)
                    atomicAdd(&hist[(k >> shift) & 255u], 1u);
            }
            __syncwarp();
            unsigned int h8[8]; unsigned int tot = 0u;
#pragma unroll
            for (int t = 0; t < 8; t++) { h8[t] = hist[lane * 8 + t]; tot += h8[t]; }
            unsigned int incl = tot;
#pragma unroll
            for (int off = 1; off < 32; off <<= 1) {
                unsigned int v = __shfl_up_sync(0xffffffffu, incl, off);
                if (lane >= off) incl += v;
            }
            unsigned int base = incl - tot;
            int bin = -1, nr = 0;
            unsigned int run = base;
#pragma unroll
            for (int t = 0; t < 8; t++) {
                unsigned int c = run + h8[t];
                if (bin < 0 && (unsigned int)rank >= run && (unsigned int)rank < c) {
                    bin = lane * 8 + t; nr = rank - (int)run;
                }
                run = c;
            }
            unsigned int mball = __ballot_sync(0xffffffffu, bin >= 0);
            int src = __ffs(mball) - 1;
            bin = __shfl_sync(0xffffffffu, bin, src);
            nr  = __shfl_sync(0xffffffffu, nr, src);
            prefval |= ((unsigned int)bin) << shift;
            maskhi  |= 0xFFu << shift;
            rank = nr;
        }
        const float v716 = __uint_as_float(prefval);

        // ---- rank 717: count <= v716 and min-above ----
        int cLE = 0; unsigned int mA = 0xFFFFFFFFu;
#pragma unroll
        for (int q = 0; q < 32; q++) {
            float a = rowA[q * 32 + lane];
            if (a <= v716) cLE++;
            else { unsigned int k = __float_as_uint(a); mA = (k < mA) ? k : mA; }
        }
#pragma unroll
        for (int off = 16; off > 0; off >>= 1) {
            cLE += __shfl_xor_sync(0xffffffffu, cLE, off);
            unsigned int o = __shfl_xor_sync(0xffffffffu, mA, off);
            mA = (o < mA) ? o : mA;
        }
        const float v717 = (cLE > 717) ? v716 : __uint_as_float(mA);
        const float delta = v716 + fr * (v717 - v716);

        // ---- mask compaction (warp scan; set identical, order permuted) ----
        int cnt = 0; unsigned short loc[32];
#pragma unroll
        for (int q = 0; q < 32; q++) {
            int j = q * 32 + lane;
            if (rowA[j] > delta || j == i_row) loc[cnt++] = (unsigned short)j;
        }
        int incl = cnt;
#pragma unroll
        for (int off = 1; off < 32; off <<= 1) {
            int v = __shfl_up_sync(0xffffffffu, incl, off);
            if (lane >= off) incl += v;
        }
        int base = incl - cnt;
        int total = __shfl_sync(0xffffffffu, incl, 31);
        for (int t = 0; t < cnt; t++) lst[base + t] = loc[t];
        __syncwarp();

        // ---- masked leaky-relu softmax (overwrite rowA[0..total)) ----
        const float eb = esrc[rowidx + i_row] + bb;
        float lmax = -3.4e38f;
        for (int p = lane; p < total; p += 32) {
            int j = lst[p];
            float e = eb + edst[rowidx + j];
            e = (e >= 0.f) ? e : 0.01f * e;
            rowA[p] = e;
            lmax = fmaxf(lmax, e);
        }
#pragma unroll
        for (int off = 16; off > 0; off >>= 1)
            lmax = fmaxf(lmax, __shfl_xor_sync(0xffffffffu, lmax, off));
        __syncwarp();
        float lsum = 0.f;
        for (int p = lane; p < total; p += 32) {
            float a = expf(rowA[p] - lmax);
            rowA[p] = a;
            lsum += a;
        }
#pragma unroll
        for (int off = 16; off > 0; off >>= 1)
            lsum += __shfl_xor_sync(0xffffffffu, lsum, off);
        const float inv = 1.f / lsum;
        __syncwarp();

        // ---- out_i[c] = sum_j alpha_j h[j][c]; lane owns 8 cols ----
        float a0 = 0.f, a1 = 0.f, a2 = 0.f, a3 = 0.f;
        float a4 = 0.f, a5 = 0.f, a6 = 0.f, a7 = 0.f;
        const float* hb = h + (size_t)rowidx * 256;
        for (int p = 0; p < total; p++) {
            int j = lst[p];
            float wgt = rowA[p];
            const float4* hr = (const float4*)(hb + (size_t)j * 256 + lane * 8);
            float4 x0 = hr[0], x1 = hr[1];
            a0 += wgt * x0.x; a1 += wgt * x0.y; a2 += wgt * x0.z; a3 += wgt * x0.w;
            a4 += wgt * x1.x; a5 += wgt * x1.y; a6 += wgt * x1.z; a7 += wgt * x1.w;
        }
        float* op = out + ((size_t)rowidx + i_row) * 256 + lane * 8;
        *(float4*)(op)     = make_float4(a0 * inv, a1 * inv, a2 * inv, a3 * inv);
        *(float4*)(op + 4) = make_float4(a4 * inv, a5 * inv, a6 * inv, a7 * inv);
    }
}

// ---------------- partial mean over L per (head,batch): 8 chunks of 128 ----------------
__global__ void __launch_bounds__(256)
mean_kernel(const float* __restrict__ o, float* __restrict__ meanp)
{
    int z = blockIdx.x;
    int ch = blockIdx.y;
    int c = threadIdx.x;
    const float* p = o + (size_t)z * 262144 + (size_t)ch * 128 * 256 + c;
    float s = 0.f;
    for (int l = 0; l < 128; l++) s += p[(size_t)l * 256];
    meanp[(z * 8 + ch) * 256 + c] = s;
}

// ---------------- final projections + LN ----------------
__global__ void __launch_bounds__(256)
final_kernel(const float* __restrict__ meanp,
             const float* __restrict__ Wl, const float* __restrict__ bl,
             const float* __restrict__ Ws, const float* __restrict__ bs,
             const float* __restrict__ Wc, const float* __restrict__ bc,
             const float* __restrict__ gl, const float* __restrict__ betal,
             const float* __restrict__ gs, const float* __restrict__ betas,
             const float* __restrict__ gc, const float* __restrict__ betac,
             float* __restrict__ outp)
{
    const int b = blockIdx.x, type = blockIdx.y, tid = threadIdx.x;
    __shared__ float v[1024];
    __shared__ float red[256];

    const float *W, *bias, *g, *beta;
    int K, hbase;
    if (type == 0)      { W = Wl; bias = bl; g = gl; beta = betal; K = 512;  hbase = 0; }
    else if (type == 1) { W = Ws; bias = bs; g = gs; beta = betas; K = 512;  hbase = 2; }
    else                { W = Wc; bias = bc; g = gc; beta = betac; K = 1024; hbase = 0; }

    for (int k = tid; k < K; k += 256) {
        int head = hbase + (k >> 8);
        int c = k & 255;
        float s = 0.f;
#pragma unroll
        for (int c8 = 0; c8 < 8; c8++)
            s += meanp[((head * 16 + b) * 8 + c8) * 256 + c];
        v[k] = s * (1.f / 1024.f);
    }
    __syncthreads();

    float acc[3];
#pragma unroll
    for (int q = 0; q < 3; q++) {
        int c = tid + q * 256;
        float s = bias[c];
        for (int k = 0; k < K; k++) s += v[k] * W[(size_t)k * 768 + c];
        acc[q] = s;
    }

    red[tid] = acc[0] + acc[1] + acc[2];
    __syncthreads();
    for (int off = 128; off > 0; off >>= 1) {
        if (tid < off) red[tid] += red[tid + off];
        __syncthreads();
    }
    float mu = red[0] * (1.f / 768.f);
    __syncthreads();
    float d0 = acc[0] - mu, d1 = acc[1] - mu, d2 = acc[2] - mu;
    red[tid] = d0 * d0 + d1 * d1 + d2 * d2;
    __syncthreads();
    for (int off = 128; off > 0; off >>= 1) {
        if (tid < off) red[tid] += red[tid + off];
        __syncthreads();
    }
    float rstd = rsqrtf(red[0] * (1.f / 768.f) + 1e-5f);
    __syncthreads();

#pragma unroll
    for (int q = 0; q < 3; q++) {
        int c = tid + q * 256;
        outp[(size_t)type * 16 * 768 + (size_t)b * 768 + c] =
            (acc[q] - mu) * rstd * g[c] + beta[c];
    }
}

// ---------------- launch ----------------
extern "C" void kernel_launch(void* const* d_in, const int* in_sizes, int n_in,
                              void* d_out, int out_size)
{
    const float* x      = (const float*)d_in[0];
    const float* Wfc    = (const float*)d_in[1];
    const float* bfc    = (const float*)d_in[2];
    const float* lng    = (const float*)d_in[3];
    const float* lnb    = (const float*)d_in[4];
    const float* adjw   = (const float*)d_in[5];
    const float* Watt   = (const float*)d_in[6];
    const float* batt   = (const float*)d_in[7];
    const float* Wl     = (const float*)d_in[8];
    const float* bl     = (const float*)d_in[9];
    const float* Ws     = (const float*)d_in[10];
    const float* bs     = (const float*)d_in[11];
    const float* Wc     = (const float*)d_in[12];
    const float* bc     = (const float*)d_in[13];
    const float* gl     = (const float*)d_in[14];
    const float* betal  = (const float*)d_in[15];
    const float* gs     = (const float*)d_in[16];
    const float* betas  = (const float*)d_in[17];
    const float* gc     = (const float*)d_in[18];
    const float* betac  = (const float*)d_in[19];
    float* outp = (float*)d_out;

    float *h, *tmp, *ob, *esrc, *edst, *meanp;
    cudaGetSymbolAddress((void**)&h,     g_h);
    cudaGetSymbolAddress((void**)&tmp,   g_tmp);
    cudaGetSymbolAddress((void**)&ob,    g_out);
    cudaGetSymbolAddress((void**)&esrc,  g_esrc);
    cudaGetSymbolAddress((void**)&edst,  g_edst);
    cudaGetSymbolAddress((void**)&meanp, g_meanp);

    cudaFuncSetAttribute(attn_fused,
                         cudaFuncAttributeMaxDynamicSharedMemorySize, FS_SMEM);

    // K1: pre = x @ Wfc + bfc   (per head)
    sgemm_nn<<<dim3(2, 128, 4), 256>>>(x, Wfc, tmp, bfc,
                                       16384, 256, 768,
                                       (size_t)0, (size_t)768 * 256,
                                       (size_t)16384 * 256, (size_t)256);
    // K2: LN + e_src/e_dst
    ln_esrc_kernel<<<8192, 256>>>(tmp, h, lng, lnb, Watt, esrc, edst);
    // K3: g = h @ adjw (per head)
    sgemm_nn<<<dim3(2, 128, 4), 256>>>(h, adjw, tmp, nullptr,
                                       16384, 256, 256,
                                       (size_t)16384 * 256, (size_t)256 * 256,
                                       (size_t)16384 * 256, (size_t)0);
    // K4+K5 fused: S tile in smem -> sigmoid -> quantile mask -> softmax -> gather
    attn_fused<<<dim3(32, 16, 4), 512, FS_SMEM>>>(tmp, h, esrc, edst, batt, ob);
    // K6: partial mean over L
    mean_kernel<<<dim3(64, 8), 256>>>(ob, meanp);
    // K7: final projections + LN
    final_kernel<<<dim3(16, 3), 256>>>(meanp, Wl, bl, Ws, bs, Wc, bc,
                                       gl, betal, gs, betas, gc, betac, outp);
}

// round 6
// speedup vs baseline: 1.9720x; 1.9720x over previous
#include <cuda_runtime.h>
#include <cstdint>
#include <cstddef>

// ---------------- static scratch ----------------
__device__ float g_h[4 * 16384 * 256];
__device__ float g_tmp[4 * 16384 * 256];
__device__ float g_A[4 * 16 * 1024 * 1024];
__device__ float g_out[4 * 16384 * 256];
__device__ float g_esrc[4 * 16384];
__device__ float g_edst[4 * 16384];
__device__ float g_meanp[64 * 8 * 256];

__device__ __forceinline__ uint32_t f2tf(float x) {
    uint32_t r;
    asm("cvt.rna.tf32.f32 %0, %1;" : "=r"(r) : "f"(x));
    return r;
}

__device__ __forceinline__ void mma_tf32(float c[4], const uint32_t a[4], const uint32_t b[2]) {
    asm volatile(
        "mma.sync.aligned.m16n8k8.row.col.f32.tf32.tf32.f32 "
        "{%0,%1,%2,%3}, {%4,%5,%6,%7}, {%8,%9}, {%0,%1,%2,%3};"
        : "+f"(c[0]), "+f"(c[1]), "+f"(c[2]), "+f"(c[3])
        : "r"(a[0]), "r"(a[1]), "r"(a[2]), "r"(a[3]), "r"(b[0]), "r"(b[1]));
}

// =====================================================================
// tf32 tensor-core GEMM: C = A@B (NT=false, B is KxN) or A@B^T (NT=true,
// B is NxK). 128x128x32 tiles, 8 warps, each warp 64x32 via m16n8k8.
// Optional bias (+per-z stride) and sigmoid epilogue.
// =====================================================================
template<bool NT, bool SIG, bool HASBIAS>
__global__ void __launch_bounds__(256, 2)
mma_gemm(const float* __restrict__ Ab, const float* __restrict__ Bb,
         float* __restrict__ Cb, const float* __restrict__ biasb,
         int N, int K,
         size_t sA, size_t sB, size_t sC, size_t sBias)
{
    const float* A = Ab + (size_t)blockIdx.z * sA;
    const float* B = Bb + (size_t)blockIdx.z * sB;
    float* C = Cb + (size_t)blockIdx.z * sC;
    const float* bias = HASBIAS ? biasb + (size_t)blockIdx.z * sBias : nullptr;

    __shared__ uint32_t As[128 * 36];   // [m][k], stride 36
    __shared__ uint32_t Bs[128 * 36];   // [n][k], stride 36

    const int tid = threadIdx.x;
    const int row0 = blockIdx.y * 128;
    const int col0 = blockIdx.x * 128;

    const int wid = tid >> 5, lane = tid & 31;
    const int wm = (wid >> 2) * 64;          // 0 or 64
    const int wn = (wid & 3) * 32;           // 0,32,64,96
    const int g4 = lane >> 2, t4 = lane & 3;

    float acc[4][4][4];
#pragma unroll
    for (int mi = 0; mi < 4; mi++)
#pragma unroll
        for (int nj = 0; nj < 4; nj++)
#pragma unroll
            for (int q = 0; q < 4; q++) acc[mi][nj][q] = 0.f;

    const int nStages = K >> 5;
    for (int s = 0; s < nStages; s++) {
        const int kb = s * 32;
        __syncthreads();
        // ---- stage A: As[r][k] = tf32(A[row0+r][kb+k]) ----
        {
            int r = tid >> 1;
            int kq = (tid & 1) * 16;
            const float* ap = A + (size_t)(row0 + r) * K + kb + kq;
            uint32_t* dst = &As[r * 36 + kq];
#pragma unroll
            for (int q = 0; q < 4; q++) {
                float4 v = *(const float4*)(ap + q * 4);
                dst[q * 4 + 0] = f2tf(v.x); dst[q * 4 + 1] = f2tf(v.y);
                dst[q * 4 + 2] = f2tf(v.z); dst[q * 4 + 3] = f2tf(v.w);
            }
        }
        // ---- stage B ----
        if (NT) {   // B is N x K row-major: Bs[n][k] = B[col0+n][kb+k]
            int r = tid >> 1;
            int kq = (tid & 1) * 16;
            const float* bp = B + (size_t)(col0 + r) * K + kb + kq;
            uint32_t* dst = &Bs[r * 36 + kq];
#pragma unroll
            for (int q = 0; q < 4; q++) {
                float4 v = *(const float4*)(bp + q * 4);
                dst[q * 4 + 0] = f2tf(v.x); dst[q * 4 + 1] = f2tf(v.y);
                dst[q * 4 + 2] = f2tf(v.z); dst[q * 4 + 3] = f2tf(v.w);
            }
        } else {    // B is K x N row-major: Bs[n][k] = B[kb+k][col0+n]
            int k = tid >> 3;
            int n0 = (tid & 7) * 16;
            const float* bp = B + (size_t)(kb + k) * N + col0 + n0;
#pragma unroll
            for (int q = 0; q < 4; q++) {
                float4 v = *(const float4*)(bp + q * 4);
                Bs[(n0 + q * 4 + 0) * 36 + k] = f2tf(v.x);
                Bs[(n0 + q * 4 + 1) * 36 + k] = f2tf(v.y);
                Bs[(n0 + q * 4 + 2) * 36 + k] = f2tf(v.z);
                Bs[(n0 + q * 4 + 3) * 36 + k] = f2tf(v.w);
            }
        }
        __syncthreads();

#pragma unroll
        for (int ks = 0; ks < 4; ks++) {
            const int k0 = ks * 8;
            uint32_t afr[4][4];
#pragma unroll
            for (int mi = 0; mi < 4; mi++) {
                int r = wm + mi * 16 + g4;
                afr[mi][0] = As[r * 36 + k0 + t4];
                afr[mi][1] = As[(r + 8) * 36 + k0 + t4];
                afr[mi][2] = As[r * 36 + k0 + t4 + 4];
                afr[mi][3] = As[(r + 8) * 36 + k0 + t4 + 4];
            }
            uint32_t bfr[4][2];
#pragma unroll
            for (int nj = 0; nj < 4; nj++) {
                int cn = wn + nj * 8 + g4;
                bfr[nj][0] = Bs[cn * 36 + k0 + t4];
                bfr[nj][1] = Bs[cn * 36 + k0 + t4 + 4];
            }
#pragma unroll
            for (int mi = 0; mi < 4; mi++)
#pragma unroll
                for (int nj = 0; nj < 4; nj++)
                    mma_tf32(acc[mi][nj], afr[mi], bfr[nj]);
        }
    }

    // ---- epilogue ----
#pragma unroll
    for (int mi = 0; mi < 4; mi++) {
#pragma unroll
        for (int nj = 0; nj < 4; nj++) {
            int r = row0 + wm + mi * 16 + g4;
            int cn = col0 + wn + nj * 8 + 2 * t4;
            float v0 = acc[mi][nj][0], v1 = acc[mi][nj][1];
            float v2 = acc[mi][nj][2], v3 = acc[mi][nj][3];
            if (HASBIAS) {
                float b0 = bias[cn], b1 = bias[cn + 1];
                v0 += b0; v1 += b1; v2 += b0; v3 += b1;
            }
            if (SIG) {
                v0 = 1.f / (1.f + expf(-v0)); v1 = 1.f / (1.f + expf(-v1));
                v2 = 1.f / (1.f + expf(-v2)); v3 = 1.f / (1.f + expf(-v3));
            }
            *(float2*)(C + (size_t)r * N + cn)       = make_float2(v0, v1);
            *(float2*)(C + (size_t)(r + 8) * N + cn) = make_float2(v2, v3);
        }
    }
}

// ---------------- LN over H=256 per row, fused e_src/e_dst GEMVs ----------------
__global__ void __launch_bounds__(256)
ln_esrc_kernel(const float* __restrict__ pre, float* __restrict__ h,
               const float* __restrict__ lng, const float* __restrict__ lnb,
               const float* __restrict__ Watt,
               float* __restrict__ esrc, float* __restrict__ edst)
{
    int w = (blockIdx.x * blockDim.x + threadIdx.x) >> 5;
    int lane = threadIdx.x & 31;
    int hd = w >> 14;
    const float* row = pre + (size_t)w * 256;

    float x[8];
    float s = 0.f;
#pragma unroll
    for (int i = 0; i < 8; i++) { x[i] = row[lane + 32 * i]; s += x[i]; }
#pragma unroll
    for (int off = 16; off > 0; off >>= 1) s += __shfl_xor_sync(0xffffffffu, s, off);
    float mu = s * (1.f / 256.f);

    float v = 0.f;
#pragma unroll
    for (int i = 0; i < 8; i++) { float d = x[i] - mu; v += d * d; }
#pragma unroll
    for (int off = 16; off > 0; off >>= 1) v += __shfl_xor_sync(0xffffffffu, v, off);
    float rstd = rsqrtf(v * (1.f / 256.f) + 1e-5f);

    float es = 0.f, ed = 0.f;
    float* hrow = h + (size_t)w * 256;
#pragma unroll
    for (int i = 0; i < 8; i++) {
        int c = lane + 32 * i;
        float y = (x[i] - mu) * rstd * lng[hd * 256 + c] + lnb[hd * 256 + c];
        hrow[c] = y;
        es += y * Watt[hd * 512 + c];
        ed += y * Watt[hd * 512 + 256 + c];
    }
#pragma unroll
    for (int off = 16; off > 0; off >>= 1) {
        es += __shfl_xor_sync(0xffffffffu, es, off);
        ed += __shfl_xor_sync(0xffffffffu, ed, off);
    }
    if (lane == 0) { esrc[w] = es; edst[w] = ed; }
}

// ---------------- per-row: radix-select quantile, masked softmax, sparse gather ----------------
__global__ void __launch_bounds__(256)
attn_kernel(const float* __restrict__ Aprob, const float* __restrict__ h,
            const float* __restrict__ esrc, const float* __restrict__ edst,
            const float* __restrict__ batt, float* __restrict__ out)
{
    const int i = blockIdx.x, b = blockIdx.y, hd = blockIdx.z;
    const int tid = threadIdx.x;

    __shared__ float sA[1024];
    __shared__ float sE[1024];
    __shared__ int   sList[1024];
    __shared__ unsigned int sHist[256];
    __shared__ int   sScan[256];
    __shared__ float sRed[256];
    __shared__ int   sSel, sRank;

    const size_t rowbase = ((size_t)(hd * 16 + b) * 1024 + i) * 1024;
#pragma unroll
    for (int q = 0; q < 4; q++)
        sA[tid + 256 * q] = Aprob[rowbase + tid + 256 * q];
    __syncthreads();

    // ---- radix select: exact value at ascending rank 716
    int rank = 716;
    unsigned int prefval = 0u, maskhi = 0u;
    for (int shift = 24; shift >= 0; shift -= 8) {
        sHist[tid] = 0u;
        __syncthreads();
#pragma unroll
        for (int q = 0; q < 4; q++) {
            unsigned int k = __float_as_uint(sA[tid + 256 * q]);
            if ((k & maskhi) == prefval)
                atomicAdd(&sHist[(k >> shift) & 255u], 1u);
        }
        __syncthreads();
        for (int off = 1; off < 256; off <<= 1) {
            unsigned int v = (tid >= off) ? sHist[tid - off] : 0u;
            __syncthreads();
            sHist[tid] += v;
            __syncthreads();
        }
        int cum  = (int)sHist[tid];
        int prev = (tid > 0) ? (int)sHist[tid - 1] : 0;
        if (rank >= prev && rank < cum) { sSel = tid; sRank = rank - prev; }
        __syncthreads();
        prefval |= ((unsigned int)sSel) << shift;
        maskhi  |= 0xFFu << shift;
        rank = sRank;
        __syncthreads();
    }
    const float v716 = __uint_as_float(prefval);

    // ---- value at rank 717
    int cLE = 0; unsigned int mA = 0xFFFFFFFFu;
#pragma unroll
    for (int q = 0; q < 4; q++) {
        float a = sA[tid + 256 * q];
        if (a <= v716) cLE++;
        else { unsigned int k = __float_as_uint(a); mA = (k < mA) ? k : mA; }
    }
    sScan[tid] = cLE; sHist[tid] = mA;
    __syncthreads();
    for (int off = 128; off > 0; off >>= 1) {
        if (tid < off) {
            sScan[tid] += sScan[tid + off];
            unsigned int o = sHist[tid + off];
            if (o < sHist[tid]) sHist[tid] = o;
        }
        __syncthreads();
    }
    const float v717 = (sScan[0] > 717) ? v716 : __uint_as_float(sHist[0]);
    __syncthreads();

    const float fr = 0.7f * 1023.0f - 716.0f;
    const float delta = v716 + fr * (v717 - v716);

    // ---- mask compaction
    int cnt = 0; int loc[4];
#pragma unroll
    for (int q = 0; q < 4; q++) {
        int j = tid * 4 + q;
        bool m = (sA[j] > delta) || (j == i);
        if (m) loc[cnt++] = j;
    }
    sScan[tid] = cnt;
    __syncthreads();
    for (int off = 1; off < 256; off <<= 1) {
        int v = (tid >= off) ? sScan[tid - off] : 0;
        __syncthreads();
        sScan[tid] += v;
        __syncthreads();
    }
    const int total = sScan[255];
    int base = sScan[tid] - cnt;
    for (int q = 0; q < cnt; q++) sList[base + q] = loc[q];
    __syncthreads();

    // ---- masked leaky-relu softmax
    const int rowidx = hd * 16384 + b * 1024;
    const float ei = esrc[rowidx + i];
    const float bb = batt[hd];
    float lmax = -3.4e38f;
    for (int p = tid; p < total; p += 256) {
        int j = sList[p];
        float e = ei + edst[rowidx + j] + bb;
        e = (e >= 0.f) ? e : 0.01f * e;
        sE[p] = e;
        lmax = fmaxf(lmax, e);
    }
    sRed[tid] = lmax; __syncthreads();
    for (int off = 128; off > 0; off >>= 1) {
        if (tid < off) sRed[tid] = fmaxf(sRed[tid], sRed[tid + off]);
        __syncthreads();
    }
    const float emax = sRed[0];
    __syncthreads();

    float lsum = 0.f;
    for (int p = tid; p < total; p += 256) {
        float a = expf(sE[p] - emax);
        sE[p] = a;
        lsum += a;
    }
    sRed[tid] = lsum; __syncthreads();
    for (int off = 128; off > 0; off >>= 1) {
        if (tid < off) sRed[tid] += sRed[tid + off];
        __syncthreads();
    }
    const float inv = 1.f / sRed[0];
    __syncthreads();

    // ---- out_i[c] = sum over masked j of alpha_j * h[j][c]
    const float* hbase = h + (size_t)rowidx * 256;
    float acc = 0.f;
    for (int p = 0; p < total; p++) {
        int j = sList[p];
        acc += sE[p] * hbase[(size_t)j * 256 + tid];
    }
    out[((size_t)rowidx + i) * 256 + tid] = acc * inv;
}

// ---------------- partial mean over L per (head,batch): 8 chunks of 128 ----------------
__global__ void __launch_bounds__(256)
mean_kernel(const float* __restrict__ o, float* __restrict__ meanp)
{
    int z = blockIdx.x;
    int ch = blockIdx.y;
    int c = threadIdx.x;
    const float* p = o + (size_t)z * 262144 + (size_t)ch * 128 * 256 + c;
    float s = 0.f;
    for (int l = 0; l < 128; l++) s += p[(size_t)l * 256];
    meanp[(z * 8 + ch) * 256 + c] = s;
}

// ---------------- final projections + LN ----------------
__global__ void __launch_bounds__(256)
final_kernel(const float* __restrict__ meanp,
             const float* __restrict__ Wl, const float* __restrict__ bl,
             const float* __restrict__ Ws, const float* __restrict__ bs,
             const float* __restrict__ Wc, const float* __restrict__ bc,
             const float* __restrict__ gl, const float* __restrict__ betal,
             const float* __restrict__ gs, const float* __restrict__ betas,
             const float* __restrict__ gc, const float* __restrict__ betac,
             float* __restrict__ outp)
{
    const int b = blockIdx.x, type = blockIdx.y, tid = threadIdx.x;
    __shared__ float v[1024];
    __shared__ float red[256];

    const float *W, *bias, *g, *beta;
    int K, hbase;
    if (type == 0)      { W = Wl; bias = bl; g = gl; beta = betal; K = 512;  hbase = 0; }
    else if (type == 1) { W = Ws; bias = bs; g = gs; beta = betas; K = 512;  hbase = 2; }
    else                { W = Wc; bias = bc; g = gc; beta = betac; K = 1024; hbase = 0; }

    for (int k = tid; k < K; k += 256) {
        int head = hbase + (k >> 8);
        int c = k & 255;
        float s = 0.f;
#pragma unroll
        for (int c8 = 0; c8 < 8; c8++)
            s += meanp[((head * 16 + b) * 8 + c8) * 256 + c];
        v[k] = s * (1.f / 1024.f);
    }
    __syncthreads();

    float acc[3];
#pragma unroll
    for (int q = 0; q < 3; q++) {
        int c = tid + q * 256;
        float s = bias[c];
        for (int k = 0; k < K; k++) s += v[k] * W[(size_t)k * 768 + c];
        acc[q] = s;
    }

    red[tid] = acc[0] + acc[1] + acc[2];
    __syncthreads();
    for (int off = 128; off > 0; off >>= 1) {
        if (tid < off) red[tid] += red[tid + off];
        __syncthreads();
    }
    float mu = red[0] * (1.f / 768.f);
    __syncthreads();
    float d0 = acc[0] - mu, d1 = acc[1] - mu, d2 = acc[2] - mu;
    red[tid] = d0 * d0 + d1 * d1 + d2 * d2;
    __syncthreads();
    for (int off = 128; off > 0; off >>= 1) {
        if (tid < off) red[tid] += red[tid + off];
        __syncthreads();
    }
    float rstd = rsqrtf(red[0] * (1.f / 768.f) + 1e-5f);
    __syncthreads();

#pragma unroll
    for (int q = 0; q < 3; q++) {
        int c = tid + q * 256;
        outp[(size_t)type * 16 * 768 + (size_t)b * 768 + c] =
            (acc[q] - mu) * rstd * g[c] + beta[c];
    }
}

// ---------------- launch ----------------
extern "C" void kernel_launch(void* const* d_in, const int* in_sizes, int n_in,
                              void* d_out, int out_size)
{
    const float* x      = (const float*)d_in[0];
    const float* Wfc    = (const float*)d_in[1];
    const float* bfc    = (const float*)d_in[2];
    const float* lng    = (const float*)d_in[3];
    const float* lnb    = (const float*)d_in[4];
    const float* adjw   = (const float*)d_in[5];
    const float* Watt   = (const float*)d_in[6];
    const float* batt   = (const float*)d_in[7];
    const float* Wl     = (const float*)d_in[8];
    const float* bl     = (const float*)d_in[9];
    const float* Ws     = (const float*)d_in[10];
    const float* bs     = (const float*)d_in[11];
    const float* Wc     = (const float*)d_in[12];
    const float* bc     = (const float*)d_in[13];
    const float* gl     = (const float*)d_in[14];
    const float* betal  = (const float*)d_in[15];
    const float* gs     = (const float*)d_in[16];
    const float* betas  = (const float*)d_in[17];
    const float* gc     = (const float*)d_in[18];
    const float* betac  = (const float*)d_in[19];
    float* outp = (float*)d_out;

    float *h, *tmp, *A, *ob, *esrc, *edst, *meanp;
    cudaGetSymbolAddress((void**)&h,     g_h);
    cudaGetSymbolAddress((void**)&tmp,   g_tmp);
    cudaGetSymbolAddress((void**)&A,     g_A);
    cudaGetSymbolAddress((void**)&ob,    g_out);
    cudaGetSymbolAddress((void**)&esrc,  g_esrc);
    cudaGetSymbolAddress((void**)&edst,  g_edst);
    cudaGetSymbolAddress((void**)&meanp, g_meanp);

    // K1: pre = x @ Wfc + bfc   (per head, tf32 tensor cores)
    mma_gemm<false, false, true><<<dim3(2, 128, 4), 256>>>(
        x, Wfc, tmp, bfc, 256, 768,
        (size_t)0, (size_t)768 * 256, (size_t)16384 * 256, (size_t)256);
    // K2: LN + e_src/e_dst
    ln_esrc_kernel<<<8192, 256>>>(tmp, h, lng, lnb, Watt, esrc, edst);
    // K3: g = h @ adjw (per head, tf32)
    mma_gemm<false, false, false><<<dim3(2, 128, 4), 256>>>(
        h, adjw, tmp, nullptr, 256, 256,
        (size_t)16384 * 256, (size_t)256 * 256, (size_t)16384 * 256, (size_t)0);
    // K4: A = sigmoid(g @ h^T) per (head,batch), tf32
    mma_gemm<true, true, false><<<dim3(8, 8, 64), 256>>>(
        tmp, h, A, nullptr, 1024, 256,
        (size_t)1024 * 256, (size_t)1024 * 256, (size_t)1024 * 1024, (size_t)0);
    // K5: radix-select quantile + masked softmax + sparse alpha@h
    attn_kernel<<<dim3(1024, 16, 4), 256>>>(A, h, esrc, edst, batt, ob);
    // K6: partial mean over L
    mean_kernel<<<dim3(64, 8), 256>>>(ob, meanp);
    // K7: final projections + LN
    final_kernel<<<dim3(16, 3), 256>>>(meanp, Wl, bl, Ws, bs, Wc, bc,
                                       gl, betal, gs, betas, gc, betac, outp);
}

// round 8
// speedup vs baseline: 2.4867x; 1.2610x over previous
#include <cuda_runtime.h>
#include <cstdint>
#include <cstddef>

// ---------------- static scratch ----------------
__device__ float g_h[4 * 16384 * 256];
__device__ float g_tmp[4 * 16384 * 256];
__device__ float g_A[4 * 16 * 1024 * 1024];
__device__ float g_out[4 * 16384 * 256];
__device__ float g_esrc[4 * 16384];
__device__ float g_edst[4 * 16384];
__device__ float g_meanp[64 * 8 * 256];

__device__ __forceinline__ uint32_t f2tf(float x) {
    uint32_t r;
    asm("cvt.rna.tf32.f32 %0, %1;" : "=r"(r) : "f"(x));
    return r;
}

__device__ __forceinline__ void mma_tf32(float c[4], const uint32_t a[4], const uint32_t b[2]) {
    asm volatile(
        "mma.sync.aligned.m16n8k8.row.col.f32.tf32.tf32.f32 "
        "{%0,%1,%2,%3}, {%4,%5,%6,%7}, {%8,%9}, {%0,%1,%2,%3};"
        : "+f"(c[0]), "+f"(c[1]), "+f"(c[2]), "+f"(c[3])
        : "r"(a[0]), "r"(a[1]), "r"(a[2]), "r"(a[3]), "r"(b[0]), "r"(b[1]));
}

// =====================================================================
// tf32 tensor-core GEMM, 128x128 tiles, K-chunk 16, double-buffered smem
// with register prefetch; ONE __syncthreads per stage.
// NT=false: B is KxN (C=A@B). NT=true: B is NxK (C=A@B^T).
// =====================================================================
template<bool NT, bool SIG, bool HASBIAS>
__global__ void __launch_bounds__(256, 2)
mma_gemm(const float* __restrict__ Ab, const float* __restrict__ Bb,
         float* __restrict__ Cb, const float* __restrict__ biasb,
         int N, int K,
         size_t sA, size_t sB, size_t sC, size_t sBias)
{
    const float* A = Ab + (size_t)blockIdx.z * sA;
    const float* B = Bb + (size_t)blockIdx.z * sB;
    float* C = Cb + (size_t)blockIdx.z * sC;
    const float* bias = HASBIAS ? biasb + (size_t)blockIdx.z * sBias : nullptr;

    __shared__ uint32_t As[2][128 * 20];   // [m][k], stride 20
    __shared__ uint32_t Bs[2][128 * 20];   // [n][k], stride 20

    const int tid = threadIdx.x;
    const int row0 = blockIdx.y * 128;
    const int col0 = blockIdx.x * 128;

    const int wid = tid >> 5, lane = tid & 31;
    const int wm = (wid >> 2) * 64;
    const int wn = (wid & 3) * 32;
    const int g4 = lane >> 2, t4 = lane & 3;

    // staging coordinates
    const int r  = tid >> 1;             // 0..127
    const int kq = (tid & 1) * 8;        // 0 or 8
    const int kkB = tid >> 4;            // 0..15   (NN B)
    const int n0B = (tid & 15) * 8;      // 0..120  (NN B)

    const float* Abase  = A + (size_t)(row0 + r) * K + kq;
    const float* BbaseT = B + (size_t)(col0 + r) * K + kq;

    float acc[4][4][4];
#pragma unroll
    for (int mi = 0; mi < 4; mi++)
#pragma unroll
        for (int nj = 0; nj < 4; nj++)
#pragma unroll
            for (int q = 0; q < 4; q++) acc[mi][nj][q] = 0.f;

    float a_pre[8], b_pre[8];

    auto loadStage = [&](int s) {
        const float* ap = Abase + s * 16;
        *(float4*)(a_pre)     = *(const float4*)(ap);
        *(float4*)(a_pre + 4) = *(const float4*)(ap + 4);
        if (NT) {
            const float* bp = BbaseT + s * 16;
            *(float4*)(b_pre)     = *(const float4*)(bp);
            *(float4*)(b_pre + 4) = *(const float4*)(bp + 4);
        } else {
            const float* bp = B + (size_t)(s * 16 + kkB) * N + col0 + n0B;
            *(float4*)(b_pre)     = *(const float4*)(bp);
            *(float4*)(b_pre + 4) = *(const float4*)(bp + 4);
        }
    };
    auto storeStage = [&](int bf) {
        uint32_t* da = &As[bf][r * 20 + kq];
#pragma unroll
        for (int q = 0; q < 8; q++) da[q] = f2tf(a_pre[q]);
        if (NT) {
            uint32_t* db = &Bs[bf][r * 20 + kq];
#pragma unroll
            for (int q = 0; q < 8; q++) db[q] = f2tf(b_pre[q]);
        } else {
#pragma unroll
            for (int q = 0; q < 8; q++)
                Bs[bf][(n0B + q) * 20 + kkB] = f2tf(b_pre[q]);
        }
    };

    const int nS = K >> 4;
    loadStage(0);
    storeStage(0);
    __syncthreads();

    int buf = 0;
    for (int s = 0; s < nS; s++) {
        if (s + 1 < nS) loadStage(s + 1);
#pragma unroll
        for (int ks = 0; ks < 2; ks++) {
            const int k0 = ks * 8;
            uint32_t afr[4][4];
#pragma unroll
            for (int mi = 0; mi < 4; mi++) {
                int rr = wm + mi * 16 + g4;
                afr[mi][0] = As[buf][rr * 20 + k0 + t4];
                afr[mi][1] = As[buf][(rr + 8) * 20 + k0 + t4];
                afr[mi][2] = As[buf][rr * 20 + k0 + t4 + 4];
                afr[mi][3] = As[buf][(rr + 8) * 20 + k0 + t4 + 4];
            }
            uint32_t bfr[4][2];
#pragma unroll
            for (int nj = 0; nj < 4; nj++) {
                int cn = wn + nj * 8 + g4;
                bfr[nj][0] = Bs[buf][cn * 20 + k0 + t4];
                bfr[nj][1] = Bs[buf][cn * 20 + k0 + t4 + 4];
            }
#pragma unroll
            for (int mi = 0; mi < 4; mi++)
#pragma unroll
                for (int nj = 0; nj < 4; nj++)
                    mma_tf32(acc[mi][nj], afr[mi], bfr[nj]);
        }
        if (s + 1 < nS) {
            storeStage(buf ^ 1);
            __syncthreads();
            buf ^= 1;
        }
    }

    // ---- epilogue ----
#pragma unroll
    for (int mi = 0; mi < 4; mi++) {
#pragma unroll
        for (int nj = 0; nj < 4; nj++) {
            int rr = row0 + wm + mi * 16 + g4;
            int cn = col0 + wn + nj * 8 + 2 * t4;
            float v0 = acc[mi][nj][0], v1 = acc[mi][nj][1];
            float v2 = acc[mi][nj][2], v3 = acc[mi][nj][3];
            if (HASBIAS) {
                float b0 = bias[cn], b1 = bias[cn + 1];
                v0 += b0; v1 += b1; v2 += b0; v3 += b1;
            }
            if (SIG) {
                v0 = 1.f / (1.f + expf(-v0)); v1 = 1.f / (1.f + expf(-v1));
                v2 = 1.f / (1.f + expf(-v2)); v3 = 1.f / (1.f + expf(-v3));
            }
            *(float2*)(C + (size_t)rr * N + cn)       = make_float2(v0, v1);
            *(float2*)(C + (size_t)(rr + 8) * N + cn) = make_float2(v2, v3);
        }
    }
}

// ---------------- LN over H=256 per row, fused e_src/e_dst GEMVs ----------------
__global__ void __launch_bounds__(256)
ln_esrc_kernel(const float* __restrict__ pre, float* __restrict__ h,
               const float* __restrict__ lng, const float* __restrict__ lnb,
               const float* __restrict__ Watt,
               float* __restrict__ esrc, float* __restrict__ edst)
{
    int w = (blockIdx.x * blockDim.x + threadIdx.x) >> 5;
    int lane = threadIdx.x & 31;
    int hd = w >> 14;
    const float* row = pre + (size_t)w * 256;

    float x[8];
    float s = 0.f;
#pragma unroll
    for (int i = 0; i < 8; i++) { x[i] = row[lane + 32 * i]; s += x[i]; }
#pragma unroll
    for (int off = 16; off > 0; off >>= 1) s += __shfl_xor_sync(0xffffffffu, s, off);
    float mu = s * (1.f / 256.f);

    float v = 0.f;
#pragma unroll
    for (int i = 0; i < 8; i++) { float d = x[i] - mu; v += d * d; }
#pragma unroll
    for (int off = 16; off > 0; off >>= 1) v += __shfl_xor_sync(0xffffffffu, v, off);
    float rstd = rsqrtf(v * (1.f / 256.f) + 1e-5f);

    float es = 0.f, ed = 0.f;
    float* hrow = h + (size_t)w * 256;
#pragma unroll
    for (int i = 0; i < 8; i++) {
        int c = lane + 32 * i;
        float y = (x[i] - mu) * rstd * lng[hd * 256 + c] + lnb[hd * 256 + c];
        hrow[c] = y;
        es += y * Watt[hd * 512 + c];
        ed += y * Watt[hd * 512 + 256 + c];
    }
#pragma unroll
    for (int off = 16; off > 0; off >>= 1) {
        es += __shfl_xor_sync(0xffffffffu, es, off);
        ed += __shfl_xor_sync(0xffffffffu, ed, off);
    }
    if (lane == 0) { esrc[w] = es; edst[w] = ed; }
}

// =====================================================================
// Warp-per-row attention: radix-select quantile(0.7), masked leaky-relu
// softmax, sparse alpha@h gather. No block barriers in hot path.
// grid (128, 16, 4), block 256 (8 warps = 8 rows), dyn smem 57344 B:
//   [0,     8192)  hist u32 [8][256]
//   [8192,  24576) list u16 [8][1024]
//   [24576, 57344) sE   f32 [8][1024]
// =====================================================================
#define ATTN_SMEM 57344
__global__ void __launch_bounds__(256)
attn_warp(const float* __restrict__ Aprob, const float* __restrict__ h,
          const float* __restrict__ esrc, const float* __restrict__ edst,
          const float* __restrict__ batt, float* __restrict__ out)
{
    extern __shared__ char smemraw[];
    const int tid = threadIdx.x;
    const int w = tid >> 5, lane = tid & 31;
    const int hd = blockIdx.z, b = blockIdx.y;
    const int i_row = blockIdx.x * 8 + w;
    const int rowidx = hd * 16384 + b * 1024;

    unsigned int* hist = (unsigned int*)smemraw + w * 256;
    unsigned short* lst = (unsigned short*)(smemraw + 8192) + w * 1024;
    float* sE = (float*)(smemraw + 24576) + w * 1024;

    // ---- load row into registers: av[q] = A[i_row][q*32+lane] ----
    const float* rowp = Aprob + ((size_t)rowidx + i_row) * 1024;
    float av[32];
#pragma unroll
    for (int q = 0; q < 32; q++) av[q] = rowp[q * 32 + lane];

    // ---- radix select: value at ascending rank 716 ----
    unsigned int prefval = 0u, maskhi = 0u;
    int rank = 716;
#pragma unroll
    for (int shift = 24; shift >= 0; shift -= 8) {
#pragma unroll
        for (int t = 0; t < 8; t++) hist[lane * 8 + t] = 0u;
        __syncwarp();
#pragma unroll
        for (int q = 0; q < 32; q++) {
            unsigned int k = __float_as_uint(av[q]);
            if ((k & maskhi) == prefval)
                atomicAdd(&hist[(k >> shift) & 255u], 1u);
        }
        __syncwarp();
        unsigned int h8[8]; unsigned int tot = 0u;
#pragma unroll
        for (int t = 0; t < 8; t++) { h8[t] = hist[lane * 8 + t]; tot += h8[t]; }
        unsigned int incl = tot;
#pragma unroll
        for (int off = 1; off < 32; off <<= 1) {
            unsigned int v = __shfl_up_sync(0xffffffffu, incl, off);
            if (lane >= off) incl += v;
        }
        unsigned int base = incl - tot;
        int bin = -1, nr = 0;
        unsigned int run = base;
#pragma unroll
        for (int t = 0; t < 8; t++) {
            unsigned int c = run + h8[t];
            if (bin < 0 && (unsigned int)rank >= run && (unsigned int)rank < c) {
                bin = lane * 8 + t; nr = rank - (int)run;
            }
            run = c;
        }
        unsigned int mball = __ballot_sync(0xffffffffu, bin >= 0);
        int src = __ffs(mball) - 1;
        bin = __shfl_sync(0xffffffffu, bin, src);
        nr  = __shfl_sync(0xffffffffu, nr, src);
        prefval |= ((unsigned int)bin) << shift;
        maskhi  |= 0xFFu << shift;
        rank = nr;
    }
    const float v716 = __uint_as_float(prefval);

    // ---- rank 717: count <= v716 and min-above ----
    int cLE = 0; unsigned int mA = 0xFFFFFFFFu;
#pragma unroll
    for (int q = 0; q < 32; q++) {
        float a = av[q];
        if (a <= v716) cLE++;
        else { unsigned int k = __float_as_uint(a); mA = (k < mA) ? k : mA; }
    }
#pragma unroll
    for (int off = 16; off > 0; off >>= 1) {
        cLE += __shfl_xor_sync(0xffffffffu, cLE, off);
        unsigned int o = __shfl_xor_sync(0xffffffffu, mA, off);
        mA = (o < mA) ? o : mA;
    }
    const float v717 = (cLE > 717) ? v716 : __uint_as_float(mA);
    const float fr = 0.7f * 1023.0f - 716.0f;
    const float delta = v716 + fr * (v717 - v716);

    // ---- mask compaction (warp scan) ----
    int cnt = 0; unsigned short loc[32];
#pragma unroll
    for (int q = 0; q < 32; q++) {
        int j = q * 32 + lane;
        if (av[q] > delta || j == i_row) loc[cnt++] = (unsigned short)j;
    }
    int incl = cnt;
#pragma unroll
    for (int off = 1; off < 32; off <<= 1) {
        int v = __shfl_up_sync(0xffffffffu, incl, off);
        if (lane >= off) incl += v;
    }
    int base = incl - cnt;
    int total = __shfl_sync(0xffffffffu, incl, 31);
    for (int t = 0; t < cnt; t++) lst[base + t] = loc[t];
    __syncwarp();

    // ---- masked leaky-relu softmax ----
    const float eb = esrc[rowidx + i_row] + batt[hd];
    float lmax = -3.4e38f;
    for (int p = lane; p < total; p += 32) {
        int j = lst[p];
        float e = eb + edst[rowidx + j];
        e = (e >= 0.f) ? e : 0.01f * e;
        sE[p] = e;
        lmax = fmaxf(lmax, e);
    }
#pragma unroll
    for (int off = 16; off > 0; off >>= 1)
        lmax = fmaxf(lmax, __shfl_xor_sync(0xffffffffu, lmax, off));
    __syncwarp();
    float lsum = 0.f;
    for (int p = lane; p < total; p += 32) {
        float a = expf(sE[p] - lmax);
        sE[p] = a;
        lsum += a;
    }
#pragma unroll
    for (int off = 16; off > 0; off >>= 1)
        lsum += __shfl_xor_sync(0xffffffffu, lsum, off);
    const float inv = 1.f / lsum;
    __syncwarp();

    // ---- out[i_row][c] = inv * sum_p alpha_p * h[j_p][c]; lane owns 8 cols ----
    float a0 = 0.f, a1 = 0.f, a2 = 0.f, a3 = 0.f;
    float a4 = 0.f, a5 = 0.f, a6 = 0.f, a7 = 0.f;
    const float* hb = h + (size_t)rowidx * 256;
    for (int p = 0; p < total; p++) {
        int j = lst[p];
        float wgt = sE[p];
        const float4* hr = (const float4*)(hb + (size_t)j * 256 + lane * 8);
        float4 x0 = hr[0], x1 = hr[1];
        a0 += wgt * x0.x; a1 += wgt * x0.y; a2 += wgt * x0.z; a3 += wgt * x0.w;
        a4 += wgt * x1.x; a5 += wgt * x1.y; a6 += wgt * x1.z; a7 += wgt * x1.w;
    }
    float* op = out + ((size_t)rowidx + i_row) * 256 + lane * 8;
    *(float4*)(op)     = make_float4(a0 * inv, a1 * inv, a2 * inv, a3 * inv);
    *(float4*)(op + 4) = make_float4(a4 * inv, a5 * inv, a6 * inv, a7 * inv);
}

// ---------------- partial mean over L per (head,batch): 8 chunks of 128 ----------------
__global__ void __launch_bounds__(256)
mean_kernel(const float* __restrict__ o, float* __restrict__ meanp)
{
    int z = blockIdx.x;
    int ch = blockIdx.y;
    int c = threadIdx.x;
    const float* p = o + (size_t)z * 262144 + (size_t)ch * 128 * 256 + c;
    float s = 0.f;
    for (int l = 0; l < 128; l++) s += p[(size_t)l * 256];
    meanp[(z * 8 + ch) * 256 + c] = s;
}

// ---------------- final projections + LN ----------------
__global__ void __launch_bounds__(256)
final_kernel(const float* __restrict__ meanp,
             const float* __restrict__ Wl, const float* __restrict__ bl,
             const float* __restrict__ Ws, const float* __restrict__ bs,
             const float* __restrict__ Wc, const float* __restrict__ bc,
             const float* __restrict__ gl, const float* __restrict__ betal,
             const float* __restrict__ gs, const float* __restrict__ betas,
             const float* __restrict__ gc, const float* __restrict__ betac,
             float* __restrict__ outp)
{
    const int b = blockIdx.x, type = blockIdx.y, tid = threadIdx.x;
    __shared__ float v[1024];
    __shared__ float red[256];

    const float *W, *bias, *g, *beta;
    int K, hbase;
    if (type == 0)      { W = Wl; bias = bl; g = gl; beta = betal; K = 512;  hbase = 0; }
    else if (type == 1) { W = Ws; bias = bs; g = gs; beta = betas; K = 512;  hbase = 2; }
    else                { W = Wc; bias = bc; g = gc; beta = betac; K = 1024; hbase = 0; }

    for (int k = tid; k < K; k += 256) {
        int head = hbase + (k >> 8);
        int c = k & 255;
        float s = 0.f;
#pragma unroll
        for (int c8 = 0; c8 < 8; c8++)
            s += meanp[((head * 16 + b) * 8 + c8) * 256 + c];
        v[k] = s * (1.f / 1024.f);
    }
    __syncthreads();

    float acc[3];
#pragma unroll
    for (int q = 0; q < 3; q++) {
        int c = tid + q * 256;
        float s = bias[c];
        for (int k = 0; k < K; k++) s += v[k] * W[(size_t)k * 768 + c];
        acc[q] = s;
    }

    red[tid] = acc[0] + acc[1] + acc[2];
    __syncthreads();
    for (int off = 128; off > 0; off >>= 1) {
        if (tid < off) red[tid] += red[tid + off];
        __syncthreads();
    }
    float mu = red[0] * (1.f / 768.f);
    __syncthreads();
    float d0 = acc[0] - mu, d1 = acc[1] - mu, d2 = acc[2] - mu;
    red[tid] = d0 * d0 + d1 * d1 + d2 * d2;
    __syncthreads();
    for (int off = 128; off > 0; off >>= 1) {
        if (tid < off) red[tid] += red[tid + off];
        __syncthreads();
    }
    float rstd = rsqrtf(red[0] * (1.f / 768.f) + 1e-5f);
    __syncthreads();

#pragma unroll
    for (int q = 0; q < 3; q++) {
        int c = tid + q * 256;
        outp[(size_t)type * 16 * 768 + (size_t)b * 768 + c] =
            (acc[q] - mu) * rstd * g[c] + beta[c];
    }
}

// ---------------- launch ----------------
extern "C" void kernel_launch(void* const* d_in, const int* in_sizes, int n_in,
                              void* d_out, int out_size)
{
    const float* x      = (const float*)d_in[0];
    const float* Wfc    = (const float*)d_in[1];
    const float* bfc    = (const float*)d_in[2];
    const float* lng    = (const float*)d_in[3];
    const float* lnb    = (const float*)d_in[4];
    const float* adjw   = (const float*)d_in[5];
    const float* Watt   = (const float*)d_in[6];
    const float* batt   = (const float*)d_in[7];
    const float* Wl     = (const float*)d_in[8];
    const float* bl     = (const float*)d_in[9];
    const float* Ws     = (const float*)d_in[10];
    const float* bs     = (const float*)d_in[11];
    const float* Wc     = (const float*)d_in[12];
    const float* bc     = (const float*)d_in[13];
    const float* gl     = (const float*)d_in[14];
    const float* betal  = (const float*)d_in[15];
    const float* gs     = (const float*)d_in[16];
    const float* betas  = (const float*)d_in[17];
    const float* gc     = (const float*)d_in[18];
    const float* betac  = (const float*)d_in[19];
    float* outp = (float*)d_out;

    float *h, *tmp, *A, *ob, *esrc, *edst, *meanp;
    cudaGetSymbolAddress((void**)&h,     g_h);
    cudaGetSymbolAddress((void**)&tmp,   g_tmp);
    cudaGetSymbolAddress((void**)&A,     g_A);
    cudaGetSymbolAddress((void**)&ob,    g_out);
    cudaGetSymbolAddress((void**)&esrc,  g_esrc);
    cudaGetSymbolAddress((void**)&edst,  g_edst);
    cudaGetSymbolAddress((void**)&meanp, g_meanp);

    cudaFuncSetAttribute(attn_warp,
                         cudaFuncAttributeMaxDynamicSharedMemorySize, ATTN_SMEM);

    // K1: pre = x @ Wfc + bfc   (per head, tf32)
    mma_gemm<false, false, true><<<dim3(2, 128, 4), 256>>>(
        x, Wfc, tmp, bfc, 256, 768,
        (size_t)0, (size_t)768 * 256, (size_t)16384 * 256, (size_t)256);
    // K2: LN + e_src/e_dst
    ln_esrc_kernel<<<8192, 256>>>(tmp, h, lng, lnb, Watt, esrc, edst);
    // K3: g = h @ adjw (per head, tf32)
    mma_gemm<false, false, false><<<dim3(2, 128, 4), 256>>>(
        h, adjw, tmp, nullptr, 256, 256,
        (size_t)16384 * 256, (size_t)256 * 256, (size_t)16384 * 256, (size_t)0);
    // K4: A = sigmoid(g @ h^T) per (head,batch), tf32
    mma_gemm<true, true, false><<<dim3(8, 8, 64), 256>>>(
        tmp, h, A, nullptr, 1024, 256,
        (size_t)1024 * 256, (size_t)1024 * 256, (size_t)1024 * 1024, (size_t)0);
    // K5: warp-per-row quantile + masked softmax + sparse alpha@h
    attn_warp<<<dim3(128, 16, 4), 256, ATTN_SMEM>>>(A, h, esrc, edst, batt, ob);
    // K6: partial mean over L
    mean_kernel<<<dim3(64, 8), 256>>>(ob, meanp);
    // K7: final projections + LN
    final_kernel<<<dim3(16, 3), 256>>>(meanp, Wl, bl, Ws, bs, Wc, bc,
                                       gl, betal, gs, betas, gc, betac, outp);
}

// round 9
// speedup vs baseline: 2.8699x; 1.1541x over previous
#include <cuda_runtime.h>
#include <cstdint>
#include <cstddef>

// ---------------- static scratch ----------------
__device__ float g_h[4 * 16384 * 256];
__device__ float g_tmp[4 * 16384 * 256];
__device__ float g_A[4 * 16 * 1024 * 1024];
__device__ float g_out[4 * 16384 * 256];
__device__ float g_esrc[4 * 16384];
__device__ float g_edst[4 * 16384];
__device__ float g_meanp[64 * 8 * 256];

__device__ __forceinline__ uint32_t f2tf(float x) {
    uint32_t r;
    asm("cvt.rna.tf32.f32 %0, %1;" : "=r"(r) : "f"(x));
    return r;
}

__device__ __forceinline__ void mma_tf32(float c[4], const uint32_t a[4], const uint32_t b[2]) {
    asm volatile(
        "mma.sync.aligned.m16n8k8.row.col.f32.tf32.tf32.f32 "
        "{%0,%1,%2,%3}, {%4,%5,%6,%7}, {%8,%9}, {%0,%1,%2,%3};"
        : "+f"(c[0]), "+f"(c[1]), "+f"(c[2]), "+f"(c[3])
        : "r"(a[0]), "r"(a[1]), "r"(a[2]), "r"(a[3]), "r"(b[0]), "r"(b[1]));
}

// =====================================================================
// tf32 tensor-core GEMM, 128x128 tiles, K-chunk 16, double-buffered,
// FRAGMENT-MAJOR smem layout:
//   A: 16 blocks (mi 0..7, ks 0..1), stride 132 words;
//      block word idx = lane*4 + c, lane = g4*4+t4,
//      c = kh*2 + hb  ->  {A[r][t4], A[r+8][t4], A[r][t4+4], A[r+8][t4+4]}
//      (exactly the m16n8k8 tf32 A fragment) -> ONE LDS.128 per fragment.
//   B: 32 blocks (nb 0..15, ks 0..1), stride 66 words;
//      block word idx = lane*2 + kh -> ONE LDS.64 per fragment.
// NT=false: B is KxN (C=A@B). NT=true: B is NxK (C=A@B^T).
// =====================================================================
template<bool NT, bool SIG, bool HASBIAS>
__global__ void __launch_bounds__(256, 2)
mma_gemm(const float* __restrict__ Ab, const float* __restrict__ Bb,
         float* __restrict__ Cb, const float* __restrict__ biasb,
         int N, int K,
         size_t sA, size_t sB, size_t sC, size_t sBias)
{
    const float* A = Ab + (size_t)blockIdx.z * sA;
    const float* B = Bb + (size_t)blockIdx.z * sB;
    float* C = Cb + (size_t)blockIdx.z * sC;
    const float* bias = HASBIAS ? biasb + (size_t)blockIdx.z * sBias : nullptr;

    __shared__ uint32_t As[2][16 * 132];
    __shared__ uint32_t Bs[2][32 * 66];

    const int tid = threadIdx.x;
    const int row0 = blockIdx.y * 128;
    const int col0 = blockIdx.x * 128;

    const int wid = tid >> 5, lane = tid & 31;
    const int wm = (wid >> 2) * 64;
    const int wn = (wid & 3) * 32;
    const int wmi0 = wm >> 4;          // 0 or 4
    const int wnb0 = wn >> 3;          // 0,4,8,12
    const int g4 = lane >> 2, t4 = lane & 3;

    // ---- staging thread mapping ----
    // A (and NT-B): warp w5 owns g4r=w5; rloc spans mi/hb (and nb for NT-B)
    const int w5 = tid >> 5;
    const int rloc = (tid & 31) >> 1;      // 0..15
    const int ksS = tid & 1;               // k-half of chunk
    const int kqS = ksS * 8;
    const int rA  = rloc * 8 + w5;         // tile-local row 0..127 (bijective)
    const int miS = rloc >> 1, hbS = rloc & 1;
    const int nbS = rloc;
    // NN-B mapping
    const int kkB = tid >> 4;              // k within chunk 0..15
    const int n0B = (tid & 15) * 8;
    const int ksB = kkB >> 3, t4B = kkB & 3, khB = (kkB >> 2) & 1;
    const int nbN = tid & 15;

    const float* Abase  = A + (size_t)(row0 + rA) * K + kqS;
    const float* BbaseT = B + (size_t)(col0 + rA) * K + kqS;

    float acc[4][4][4];
#pragma unroll
    for (int mi = 0; mi < 4; mi++)
#pragma unroll
        for (int nj = 0; nj < 4; nj++)
#pragma unroll
            for (int q = 0; q < 4; q++) acc[mi][nj][q] = 0.f;

    float a_pre[8], b_pre[8];

    auto loadStage = [&](int s) {
        const float* ap = Abase + s * 16;
        *(float4*)(a_pre)     = *(const float4*)(ap);
        *(float4*)(a_pre + 4) = *(const float4*)(ap + 4);
        if (NT) {
            const float* bp = BbaseT + s * 16;
            *(float4*)(b_pre)     = *(const float4*)(bp);
            *(float4*)(b_pre + 4) = *(const float4*)(bp + 4);
        } else {
            const float* bp = B + (size_t)(s * 16 + kkB) * N + col0 + n0B;
            *(float4*)(b_pre)     = *(const float4*)(bp);
            *(float4*)(b_pre + 4) = *(const float4*)(bp + 4);
        }
    };
    auto storeStage = [&](int bf) {
        // A: q -> (t4=q&3, kh=q>>2); word = lane_idx*4 + kh*2 + hb
        uint32_t* da = &As[bf][(miS * 2 + ksS) * 132 + w5 * 16 + hbS];
#pragma unroll
        for (int q = 0; q < 8; q++)
            da[(q & 3) * 4 + (q >> 2) * 2] = f2tf(a_pre[q]);
        if (NT) {
            uint32_t* db = &Bs[bf][(nbS * 2 + ksS) * 66 + w5 * 8];
#pragma unroll
            for (int q = 0; q < 8; q++)
                db[(q & 3) * 2 + (q >> 2)] = f2tf(b_pre[q]);
        } else {
            uint32_t* db = &Bs[bf][(nbN * 2 + ksB) * 66 + t4B * 2 + khB];
#pragma unroll
            for (int q = 0; q < 8; q++)
                db[q * 8] = f2tf(b_pre[q]);
        }
    };

    const int nS = K >> 4;
    loadStage(0);
    storeStage(0);
    __syncthreads();

    int buf = 0;
    for (int s = 0; s < nS; s++) {
        if (s + 1 < nS) loadStage(s + 1);
#pragma unroll
        for (int ks2 = 0; ks2 < 2; ks2++) {
            uint32_t afr[4][4];
#pragma unroll
            for (int mi = 0; mi < 4; mi++) {
                const uint32_t* p = &As[buf][((wmi0 + mi) * 2 + ks2) * 132 + lane * 4];
                uint4 v = *(const uint4*)p;
                afr[mi][0] = v.x; afr[mi][1] = v.y; afr[mi][2] = v.z; afr[mi][3] = v.w;
            }
            uint32_t bfr[4][2];
#pragma unroll
            for (int nj = 0; nj < 4; nj++) {
                const uint32_t* p = &Bs[buf][((wnb0 + nj) * 2 + ks2) * 66 + lane * 2];
                uint2 v = *(const uint2*)p;
                bfr[nj][0] = v.x; bfr[nj][1] = v.y;
            }
#pragma unroll
            for (int mi = 0; mi < 4; mi++)
#pragma unroll
                for (int nj = 0; nj < 4; nj++)
                    mma_tf32(acc[mi][nj], afr[mi], bfr[nj]);
        }
        if (s + 1 < nS) {
            storeStage(buf ^ 1);
            __syncthreads();
            buf ^= 1;
        }
    }

    // ---- epilogue ----
#pragma unroll
    for (int mi = 0; mi < 4; mi++) {
#pragma unroll
        for (int nj = 0; nj < 4; nj++) {
            int rr = row0 + wm + mi * 16 + g4;
            int cn = col0 + wn + nj * 8 + 2 * t4;
            float v0 = acc[mi][nj][0], v1 = acc[mi][nj][1];
            float v2 = acc[mi][nj][2], v3 = acc[mi][nj][3];
            if (HASBIAS) {
                float b0 = bias[cn], b1 = bias[cn + 1];
                v0 += b0; v1 += b1; v2 += b0; v3 += b1;
            }
            if (SIG) {
                v0 = 1.f / (1.f + expf(-v0)); v1 = 1.f / (1.f + expf(-v1));
                v2 = 1.f / (1.f + expf(-v2)); v3 = 1.f / (1.f + expf(-v3));
            }
            *(float2*)(C + (size_t)rr * N + cn)       = make_float2(v0, v1);
            *(float2*)(C + (size_t)(rr + 8) * N + cn) = make_float2(v2, v3);
        }
    }
}

// ---------------- LN over H=256 per row, fused e_src/e_dst GEMVs ----------------
__global__ void __launch_bounds__(256)
ln_esrc_kernel(const float* __restrict__ pre, float* __restrict__ h,
               const float* __restrict__ lng, const float* __restrict__ lnb,
               const float* __restrict__ Watt,
               float* __restrict__ esrc, float* __restrict__ edst)
{
    int w = (blockIdx.x * blockDim.x + threadIdx.x) >> 5;
    int lane = threadIdx.x & 31;
    int hd = w >> 14;
    const float* row = pre + (size_t)w * 256;

    float x[8];
    float s = 0.f;
#pragma unroll
    for (int i = 0; i < 8; i++) { x[i] = row[lane + 32 * i]; s += x[i]; }
#pragma unroll
    for (int off = 16; off > 0; off >>= 1) s += __shfl_xor_sync(0xffffffffu, s, off);
    float mu = s * (1.f / 256.f);

    float v = 0.f;
#pragma unroll
    for (int i = 0; i < 8; i++) { float d = x[i] - mu; v += d * d; }
#pragma unroll
    for (int off = 16; off > 0; off >>= 1) v += __shfl_xor_sync(0xffffffffu, v, off);
    float rstd = rsqrtf(v * (1.f / 256.f) + 1e-5f);

    float es = 0.f, ed = 0.f;
    float* hrow = h + (size_t)w * 256;
#pragma unroll
    for (int i = 0; i < 8; i++) {
        int c = lane + 32 * i;
        float y = (x[i] - mu) * rstd * lng[hd * 256 + c] + lnb[hd * 256 + c];
        hrow[c] = y;
        es += y * Watt[hd * 512 + c];
        ed += y * Watt[hd * 512 + 256 + c];
    }
#pragma unroll
    for (int off = 16; off > 0; off >>= 1) {
        es += __shfl_xor_sync(0xffffffffu, es, off);
        ed += __shfl_xor_sync(0xffffffffu, ed, off);
    }
    if (lane == 0) { esrc[w] = es; edst[w] = ed; }
}

// =====================================================================
// Warp-per-row attention: radix-select quantile(0.7), masked leaky-relu
// softmax, sparse alpha@h gather. No block barriers in hot path.
// =====================================================================
#define ATTN_SMEM 57344
__global__ void __launch_bounds__(256)
attn_warp(const float* __restrict__ Aprob, const float* __restrict__ h,
          const float* __restrict__ esrc, const float* __restrict__ edst,
          const float* __restrict__ batt, float* __restrict__ out)
{
    extern __shared__ char smemraw[];
    const int tid = threadIdx.x;
    const int w = tid >> 5, lane = tid & 31;
    const int hd = blockIdx.z, b = blockIdx.y;
    const int i_row = blockIdx.x * 8 + w;
    const int rowidx = hd * 16384 + b * 1024;

    unsigned int* hist = (unsigned int*)smemraw + w * 256;
    unsigned short* lst = (unsigned short*)(smemraw + 8192) + w * 1024;
    float* sE = (float*)(smemraw + 24576) + w * 1024;

    const float* rowp = Aprob + ((size_t)rowidx + i_row) * 1024;
    float av[32];
#pragma unroll
    for (int q = 0; q < 32; q++) av[q] = rowp[q * 32 + lane];

    // ---- radix select: value at ascending rank 716 ----
    unsigned int prefval = 0u, maskhi = 0u;
    int rank = 716;
#pragma unroll
    for (int shift = 24; shift >= 0; shift -= 8) {
#pragma unroll
        for (int t = 0; t < 8; t++) hist[lane * 8 + t] = 0u;
        __syncwarp();
#pragma unroll
        for (int q = 0; q < 32; q++) {
            unsigned int k = __float_as_uint(av[q]);
            if ((k & maskhi) == prefval)
                atomicAdd(&hist[(k >> shift) & 255u], 1u);
        }
        __syncwarp();
        unsigned int h8[8]; unsigned int tot = 0u;
#pragma unroll
        for (int t = 0; t < 8; t++) { h8[t] = hist[lane * 8 + t]; tot += h8[t]; }
        unsigned int incl = tot;
#pragma unroll
        for (int off = 1; off < 32; off <<= 1) {
            unsigned int v = __shfl_up_sync(0xffffffffu, incl, off);
            if (lane >= off) incl += v;
        }
        unsigned int base = incl - tot;
        int bin = -1, nr = 0;
        unsigned int run = base;
#pragma unroll
        for (int t = 0; t < 8; t++) {
            unsigned int c = run + h8[t];
            if (bin < 0 && (unsigned int)rank >= run && (unsigned int)rank < c) {
                bin = lane * 8 + t; nr = rank - (int)run;
            }
            run = c;
        }
        unsigned int mball = __ballot_sync(0xffffffffu, bin >= 0);
        int src = __ffs(mball) - 1;
        bin = __shfl_sync(0xffffffffu, bin, src);
        nr  = __shfl_sync(0xffffffffu, nr, src);
        prefval |= ((unsigned int)bin) << shift;
        maskhi  |= 0xFFu << shift;
        rank = nr;
    }
    const float v716 = __uint_as_float(prefval);

    // ---- rank 717: count <= v716 and min-above ----
    int cLE = 0; unsigned int mA = 0xFFFFFFFFu;
#pragma unroll
    for (int q = 0; q < 32; q++) {
        float a = av[q];
        if (a <= v716) cLE++;
        else { unsigned int k = __float_as_uint(a); mA = (k < mA) ? k : mA; }
    }
#pragma unroll
    for (int off = 16; off > 0; off >>= 1) {
        cLE += __shfl_xor_sync(0xffffffffu, cLE, off);
        unsigned int o = __shfl_xor_sync(0xffffffffu, mA, off);
        mA = (o < mA) ? o : mA;
    }
    const float v717 = (cLE > 717) ? v716 : __uint_as_float(mA);
    const float fr = 0.7f * 1023.0f - 716.0f;
    const float delta = v716 + fr * (v717 - v716);

    // ---- mask compaction (warp scan) ----
    int cnt = 0; unsigned short loc[32];
#pragma unroll
    for (int q = 0; q < 32; q++) {
        int j = q * 32 + lane;
        if (av[q] > delta || j == i_row) loc[cnt++] = (unsigned short)j;
    }
    int incl = cnt;
#pragma unroll
    for (int off = 1; off < 32; off <<= 1) {
        int v = __shfl_up_sync(0xffffffffu, incl, off);
        if (lane >= off) incl += v;
    }
    int base = incl - cnt;
    int total = __shfl_sync(0xffffffffu, incl, 31);
    for (int t = 0; t < cnt; t++) lst[base + t] = loc[t];
    __syncwarp();

    // ---- masked leaky-relu softmax ----
    const float eb = esrc[rowidx + i_row] + batt[hd];
    float lmax = -3.4e38f;
    for (int p = lane; p < total; p += 32) {
        int j = lst[p];
        float e = eb + edst[rowidx + j];
        e = (e >= 0.f) ? e : 0.01f * e;
        sE[p] = e;
        lmax = fmaxf(lmax, e);
    }
#pragma unroll
    for (int off = 16; off > 0; off >>= 1)
        lmax = fmaxf(lmax, __shfl_xor_sync(0xffffffffu, lmax, off));
    __syncwarp();
    float lsum = 0.f;
    for (int p = lane; p < total; p += 32) {
        float a = expf(sE[p] - lmax);
        sE[p] = a;
        lsum += a;
    }
#pragma unroll
    for (int off = 16; off > 0; off >>= 1)
        lsum += __shfl_xor_sync(0xffffffffu, lsum, off);
    const float inv = 1.f / lsum;
    __syncwarp();

    // ---- out[i_row][c] = inv * sum_p alpha_p * h[j_p][c] ----
    float a0 = 0.f, a1 = 0.f, a2 = 0.f, a3 = 0.f;
    float a4 = 0.f, a5 = 0.f, a6 = 0.f, a7 = 0.f;
    const float* hb = h + (size_t)rowidx * 256;
    for (int p = 0; p < total; p++) {
        int j = lst[p];
        float wgt = sE[p];
        const float4* hr = (const float4*)(hb + (size_t)j * 256 + lane * 8);
        float4 x0 = hr[0], x1 = hr[1];
        a0 += wgt * x0.x; a1 += wgt * x0.y; a2 += wgt * x0.z; a3 += wgt * x0.w;
        a4 += wgt * x1.x; a5 += wgt * x1.y; a6 += wgt * x1.z; a7 += wgt * x1.w;
    }
    float* op = out + ((size_t)rowidx + i_row) * 256 + lane * 8;
    *(float4*)(op)     = make_float4(a0 * inv, a1 * inv, a2 * inv, a3 * inv);
    *(float4*)(op + 4) = make_float4(a4 * inv, a5 * inv, a6 * inv, a7 * inv);
}

// ---------------- partial mean over L per (head,batch): 8 chunks of 128 ----------------
__global__ void __launch_bounds__(256)
mean_kernel(const float* __restrict__ o, float* __restrict__ meanp)
{
    int z = blockIdx.x;
    int ch = blockIdx.y;
    int c = threadIdx.x;
    const float* p = o + (size_t)z * 262144 + (size_t)ch * 128 * 256 + c;
    float s = 0.f;
    for (int l = 0; l < 128; l++) s += p[(size_t)l * 256];
    meanp[(z * 8 + ch) * 256 + c] = s;
}

// ---------------- final projections + LN ----------------
__global__ void __launch_bounds__(256)
final_kernel(const float* __restrict__ meanp,
             const float* __restrict__ Wl, const float* __restrict__ bl,
             const float* __restrict__ Ws, const float* __restrict__ bs,
             const float* __restrict__ Wc, const float* __restrict__ bc,
             const float* __restrict__ gl, const float* __restrict__ betal,
             const float* __restrict__ gs, const float* __restrict__ betas,
             const float* __restrict__ gc, const float* __restrict__ betac,
             float* __restrict__ outp)
{
    const int b = blockIdx.x, type = blockIdx.y, tid = threadIdx.x;
    __shared__ float v[1024];
    __shared__ float red[256];

    const float *W, *bias, *g, *beta;
    int K, hbase;
    if (type == 0)      { W = Wl; bias = bl; g = gl; beta = betal; K = 512;  hbase = 0; }
    else if (type == 1) { W = Ws; bias = bs; g = gs; beta = betas; K = 512;  hbase = 2; }
    else                { W = Wc; bias = bc; g = gc; beta = betac; K = 1024; hbase = 0; }

    for (int k = tid; k < K; k += 256) {
        int head = hbase + (k >> 8);
        int c = k & 255;
        float s = 0.f;
#pragma unroll
        for (int c8 = 0; c8 < 8; c8++)
            s += meanp[((head * 16 + b) * 8 + c8) * 256 + c];
        v[k] = s * (1.f / 1024.f);
    }
    __syncthreads();

    float acc[3];
#pragma unroll
    for (int q = 0; q < 3; q++) {
        int c = tid + q * 256;
        float s = bias[c];
        for (int k = 0; k < K; k++) s += v[k] * W[(size_t)k * 768 + c];
        acc[q] = s;
    }

    red[tid] = acc[0] + acc[1] + acc[2];
    __syncthreads();
    for (int off = 128; off > 0; off >>= 1) {
        if (tid < off) red[tid] += red[tid + off];
        __syncthreads();
    }
    float mu = red[0] * (1.f / 768.f);
    __syncthreads();
    float d0 = acc[0] - mu, d1 = acc[1] - mu, d2 = acc[2] - mu;
    red[tid] = d0 * d0 + d1 * d1 + d2 * d2;
    __syncthreads();
    for (int off = 128; off > 0; off >>= 1) {
        if (tid < off) red[tid] += red[tid + off];
        __syncthreads();
    }
    float rstd = rsqrtf(red[0] * (1.f / 768.f) + 1e-5f);
    __syncthreads();

#pragma unroll
    for (int q = 0; q < 3; q++) {
        int c = tid + q * 256;
        outp[(size_t)type * 16 * 768 + (size_t)b * 768 + c] =
            (acc[q] - mu) * rstd * g[c] + beta[c];
    }
}

// ---------------- launch ----------------
extern "C" void kernel_launch(void* const* d_in, const int* in_sizes, int n_in,
                              void* d_out, int out_size)
{
    const float* x      = (const float*)d_in[0];
    const float* Wfc    = (const float*)d_in[1];
    const float* bfc    = (const float*)d_in[2];
    const float* lng    = (const float*)d_in[3];
    const float* lnb    = (const float*)d_in[4];
    const float* adjw   = (const float*)d_in[5];
    const float* Watt   = (const float*)d_in[6];
    const float* batt   = (const float*)d_in[7];
    const float* Wl     = (const float*)d_in[8];
    const float* bl     = (const float*)d_in[9];
    const float* Ws     = (const float*)d_in[10];
    const float* bs     = (const float*)d_in[11];
    const float* Wc     = (const float*)d_in[12];
    const float* bc     = (const float*)d_in[13];
    const float* gl     = (const float*)d_in[14];
    const float* betal  = (const float*)d_in[15];
    const float* gs     = (const float*)d_in[16];
    const float* betas  = (const float*)d_in[17];
    const float* gc     = (const float*)d_in[18];
    const float* betac  = (const float*)d_in[19];
    float* outp = (float*)d_out;

    float *h, *tmp, *A, *ob, *esrc, *edst, *meanp;
    cudaGetSymbolAddress((void**)&h,     g_h);
    cudaGetSymbolAddress((void**)&tmp,   g_tmp);
    cudaGetSymbolAddress((void**)&A,     g_A);
    cudaGetSymbolAddress((void**)&ob,    g_out);
    cudaGetSymbolAddress((void**)&esrc,  g_esrc);
    cudaGetSymbolAddress((void**)&edst,  g_edst);
    cudaGetSymbolAddress((void**)&meanp, g_meanp);

    cudaFuncSetAttribute(attn_warp,
                         cudaFuncAttributeMaxDynamicSharedMemorySize, ATTN_SMEM);

    // K1: pre = x @ Wfc + bfc   (per head, tf32)
    mma_gemm<false, false, true><<<dim3(2, 128, 4), 256>>>(
        x, Wfc, tmp, bfc, 256, 768,
        (size_t)0, (size_t)768 * 256, (size_t)16384 * 256, (size_t)256);
    // K2: LN + e_src/e_dst
    ln_esrc_kernel<<<8192, 256>>>(tmp, h, lng, lnb, Watt, esrc, edst);
    // K3: g = h @ adjw (per head, tf32)
    mma_gemm<false, false, false><<<dim3(2, 128, 4), 256>>>(
        h, adjw, tmp, nullptr, 256, 256,
        (size_t)16384 * 256, (size_t)256 * 256, (size_t)16384 * 256, (size_t)0);
    // K4: A = sigmoid(g @ h^T) per (head,batch), tf32
    mma_gemm<true, true, false><<<dim3(8, 8, 64), 256>>>(
        tmp, h, A, nullptr, 1024, 256,
        (size_t)1024 * 256, (size_t)1024 * 256, (size_t)1024 * 1024, (size_t)0);
    // K5: warp-per-row quantile + masked softmax + sparse alpha@h
    attn_warp<<<dim3(128, 16, 4), 256, ATTN_SMEM>>>(A, h, esrc, edst, batt, ob);
    // K6: partial mean over L
    mean_kernel<<<dim3(64, 8), 256>>>(ob, meanp);
    // K7: final projections + LN
    final_kernel<<<dim3(16, 3), 256>>>(meanp, Wl, bl, Ws, bs, Wc, bc,
                                       gl, betal, gs, betas, gc, betac, outp);
}

// round 10
// speedup vs baseline: 2.9375x; 1.0236x over previous
#include <cuda_runtime.h>
#include <cstdint>
#include <cstddef>

// ---------------- static scratch ----------------
__device__ float g_h[4 * 16384 * 256];
__device__ float g_htf[4 * 16384 * 256];
__device__ float g_tmp[4 * 16384 * 256];
__device__ float g_A[4 * 16 * 1024 * 1024];
__device__ float g_out[4 * 16384 * 256];
__device__ float g_esrc[4 * 16384];
__device__ float g_edst[4 * 16384];
__device__ float g_meanp[64 * 8 * 256];
__device__ float g_xtf[16 * 1024 * 768];
__device__ float g_wfctf[4 * 768 * 256];
__device__ float g_adjtf[4 * 256 * 256];

__device__ __forceinline__ uint32_t f2tf(float x) {
    uint32_t r;
    asm("cvt.rna.tf32.f32 %0, %1;" : "=r"(r) : "f"(x));
    return r;
}

__device__ __forceinline__ void mma_tf32(float c[4], const uint32_t a[4], const uint32_t b[2]) {
    asm volatile(
        "mma.sync.aligned.m16n8k8.row.col.f32.tf32.tf32.f32 "
        "{%0,%1,%2,%3}, {%4,%5,%6,%7}, {%8,%9}, {%0,%1,%2,%3};"
        : "+f"(c[0]), "+f"(c[1]), "+f"(c[2]), "+f"(c[3])
        : "r"(a[0]), "r"(a[1]), "r"(a[2]), "r"(a[3]), "r"(b[0]), "r"(b[1]));
}

// ---------------- round fp32 -> tf32 (elementwise, float4) ----------------
__global__ void __launch_bounds__(256)
round_tf_kernel(const float* __restrict__ src, float* __restrict__ dst, int n4)
{
    int i = blockIdx.x * blockDim.x + threadIdx.x;
    if (i < n4) {
        float4 v = ((const float4*)src)[i];
        v.x = __uint_as_float(f2tf(v.x));
        v.y = __uint_as_float(f2tf(v.y));
        v.z = __uint_as_float(f2tf(v.z));
        v.w = __uint_as_float(f2tf(v.w));
        ((float4*)dst)[i] = v;
    }
}

// =====================================================================
// tf32 tensor-core GEMM, 128x128 tiles, K-chunk 16, double-buffered,
// fragment-major smem (A frag = 1 LDS.128, B frag = 1 LDS.64).
// Inputs are PRE-ROUNDED to tf32 -> staging is raw bit moves.
//   A block (mi,ks), stride 132: word = lane*4 + hb*2 + kh
//   B block (nb,ks), stride 68 (NT) / 66 (NN): word = lane*2 + kh
// NT=false: B is KxN (C=A@B). NT=true: B is NxK (C=A@B^T).
// ROUT: round output to tf32 in epilogue (for tensors feeding later GEMMs).
// =====================================================================
template<bool NT, bool SIG, bool HASBIAS, bool ROUT>
__global__ void __launch_bounds__(256, 2)
mma_gemm(const float* __restrict__ Ab, const float* __restrict__ Bb,
         float* __restrict__ Cb, const float* __restrict__ biasb,
         int N, int K,
         size_t sA, size_t sB, size_t sC, size_t sBias)
{
    constexpr int BSTR = NT ? 68 : 66;

    const float* A = Ab + (size_t)blockIdx.z * sA;
    const float* B = Bb + (size_t)blockIdx.z * sB;
    float* C = Cb + (size_t)blockIdx.z * sC;
    const float* bias = HASBIAS ? biasb + (size_t)blockIdx.z * sBias : nullptr;

    __shared__ uint32_t As[2][16 * 132];
    __shared__ uint32_t Bs[2][32 * BSTR];

    const int tid = threadIdx.x;
    const int row0 = blockIdx.y * 128;
    const int col0 = blockIdx.x * 128;

    const int wid = tid >> 5, lane = tid & 31;
    const int wm = (wid >> 2) * 64;
    const int wn = (wid & 3) * 32;
    const int wmi0 = wm >> 4;
    const int wnb0 = wn >> 3;
    const int g4 = lane >> 2, t4 = lane & 3;

    // ---- staging thread mapping ----
    const int w5 = tid >> 5;                // 0..7 (= g4 of staged rows)
    const int rloc = (tid & 31) >> 1;       // 0..15
    const int ksS = tid & 1;
    const int kqS = ksS * 8;
    const int rA  = rloc * 8 + w5;          // tile-local row, bijective
    const int miS = rloc >> 1, hbS = rloc & 1;
    const int nbS = rloc;
    // NN-B mapping
    const int kkB = tid >> 4;
    const int n0B = (tid & 15) * 8;
    const int ksB = kkB >> 3, t4B = kkB & 3, khB = (kkB >> 2) & 1;
    const int nbN = tid & 15;

    const float* Abase  = A + (size_t)(row0 + rA) * K + kqS;
    const float* BbaseT = B + (size_t)(col0 + rA) * K + kqS;

    float acc[4][4][4];
#pragma unroll
    for (int mi = 0; mi < 4; mi++)
#pragma unroll
        for (int nj = 0; nj < 4; nj++)
#pragma unroll
            for (int q = 0; q < 4; q++) acc[mi][nj][q] = 0.f;

    float a_pre[8], b_pre[8];

    auto loadStage = [&](int s) {
        const float* ap = Abase + s * 16;
        *(float4*)(a_pre)     = *(const float4*)(ap);
        *(float4*)(a_pre + 4) = *(const float4*)(ap + 4);
        if (NT) {
            const float* bp = BbaseT + s * 16;
            *(float4*)(b_pre)     = *(const float4*)(bp);
            *(float4*)(b_pre + 4) = *(const float4*)(bp + 4);
        } else {
            const float* bp = B + (size_t)(s * 16 + kkB) * N + col0 + n0B;
            *(float4*)(b_pre)     = *(const float4*)(bp);
            *(float4*)(b_pre + 4) = *(const float4*)(bp + 4);
        }
    };
    auto storeStage = [&](int bf) {
        // A: word = lane*4 + hb*2 + kh; this thread: lane=w5*4+t4(q&3), kh=q>>2
        uint32_t* da = &As[bf][(miS * 2 + ksS) * 132 + w5 * 16 + hbS * 2];
#pragma unroll
        for (int t = 0; t < 4; t++)
            *(uint2*)(da + t * 4) = make_uint2(__float_as_uint(a_pre[t]),
                                               __float_as_uint(a_pre[t + 4]));
        if (NT) {
            uint32_t tmp[8];
#pragma unroll
            for (int q = 0; q < 8; q++)
                tmp[(q & 3) * 2 + (q >> 2)] = __float_as_uint(b_pre[q]);
            uint32_t* db = &Bs[bf][(nbS * 2 + ksS) * BSTR + w5 * 8];
            *(uint4*)(db)     = *(uint4*)(tmp);
            *(uint4*)(db + 4) = *(uint4*)(tmp + 4);
        } else {
            uint32_t* db = &Bs[bf][(nbN * 2 + ksB) * BSTR + t4B * 2 + khB];
#pragma unroll
            for (int q = 0; q < 8; q++)
                db[q * 8] = __float_as_uint(b_pre[q]);
        }
    };

    const int nS = K >> 4;
    loadStage(0);
    storeStage(0);
    __syncthreads();

    int buf = 0;
    for (int s = 0; s < nS; s++) {
        if (s + 1 < nS) loadStage(s + 1);
#pragma unroll
        for (int ks2 = 0; ks2 < 2; ks2++) {
            uint32_t afr[4][4];
#pragma unroll
            for (int mi = 0; mi < 4; mi++) {
                const uint32_t* p = &As[buf][((wmi0 + mi) * 2 + ks2) * 132 + lane * 4];
                uint4 v = *(const uint4*)p;
                // c = hb*2 + kh: frag order (hb,kh) = (0,0),(1,0),(0,1),(1,1)
                afr[mi][0] = v.x; afr[mi][1] = v.z; afr[mi][2] = v.y; afr[mi][3] = v.w;
            }
            uint32_t bfr[4][2];
#pragma unroll
            for (int nj = 0; nj < 4; nj++) {
                const uint32_t* p = &Bs[buf][((wnb0 + nj) * 2 + ks2) * BSTR + lane * 2];
                uint2 v = *(const uint2*)p;
                bfr[nj][0] = v.x; bfr[nj][1] = v.y;
            }
#pragma unroll
            for (int mi = 0; mi < 4; mi++)
#pragma unroll
                for (int nj = 0; nj < 4; nj++)
                    mma_tf32(acc[mi][nj], afr[mi], bfr[nj]);
        }
        if (s + 1 < nS) {
            storeStage(buf ^ 1);
            __syncthreads();
            buf ^= 1;
        }
    }

    // ---- epilogue ----
#pragma unroll
    for (int mi = 0; mi < 4; mi++) {
#pragma unroll
        for (int nj = 0; nj < 4; nj++) {
            int rr = row0 + wm + mi * 16 + g4;
            int cn = col0 + wn + nj * 8 + 2 * t4;
            float v0 = acc[mi][nj][0], v1 = acc[mi][nj][1];
            float v2 = acc[mi][nj][2], v3 = acc[mi][nj][3];
            if (HASBIAS) {
                float b0 = bias[cn], b1 = bias[cn + 1];
                v0 += b0; v1 += b1; v2 += b0; v3 += b1;
            }
            if (SIG) {
                v0 = 1.f / (1.f + expf(-v0)); v1 = 1.f / (1.f + expf(-v1));
                v2 = 1.f / (1.f + expf(-v2)); v3 = 1.f / (1.f + expf(-v3));
            }
            if (ROUT) {
                v0 = __uint_as_float(f2tf(v0)); v1 = __uint_as_float(f2tf(v1));
                v2 = __uint_as_float(f2tf(v2)); v3 = __uint_as_float(f2tf(v3));
            }
            *(float2*)(C + (size_t)rr * N + cn)       = make_float2(v0, v1);
            *(float2*)(C + (size_t)(rr + 8) * N + cn) = make_float2(v2, v3);
        }
    }
}

// ---------------- LN over H=256 per row, fused e_src/e_dst GEMVs ----------------
// also emits tf32-rounded copy of h for the downstream GEMMs
__global__ void __launch_bounds__(256)
ln_esrc_kernel(const float* __restrict__ pre, float* __restrict__ h,
               float* __restrict__ htf,
               const float* __restrict__ lng, const float* __restrict__ lnb,
               const float* __restrict__ Watt,
               float* __restrict__ esrc, float* __restrict__ edst)
{
    int w = (blockIdx.x * blockDim.x + threadIdx.x) >> 5;
    int lane = threadIdx.x & 31;
    int hd = w >> 14;
    const float* row = pre + (size_t)w * 256;

    float x[8];
    float s = 0.f;
#pragma unroll
    for (int i = 0; i < 8; i++) { x[i] = row[lane + 32 * i]; s += x[i]; }
#pragma unroll
    for (int off = 16; off > 0; off >>= 1) s += __shfl_xor_sync(0xffffffffu, s, off);
    float mu = s * (1.f / 256.f);

    float v = 0.f;
#pragma unroll
    for (int i = 0; i < 8; i++) { float d = x[i] - mu; v += d * d; }
#pragma unroll
    for (int off = 16; off > 0; off >>= 1) v += __shfl_xor_sync(0xffffffffu, v, off);
    float rstd = rsqrtf(v * (1.f / 256.f) + 1e-5f);

    float es = 0.f, ed = 0.f;
    float* hrow = h + (size_t)w * 256;
    float* trow = htf + (size_t)w * 256;
#pragma unroll
    for (int i = 0; i < 8; i++) {
        int c = lane + 32 * i;
        float y = (x[i] - mu) * rstd * lng[hd * 256 + c] + lnb[hd * 256 + c];
        hrow[c] = y;
        trow[c] = __uint_as_float(f2tf(y));
        es += y * Watt[hd * 512 + c];
        ed += y * Watt[hd * 512 + 256 + c];
    }
#pragma unroll
    for (int off = 16; off > 0; off >>= 1) {
        es += __shfl_xor_sync(0xffffffffu, es, off);
        ed += __shfl_xor_sync(0xffffffffu, ed, off);
    }
    if (lane == 0) { esrc[w] = es; edst[w] = ed; }
}

// =====================================================================
// Warp-per-row attention: radix-select quantile(0.7), masked leaky-relu
// softmax, sparse alpha@h gather. No block barriers in hot path.
// =====================================================================
#define ATTN_SMEM 57344
__global__ void __launch_bounds__(256)
attn_warp(const float* __restrict__ Aprob, const float* __restrict__ h,
          const float* __restrict__ esrc, const float* __restrict__ edst,
          const float* __restrict__ batt, float* __restrict__ out)
{
    extern __shared__ char smemraw[];
    const int tid = threadIdx.x;
    const int w = tid >> 5, lane = tid & 31;
    const int hd = blockIdx.z, b = blockIdx.y;
    const int i_row = blockIdx.x * 8 + w;
    const int rowidx = hd * 16384 + b * 1024;

    unsigned int* hist = (unsigned int*)smemraw + w * 256;
    unsigned short* lst = (unsigned short*)(smemraw + 8192) + w * 1024;
    float* sE = (float*)(smemraw + 24576) + w * 1024;

    const float* rowp = Aprob + ((size_t)rowidx + i_row) * 1024;
    float av[32];
#pragma unroll
    for (int q = 0; q < 32; q++) av[q] = rowp[q * 32 + lane];

    // ---- radix select: value at ascending rank 716 ----
    unsigned int prefval = 0u, maskhi = 0u;
    int rank = 716;
#pragma unroll
    for (int shift = 24; shift >= 0; shift -= 8) {
#pragma unroll
        for (int t = 0; t < 8; t++) hist[lane * 8 + t] = 0u;
        __syncwarp();
#pragma unroll
        for (int q = 0; q < 32; q++) {
            unsigned int k = __float_as_uint(av[q]);
            if ((k & maskhi) == prefval)
                atomicAdd(&hist[(k >> shift) & 255u], 1u);
        }
        __syncwarp();
        unsigned int h8[8]; unsigned int tot = 0u;
#pragma unroll
        for (int t = 0; t < 8; t++) { h8[t] = hist[lane * 8 + t]; tot += h8[t]; }
        unsigned int incl = tot;
#pragma unroll
        for (int off = 1; off < 32; off <<= 1) {
            unsigned int v = __shfl_up_sync(0xffffffffu, incl, off);
            if (lane >= off) incl += v;
        }
        unsigned int base = incl - tot;
        int bin = -1, nr = 0;
        unsigned int run = base;
#pragma unroll
        for (int t = 0; t < 8; t++) {
            unsigned int c = run + h8[t];
            if (bin < 0 && (unsigned int)rank >= run && (unsigned int)rank < c) {
                bin = lane * 8 + t; nr = rank - (int)run;
            }
            run = c;
        }
        unsigned int mball = __ballot_sync(0xffffffffu, bin >= 0);
        int src = __ffs(mball) - 1;
        bin = __shfl_sync(0xffffffffu, bin, src);
        nr  = __shfl_sync(0xffffffffu, nr, src);
        prefval |= ((unsigned int)bin) << shift;
        maskhi  |= 0xFFu << shift;
        rank = nr;
    }
    const float v716 = __uint_as_float(prefval);

    // ---- rank 717: count <= v716 and min-above ----
    int cLE = 0; unsigned int mA = 0xFFFFFFFFu;
#pragma unroll
    for (int q = 0; q < 32; q++) {
        float a = av[q];
        if (a <= v716) cLE++;
        else { unsigned int k = __float_as_uint(a); mA = (k < mA) ? k : mA; }
    }
#pragma unroll
    for (int off = 16; off > 0; off >>= 1) {
        cLE += __shfl_xor_sync(0xffffffffu, cLE, off);
        unsigned int o = __shfl_xor_sync(0xffffffffu, mA, off);
        mA = (o < mA) ? o : mA;
    }
    const float v717 = (cLE > 717) ? v716 : __uint_as_float(mA);
    const float fr = 0.7f * 1023.0f - 716.0f;
    const float delta = v716 + fr * (v717 - v716);

    // ---- mask compaction (warp scan) ----
    int cnt = 0; unsigned short loc[32];
#pragma unroll
    for (int q = 0; q < 32; q++) {
        int j = q * 32 + lane;
        if (av[q] > delta || j == i_row) loc[cnt++] = (unsigned short)j;
    }
    int incl = cnt;
#pragma unroll
    for (int off = 1; off < 32; off <<= 1) {
        int v = __shfl_up_sync(0xffffffffu, incl, off);
        if (lane >= off) incl += v;
    }
    int base = incl - cnt;
    int total = __shfl_sync(0xffffffffu, incl, 31);
    for (int t = 0; t < cnt; t++) lst[base + t] = loc[t];
    __syncwarp();

    // ---- masked leaky-relu softmax ----
    const float eb = esrc[rowidx + i_row] + batt[hd];
    float lmax = -3.4e38f;
    for (int p = lane; p < total; p += 32) {
        int j = lst[p];
        float e = eb + edst[rowidx + j];
        e = (e >= 0.f) ? e : 0.01f * e;
        sE[p] = e;
        lmax = fmaxf(lmax, e);
    }
#pragma unroll
    for (int off = 16; off > 0; off >>= 1)
        lmax = fmaxf(lmax, __shfl_xor_sync(0xffffffffu, lmax, off));
    __syncwarp();
    float lsum = 0.f;
    for (int p = lane; p < total; p += 32) {
        float a = expf(sE[p] - lmax);
        sE[p] = a;
        lsum += a;
    }
#pragma unroll
    for (int off = 16; off > 0; off >>= 1)
        lsum += __shfl_xor_sync(0xffffffffu, lsum, off);
    const float inv = 1.f / lsum;
    __syncwarp();

    // ---- out[i_row][c] = inv * sum_p alpha_p * h[j_p][c] ----
    float a0 = 0.f, a1 = 0.f, a2 = 0.f, a3 = 0.f;
    float a4 = 0.f, a5 = 0.f, a6 = 0.f, a7 = 0.f;
    const float* hb = h + (size_t)rowidx * 256;
    for (int p = 0; p < total; p++) {
        int j = lst[p];
        float wgt = sE[p];
        const float4* hr = (const float4*)(hb + (size_t)j * 256 + lane * 8);
        float4 x0 = hr[0], x1 = hr[1];
        a0 += wgt * x0.x; a1 += wgt * x0.y; a2 += wgt * x0.z; a3 += wgt * x0.w;
        a4 += wgt * x1.x; a5 += wgt * x1.y; a6 += wgt * x1.z; a7 += wgt * x1.w;
    }
    float* op = out + ((size_t)rowidx + i_row) * 256 + lane * 8;
    *(float4*)(op)     = make_float4(a0 * inv, a1 * inv, a2 * inv, a3 * inv);
    *(float4*)(op + 4) = make_float4(a4 * inv, a5 * inv, a6 * inv, a7 * inv);
}

// ---------------- partial mean over L per (head,batch): 8 chunks of 128 ----------------
__global__ void __launch_bounds__(256)
mean_kernel(const float* __restrict__ o, float* __restrict__ meanp)
{
    int z = blockIdx.x;
    int ch = blockIdx.y;
    int c = threadIdx.x;
    const float* p = o + (size_t)z * 262144 + (size_t)ch * 128 * 256 + c;
    float s = 0.f;
    for (int l = 0; l < 128; l++) s += p[(size_t)l * 256];
    meanp[(z * 8 + ch) * 256 + c] = s;
}

// ---------------- final projections + LN ----------------
__global__ void __launch_bounds__(256)
final_kernel(const float* __restrict__ meanp,
             const float* __restrict__ Wl, const float* __restrict__ bl,
             const float* __restrict__ Ws, const float* __restrict__ bs,
             const float* __restrict__ Wc, const float* __restrict__ bc,
             const float* __restrict__ gl, const float* __restrict__ betal,
             const float* __restrict__ gs, const float* __restrict__ betas,
             const float* __restrict__ gc, const float* __restrict__ betac,
             float* __restrict__ outp)
{
    const int b = blockIdx.x, type = blockIdx.y, tid = threadIdx.x;
    __shared__ float v[1024];
    __shared__ float red[256];

    const float *W, *bias, *g, *beta;
    int K, hbase;
    if (type == 0)      { W = Wl; bias = bl; g = gl; beta = betal; K = 512;  hbase = 0; }
    else if (type == 1) { W = Ws; bias = bs; g = gs; beta = betas; K = 512;  hbase = 2; }
    else                { W = Wc; bias = bc; g = gc; beta = betac; K = 1024; hbase = 0; }

    for (int k = tid; k < K; k += 256) {
        int head = hbase + (k >> 8);
        int c = k & 255;
        float s = 0.f;
#pragma unroll
        for (int c8 = 0; c8 < 8; c8++)
            s += meanp[((head * 16 + b) * 8 + c8) * 256 + c];
        v[k] = s * (1.f / 1024.f);
    }
    __syncthreads();

    float acc[3];
#pragma unroll
    for (int q = 0; q < 3; q++) {
        int c = tid + q * 256;
        float s = bias[c];
        for (int k = 0; k < K; k++) s += v[k] * W[(size_t)k * 768 + c];
        acc[q] = s;
    }

    red[tid] = acc[0] + acc[1] + acc[2];
    __syncthreads();
    for (int off = 128; off > 0; off >>= 1) {
        if (tid < off) red[tid] += red[tid + off];
        __syncthreads();
    }
    float mu = red[0] * (1.f / 768.f);
    __syncthreads();
    float d0 = acc[0] - mu, d1 = acc[1] - mu, d2 = acc[2] - mu;
    red[tid] = d0 * d0 + d1 * d1 + d2 * d2;
    __syncthreads();
    for (int off = 128; off > 0; off >>= 1) {
        if (tid < off) red[tid] += red[tid + off];
        __syncthreads();
    }
    float rstd = rsqrtf(red[0] * (1.f / 768.f) + 1e-5f);
    __syncthreads();

#pragma unroll
    for (int q = 0; q < 3; q++) {
        int c = tid + q * 256;
        outp[(size_t)type * 16 * 768 + (size_t)b * 768 + c] =
            (acc[q] - mu) * rstd * g[c] + beta[c];
    }
}

// ---------------- launch ----------------
extern "C" void kernel_launch(void* const* d_in, const int* in_sizes, int n_in,
                              void* d_out, int out_size)
{
    const float* x      = (const float*)d_in[0];
    const float* Wfc    = (const float*)d_in[1];
    const float* bfc    = (const float*)d_in[2];
    const float* lng    = (const float*)d_in[3];
    const float* lnb    = (const float*)d_in[4];
    const float* adjw   = (const float*)d_in[5];
    const float* Watt   = (const float*)d_in[6];
    const float* batt   = (const float*)d_in[7];
    const float* Wl     = (const float*)d_in[8];
    const float* bl     = (const float*)d_in[9];
    const float* Ws     = (const float*)d_in[10];
    const float* bs     = (const float*)d_in[11];
    const float* Wc     = (const float*)d_in[12];
    const float* bc     = (const float*)d_in[13];
    const float* gl     = (const float*)d_in[14];
    const float* betal  = (const float*)d_in[15];
    const float* gs     = (const float*)d_in[16];
    const float* betas  = (const float*)d_in[17];
    const float* gc     = (const float*)d_in[18];
    const float* betac  = (const float*)d_in[19];
    float* outp = (float*)d_out;

    float *h, *htf, *tmp, *A, *ob, *esrc, *edst, *meanp, *xtf, *wtf, *atf;
    cudaGetSymbolAddress((void**)&h,     g_h);
    cudaGetSymbolAddress((void**)&htf,   g_htf);
    cudaGetSymbolAddress((void**)&tmp,   g_tmp);
    cudaGetSymbolAddress((void**)&A,     g_A);
    cudaGetSymbolAddress((void**)&ob,    g_out);
    cudaGetSymbolAddress((void**)&esrc,  g_esrc);
    cudaGetSymbolAddress((void**)&edst,  g_edst);
    cudaGetSymbolAddress((void**)&meanp, g_meanp);
    cudaGetSymbolAddress((void**)&xtf,   g_xtf);
    cudaGetSymbolAddress((void**)&wtf,   g_wfctf);
    cudaGetSymbolAddress((void**)&atf,   g_adjtf);

    cudaFuncSetAttribute(attn_warp,
                         cudaFuncAttributeMaxDynamicSharedMemorySize, ATTN_SMEM);

    // K0: pre-round GEMM operands to tf32
    round_tf_kernel<<<(16 * 1024 * 768 / 4 + 255) / 256, 256>>>(x, xtf, 16 * 1024 * 768 / 4);
    round_tf_kernel<<<(4 * 768 * 256 / 4 + 255) / 256, 256>>>(Wfc, wtf, 4 * 768 * 256 / 4);
    round_tf_kernel<<<(4 * 256 * 256 / 4 + 255) / 256, 256>>>(adjw, atf, 4 * 256 * 256 / 4);

    // K1: pre = x @ Wfc + bfc   (per head, tf32)
    mma_gemm<false, false, true, false><<<dim3(2, 128, 4), 256>>>(
        xtf, wtf, tmp, bfc, 256, 768,
        (size_t)0, (size_t)768 * 256, (size_t)16384 * 256, (size_t)256);
    // K2: LN + e_src/e_dst (+ rounded h copy)
    ln_esrc_kernel<<<8192, 256>>>(tmp, h, htf, lng, lnb, Watt, esrc, edst);
    // K3: g = h @ adjw (per head, tf32), output rounded (feeds K4 only)
    mma_gemm<false, false, false, true><<<dim3(2, 128, 4), 256>>>(
        htf, atf, tmp, nullptr, 256, 256,
        (size_t)16384 * 256, (size_t)256 * 256, (size_t)16384 * 256, (size_t)0);
    // K4: A = sigmoid(g @ h^T) per (head,batch), tf32
    mma_gemm<true, true, false, false><<<dim3(8, 8, 64), 256>>>(
        tmp, htf, A, nullptr, 1024, 256,
        (size_t)1024 * 256, (size_t)1024 * 256, (size_t)1024 * 1024, (size_t)0);
    // K5: warp-per-row quantile + masked softmax + sparse alpha@h
    attn_warp<<<dim3(128, 16, 4), 256, ATTN_SMEM>>>(A, h, esrc, edst, batt, ob);
    // K6: partial mean over L
    mean_kernel<<<dim3(64, 8), 256>>>(ob, meanp);
    // K7: final projections + LN
    final_kernel<<<dim3(16, 3), 256>>>(meanp, Wl, bl, Ws, bs, Wc, bc,
                                       gl, betal, gs, betas, gc, betac, outp);
}

// round 11
// speedup vs baseline: 3.0725x; 1.0459x over previous
#include <cuda_runtime.h>
#include <cuda_fp16.h>
#include <cstdint>
#include <cstddef>

// ---------------- static scratch ----------------
__device__ float g_h[4 * 16384 * 256];
__device__ float g_htf[4 * 16384 * 256];
__device__ float g_tmp[4 * 16384 * 256];
__device__ __half g_A[4 * 16 * 1024 * 1024];
__device__ float g_out[4 * 16384 * 256];
__device__ float g_esrc[4 * 16384];
__device__ float g_edst[4 * 16384];
__device__ float g_meanp[64 * 8 * 256];
__device__ float g_xtf[16 * 1024 * 768];
__device__ float g_wfctf[4 * 768 * 256];
__device__ float g_adjtf[4 * 256 * 256];

__device__ __forceinline__ uint32_t f2tf(float x) {
    uint32_t r;
    asm("cvt.rna.tf32.f32 %0, %1;" : "=r"(r) : "f"(x));
    return r;
}

__device__ __forceinline__ void mma_tf32(float c[4], const uint32_t a[4], const uint32_t b[2]) {
    asm volatile(
        "mma.sync.aligned.m16n8k8.row.col.f32.tf32.tf32.f32 "
        "{%0,%1,%2,%3}, {%4,%5,%6,%7}, {%8,%9}, {%0,%1,%2,%3};"
        : "+f"(c[0]), "+f"(c[1]), "+f"(c[2]), "+f"(c[3])
        : "r"(a[0]), "r"(a[1]), "r"(a[2]), "r"(a[3]), "r"(b[0]), "r"(b[1]));
}

// ---------------- round fp32 -> tf32 (elementwise, float4) ----------------
__global__ void __launch_bounds__(256)
round_tf_kernel(const float* __restrict__ src, float* __restrict__ dst, int n4)
{
    int i = blockIdx.x * blockDim.x + threadIdx.x;
    if (i < n4) {
        float4 v = ((const float4*)src)[i];
        v.x = __uint_as_float(f2tf(v.x));
        v.y = __uint_as_float(f2tf(v.y));
        v.z = __uint_as_float(f2tf(v.z));
        v.w = __uint_as_float(f2tf(v.w));
        ((float4*)dst)[i] = v;
    }
}

// =====================================================================
// tf32 tensor-core GEMM, 128x128 tiles, K-chunk 16, double-buffered,
// fragment-major smem. Inputs pre-rounded to tf32.
// NT: B is NxK (C=A@B^T). SIG: sigmoid epilogue. ROUT: round output tf32.
// HOUT: C is __half* (sC/N in half elements), writes half2.
// =====================================================================
template<bool NT, bool SIG, bool HASBIAS, bool ROUT, bool HOUT>
__global__ void __launch_bounds__(256, 2)
mma_gemm(const float* __restrict__ Ab, const float* __restrict__ Bb,
         void* __restrict__ Cb, const float* __restrict__ biasb,
         int N, int K,
         size_t sA, size_t sB, size_t sC, size_t sBias)
{
    constexpr int BSTR = NT ? 68 : 66;

    const float* A = Ab + (size_t)blockIdx.z * sA;
    const float* B = Bb + (size_t)blockIdx.z * sB;
    float* Cf = HOUT ? nullptr : (float*)Cb + (size_t)blockIdx.z * sC;
    __half* Ch = HOUT ? (__half*)Cb + (size_t)blockIdx.z * sC : nullptr;
    const float* bias = HASBIAS ? biasb + (size_t)blockIdx.z * sBias : nullptr;

    __shared__ uint32_t As[2][16 * 132];
    __shared__ uint32_t Bs[2][32 * BSTR];

    const int tid = threadIdx.x;
    const int row0 = blockIdx.y * 128;
    const int col0 = blockIdx.x * 128;

    const int wid = tid >> 5, lane = tid & 31;
    const int wm = (wid >> 2) * 64;
    const int wn = (wid & 3) * 32;
    const int wmi0 = wm >> 4;
    const int wnb0 = wn >> 3;
    const int g4 = lane >> 2, t4 = lane & 3;

    const int w5 = tid >> 5;
    const int rloc = (tid & 31) >> 1;
    const int ksS = tid & 1;
    const int kqS = ksS * 8;
    const int rA  = rloc * 8 + w5;
    const int miS = rloc >> 1, hbS = rloc & 1;
    const int nbS = rloc;
    const int kkB = tid >> 4;
    const int n0B = (tid & 15) * 8;
    const int ksB = kkB >> 3, t4B = kkB & 3, khB = (kkB >> 2) & 1;
    const int nbN = tid & 15;

    const float* Abase  = A + (size_t)(row0 + rA) * K + kqS;
    const float* BbaseT = B + (size_t)(col0 + rA) * K + kqS;

    float acc[4][4][4];
#pragma unroll
    for (int mi = 0; mi < 4; mi++)
#pragma unroll
        for (int nj = 0; nj < 4; nj++)
#pragma unroll
            for (int q = 0; q < 4; q++) acc[mi][nj][q] = 0.f;

    float a_pre[8], b_pre[8];

    auto loadStage = [&](int s) {
        const float* ap = Abase + s * 16;
        *(float4*)(a_pre)     = *(const float4*)(ap);
        *(float4*)(a_pre + 4) = *(const float4*)(ap + 4);
        if (NT) {
            const float* bp = BbaseT + s * 16;
            *(float4*)(b_pre)     = *(const float4*)(bp);
            *(float4*)(b_pre + 4) = *(const float4*)(bp + 4);
        } else {
            const float* bp = B + (size_t)(s * 16 + kkB) * N + col0 + n0B;
            *(float4*)(b_pre)     = *(const float4*)(bp);
            *(float4*)(b_pre + 4) = *(const float4*)(bp + 4);
        }
    };
    auto storeStage = [&](int bf) {
        uint32_t* da = &As[bf][(miS * 2 + ksS) * 132 + w5 * 16 + hbS * 2];
#pragma unroll
        for (int t = 0; t < 4; t++)
            *(uint2*)(da + t * 4) = make_uint2(__float_as_uint(a_pre[t]),
                                               __float_as_uint(a_pre[t + 4]));
        if (NT) {
            uint32_t tmp[8];
#pragma unroll
            for (int q = 0; q < 8; q++)
                tmp[(q & 3) * 2 + (q >> 2)] = __float_as_uint(b_pre[q]);
            uint32_t* db = &Bs[bf][(nbS * 2 + ksS) * BSTR + w5 * 8];
            *(uint4*)(db)     = *(uint4*)(tmp);
            *(uint4*)(db + 4) = *(uint4*)(tmp + 4);
        } else {
            uint32_t* db = &Bs[bf][(nbN * 2 + ksB) * BSTR + t4B * 2 + khB];
#pragma unroll
            for (int q = 0; q < 8; q++)
                db[q * 8] = __float_as_uint(b_pre[q]);
        }
    };

    const int nS = K >> 4;
    loadStage(0);
    storeStage(0);
    __syncthreads();

    int buf = 0;
    for (int s = 0; s < nS; s++) {
        if (s + 1 < nS) loadStage(s + 1);
#pragma unroll
        for (int ks2 = 0; ks2 < 2; ks2++) {
            uint32_t afr[4][4];
#pragma unroll
            for (int mi = 0; mi < 4; mi++) {
                const uint32_t* p = &As[buf][((wmi0 + mi) * 2 + ks2) * 132 + lane * 4];
                uint4 v = *(const uint4*)p;
                afr[mi][0] = v.x; afr[mi][1] = v.z; afr[mi][2] = v.y; afr[mi][3] = v.w;
            }
            uint32_t bfr[4][2];
#pragma unroll
            for (int nj = 0; nj < 4; nj++) {
                const uint32_t* p = &Bs[buf][((wnb0 + nj) * 2 + ks2) * BSTR + lane * 2];
                uint2 v = *(const uint2*)p;
                bfr[nj][0] = v.x; bfr[nj][1] = v.y;
            }
#pragma unroll
            for (int mi = 0; mi < 4; mi++)
#pragma unroll
                for (int nj = 0; nj < 4; nj++)
                    mma_tf32(acc[mi][nj], afr[mi], bfr[nj]);
        }
        if (s + 1 < nS) {
            storeStage(buf ^ 1);
            __syncthreads();
            buf ^= 1;
        }
    }

    // ---- epilogue ----
#pragma unroll
    for (int mi = 0; mi < 4; mi++) {
#pragma unroll
        for (int nj = 0; nj < 4; nj++) {
            int rr = row0 + wm + mi * 16 + g4;
            int cn = col0 + wn + nj * 8 + 2 * t4;
            float v0 = acc[mi][nj][0], v1 = acc[mi][nj][1];
            float v2 = acc[mi][nj][2], v3 = acc[mi][nj][3];
            if (HASBIAS) {
                float b0 = bias[cn], b1 = bias[cn + 1];
                v0 += b0; v1 += b1; v2 += b0; v3 += b1;
            }
            if (SIG) {
                v0 = 1.f / (1.f + expf(-v0)); v1 = 1.f / (1.f + expf(-v1));
                v2 = 1.f / (1.f + expf(-v2)); v3 = 1.f / (1.f + expf(-v3));
            }
            if (ROUT) {
                v0 = __uint_as_float(f2tf(v0)); v1 = __uint_as_float(f2tf(v1));
                v2 = __uint_as_float(f2tf(v2)); v3 = __uint_as_float(f2tf(v3));
            }
            if (HOUT) {
                *(half2*)(Ch + (size_t)rr * N + cn)       = __floats2half2_rn(v0, v1);
                *(half2*)(Ch + (size_t)(rr + 8) * N + cn) = __floats2half2_rn(v2, v3);
            } else {
                *(float2*)(Cf + (size_t)rr * N + cn)       = make_float2(v0, v1);
                *(float2*)(Cf + (size_t)(rr + 8) * N + cn) = make_float2(v2, v3);
            }
        }
    }
}

// ---------------- LN over H=256 per row, fused e_src/e_dst GEMVs ----------------
__global__ void __launch_bounds__(256)
ln_esrc_kernel(const float* __restrict__ pre, float* __restrict__ h,
               float* __restrict__ htf,
               const float* __restrict__ lng, const float* __restrict__ lnb,
               const float* __restrict__ Watt,
               float* __restrict__ esrc, float* __restrict__ edst)
{
    int w = (blockIdx.x * blockDim.x + threadIdx.x) >> 5;
    int lane = threadIdx.x & 31;
    int hd = w >> 14;
    const float* row = pre + (size_t)w * 256;

    float x[8];
    float s = 0.f;
#pragma unroll
    for (int i = 0; i < 8; i++) { x[i] = row[lane + 32 * i]; s += x[i]; }
#pragma unroll
    for (int off = 16; off > 0; off >>= 1) s += __shfl_xor_sync(0xffffffffu, s, off);
    float mu = s * (1.f / 256.f);

    float v = 0.f;
#pragma unroll
    for (int i = 0; i < 8; i++) { float d = x[i] - mu; v += d * d; }
#pragma unroll
    for (int off = 16; off > 0; off >>= 1) v += __shfl_xor_sync(0xffffffffu, v, off);
    float rstd = rsqrtf(v * (1.f / 256.f) + 1e-5f);

    float es = 0.f, ed = 0.f;
    float* hrow = h + (size_t)w * 256;
    float* trow = htf + (size_t)w * 256;
#pragma unroll
    for (int i = 0; i < 8; i++) {
        int c = lane + 32 * i;
        float y = (x[i] - mu) * rstd * lng[hd * 256 + c] + lnb[hd * 256 + c];
        hrow[c] = y;
        trow[c] = __uint_as_float(f2tf(y));
        es += y * Watt[hd * 512 + c];
        ed += y * Watt[hd * 512 + 256 + c];
    }
#pragma unroll
    for (int off = 16; off > 0; off >>= 1) {
        es += __shfl_xor_sync(0xffffffffu, es, off);
        ed += __shfl_xor_sync(0xffffffffu, ed, off);
    }
    if (lane == 0) { esrc[w] = es; edst[w] = ed; }
}

// =====================================================================
// Warp-per-row attention on fp16 A: 2-pass radix-select quantile(0.7),
// masked leaky-relu softmax, sparse alpha@h gather.
// grid (128, 16, 4), block 256 (8 warps = 8 rows), dyn smem 57344 B.
// =====================================================================
#define ATTN_SMEM 57344
__global__ void __launch_bounds__(256)
attn_warp(const __half* __restrict__ Aprob, const float* __restrict__ h,
          const float* __restrict__ esrc, const float* __restrict__ edst,
          const float* __restrict__ batt, float* __restrict__ out)
{
    extern __shared__ char smemraw[];
    const int tid = threadIdx.x;
    const int w = tid >> 5, lane = tid & 31;
    const int hd = blockIdx.z, b = blockIdx.y;
    const int i_row = blockIdx.x * 8 + w;
    const int rowidx = hd * 16384 + b * 1024;

    unsigned int* hist = (unsigned int*)smemraw + w * 256;
    unsigned short* lst = (unsigned short*)(smemraw + 8192) + w * 1024;
    float* sE = (float*)(smemraw + 24576) + w * 1024;

    // ---- load row: 16 words = 32 halves per lane; elem j = (q*32+lane)*2 + t
    const uint32_t* rowp = (const uint32_t*)(Aprob + ((size_t)rowidx + i_row) * 1024);
    uint32_t av[16];
#pragma unroll
    for (int q = 0; q < 16; q++) av[q] = rowp[q * 32 + lane];

    // ---- 2-pass radix select: value at ascending rank 716 (u16 keys, A>=0)
    unsigned int prefval = 0u, maskhi = 0u;
    int rank = 716;
#pragma unroll
    for (int shift = 8; shift >= 0; shift -= 8) {
#pragma unroll
        for (int t = 0; t < 8; t++) hist[lane * 8 + t] = 0u;
        __syncwarp();
#pragma unroll
        for (int q = 0; q < 16; q++) {
            unsigned int k0 = av[q] & 0xFFFFu;
            unsigned int k1 = av[q] >> 16;
            if ((k0 & maskhi) == prefval) atomicAdd(&hist[(k0 >> shift) & 255u], 1u);
            if ((k1 & maskhi) == prefval) atomicAdd(&hist[(k1 >> shift) & 255u], 1u);
        }
        __syncwarp();
        unsigned int h8[8]; unsigned int tot = 0u;
#pragma unroll
        for (int t = 0; t < 8; t++) { h8[t] = hist[lane * 8 + t]; tot += h8[t]; }
        unsigned int incl = tot;
#pragma unroll
        for (int off = 1; off < 32; off <<= 1) {
            unsigned int v = __shfl_up_sync(0xffffffffu, incl, off);
            if (lane >= off) incl += v;
        }
        unsigned int base = incl - tot;
        int bin = -1, nr = 0;
        unsigned int run = base;
#pragma unroll
        for (int t = 0; t < 8; t++) {
            unsigned int c = run + h8[t];
            if (bin < 0 && (unsigned int)rank >= run && (unsigned int)rank < c) {
                bin = lane * 8 + t; nr = rank - (int)run;
            }
            run = c;
        }
        unsigned int mball = __ballot_sync(0xffffffffu, bin >= 0);
        int src = __ffs(mball) - 1;
        bin = __shfl_sync(0xffffffffu, bin, src);
        nr  = __shfl_sync(0xffffffffu, nr, src);
        prefval |= ((unsigned int)bin) << shift;
        maskhi  |= 0xFFu << shift;
        rank = nr;
    }
    const float v716 = __half2float(__ushort_as_half((unsigned short)prefval));

    // ---- rank 717: count <= key716 and min-above (u16 space) ----
    int cLE = 0; unsigned int mA = 0xFFFFFFFFu;
#pragma unroll
    for (int q = 0; q < 16; q++) {
        unsigned int k0 = av[q] & 0xFFFFu;
        unsigned int k1 = av[q] >> 16;
        if (k0 <= prefval) cLE++; else mA = (k0 < mA) ? k0 : mA;
        if (k1 <= prefval) cLE++; else mA = (k1 < mA) ? k1 : mA;
    }
#pragma unroll
    for (int off = 16; off > 0; off >>= 1) {
        cLE += __shfl_xor_sync(0xffffffffu, cLE, off);
        unsigned int o = __shfl_xor_sync(0xffffffffu, mA, off);
        mA = (o < mA) ? o : mA;
    }
    const float v717 = (cLE > 717) ? v716
                     : __half2float(__ushort_as_half((unsigned short)mA));
    const float fr = 0.7f * 1023.0f - 716.0f;
    const float delta = v716 + fr * (v717 - v716);

    // ---- mask compaction: count, scan, then write (no local array) ----
    int cnt = 0;
#pragma unroll
    for (int q = 0; q < 16; q++) {
        float a0 = __half2float(__ushort_as_half((unsigned short)(av[q] & 0xFFFFu)));
        float a1 = __half2float(__ushort_as_half((unsigned short)(av[q] >> 16)));
        int j0 = (q * 32 + lane) * 2, j1 = j0 + 1;
        if (a0 > delta || j0 == i_row) cnt++;
        if (a1 > delta || j1 == i_row) cnt++;
    }
    int incl = cnt;
#pragma unroll
    for (int off = 1; off < 32; off <<= 1) {
        int v = __shfl_up_sync(0xffffffffu, incl, off);
        if (lane >= off) incl += v;
    }
    int pos = incl - cnt;
    int total = __shfl_sync(0xffffffffu, incl, 31);
#pragma unroll
    for (int q = 0; q < 16; q++) {
        float a0 = __half2float(__ushort_as_half((unsigned short)(av[q] & 0xFFFFu)));
        float a1 = __half2float(__ushort_as_half((unsigned short)(av[q] >> 16)));
        int j0 = (q * 32 + lane) * 2, j1 = j0 + 1;
        if (a0 > delta || j0 == i_row) lst[pos++] = (unsigned short)j0;
        if (a1 > delta || j1 == i_row) lst[pos++] = (unsigned short)j1;
    }
    __syncwarp();

    // ---- masked leaky-relu softmax ----
    const float eb = esrc[rowidx + i_row] + batt[hd];
    float lmax = -3.4e38f;
    for (int p = lane; p < total; p += 32) {
        int j = lst[p];
        float e = eb + edst[rowidx + j];
        e = (e >= 0.f) ? e : 0.01f * e;
        sE[p] = e;
        lmax = fmaxf(lmax, e);
    }
#pragma unroll
    for (int off = 16; off > 0; off >>= 1)
        lmax = fmaxf(lmax, __shfl_xor_sync(0xffffffffu, lmax, off));
    __syncwarp();
    float lsum = 0.f;
    for (int p = lane; p < total; p += 32) {
        float a = expf(sE[p] - lmax);
        sE[p] = a;
        lsum += a;
    }
#pragma unroll
    for (int off = 16; off > 0; off >>= 1)
        lsum += __shfl_xor_sync(0xffffffffu, lsum, off);
    const float inv = 1.f / lsum;
    __syncwarp();

    // ---- out[i_row][c] = inv * sum_p alpha_p * h[j_p][c] ----
    float a0 = 0.f, a1 = 0.f, a2 = 0.f, a3 = 0.f;
    float a4 = 0.f, a5 = 0.f, a6 = 0.f, a7 = 0.f;
    const float* hb = h + (size_t)rowidx * 256;
    for (int p = 0; p < total; p++) {
        int j = lst[p];
        float wgt = sE[p];
        const float4* hr = (const float4*)(hb + (size_t)j * 256 + lane * 8);
        float4 x0 = hr[0], x1 = hr[1];
        a0 += wgt * x0.x; a1 += wgt * x0.y; a2 += wgt * x0.z; a3 += wgt * x0.w;
        a4 += wgt * x1.x; a5 += wgt * x1.y; a6 += wgt * x1.z; a7 += wgt * x1.w;
    }
    float* op = out + ((size_t)rowidx + i_row) * 256 + lane * 8;
    *(float4*)(op)     = make_float4(a0 * inv, a1 * inv, a2 * inv, a3 * inv);
    *(float4*)(op + 4) = make_float4(a4 * inv, a5 * inv, a6 * inv, a7 * inv);
}

// ---------------- partial mean over L per (head,batch): 8 chunks of 128 ----------------
__global__ void __launch_bounds__(256)
mean_kernel(const float* __restrict__ o, float* __restrict__ meanp)
{
    int z = blockIdx.x;
    int ch = blockIdx.y;
    int c = threadIdx.x;
    const float* p = o + (size_t)z * 262144 + (size_t)ch * 128 * 256 + c;
    float s = 0.f;
    for (int l = 0; l < 128; l++) s += p[(size_t)l * 256];
    meanp[(z * 8 + ch) * 256 + c] = s;
}

// ---------------- final projections + LN ----------------
__global__ void __launch_bounds__(256)
final_kernel(const float* __restrict__ meanp,
             const float* __restrict__ Wl, const float* __restrict__ bl,
             const float* __restrict__ Ws, const float* __restrict__ bs,
             const float* __restrict__ Wc, const float* __restrict__ bc,
             const float* __restrict__ gl, const float* __restrict__ betal,
             const float* __restrict__ gs, const float* __restrict__ betas,
             const float* __restrict__ gc, const float* __restrict__ betac,
             float* __restrict__ outp)
{
    const int b = blockIdx.x, type = blockIdx.y, tid = threadIdx.x;
    __shared__ float v[1024];
    __shared__ float red[256];

    const float *W, *bias, *g, *beta;
    int K, hbase;
    if (type == 0)      { W = Wl; bias = bl; g = gl; beta = betal; K = 512;  hbase = 0; }
    else if (type == 1) { W = Ws; bias = bs; g = gs; beta = betas; K = 512;  hbase = 2; }
    else                { W = Wc; bias = bc; g = gc; beta = betac; K = 1024; hbase = 0; }

    for (int k = tid; k < K; k += 256) {
        int head = hbase + (k >> 8);
        int c = k & 255;
        float s = 0.f;
#pragma unroll
        for (int c8 = 0; c8 < 8; c8++)
            s += meanp[((head * 16 + b) * 8 + c8) * 256 + c];
        v[k] = s * (1.f / 1024.f);
    }
    __syncthreads();

    float acc[3];
#pragma unroll
    for (int q = 0; q < 3; q++) {
        int c = tid + q * 256;
        float s = bias[c];
        for (int k = 0; k < K; k++) s += v[k] * W[(size_t)k * 768 + c];
        acc[q] = s;
    }

    red[tid] = acc[0] + acc[1] + acc[2];
    __syncthreads();
    for (int off = 128; off > 0; off >>= 1) {
        if (tid < off) red[tid] += red[tid + off];
        __syncthreads();
    }
    float mu = red[0] * (1.f / 768.f);
    __syncthreads();
    float d0 = acc[0] - mu, d1 = acc[1] - mu, d2 = acc[2] - mu;
    red[tid] = d0 * d0 + d1 * d1 + d2 * d2;
    __syncthreads();
    for (int off = 128; off > 0; off >>= 1) {
        if (tid < off) red[tid] += red[tid + off];
        __syncthreads();
    }
    float rstd = rsqrtf(red[0] * (1.f / 768.f) + 1e-5f);
    __syncthreads();

#pragma unroll
    for (int q = 0; q < 3; q++) {
        int c = tid + q * 256;
        outp[(size_t)type * 16 * 768 + (size_t)b * 768 + c] =
            (acc[q] - mu) * rstd * g[c] + beta[c];
    }
}

// ---------------- launch ----------------
extern "C" void kernel_launch(void* const* d_in, const int* in_sizes, int n_in,
                              void* d_out, int out_size)
{
    const float* x      = (const float*)d_in[0];
    const float* Wfc    = (const float*)d_in[1];
    const float* bfc    = (const float*)d_in[2];
    const float* lng    = (const float*)d_in[3];
    const float* lnb    = (const float*)d_in[4];
    const float* adjw   = (const float*)d_in[5];
    const float* Watt   = (const float*)d_in[6];
    const float* batt   = (const float*)d_in[7];
    const float* Wl     = (const float*)d_in[8];
    const float* bl     = (const float*)d_in[9];
    const float* Ws     = (const float*)d_in[10];
    const float* bs     = (const float*)d_in[11];
    const float* Wc     = (const float*)d_in[12];
    const float* bc     = (const float*)d_in[13];
    const float* gl     = (const float*)d_in[14];
    const float* betal  = (const float*)d_in[15];
    const float* gs     = (const float*)d_in[16];
    const float* betas  = (const float*)d_in[17];
    const float* gc     = (const float*)d_in[18];
    const float* betac  = (const float*)d_in[19];
    float* outp = (float*)d_out;

    float *h, *htf, *tmp, *ob, *esrc, *edst, *meanp, *xtf, *wtf, *atf;
    __half* A;
    cudaGetSymbolAddress((void**)&h,     g_h);
    cudaGetSymbolAddress((void**)&htf,   g_htf);
    cudaGetSymbolAddress((void**)&tmp,   g_tmp);
    cudaGetSymbolAddress((void**)&A,     g_A);
    cudaGetSymbolAddress((void**)&ob,    g_out);
    cudaGetSymbolAddress((void**)&esrc,  g_esrc);
    cudaGetSymbolAddress((void**)&edst,  g_edst);
    cudaGetSymbolAddress((void**)&meanp, g_meanp);
    cudaGetSymbolAddress((void**)&xtf,   g_xtf);
    cudaGetSymbolAddress((void**)&wtf,   g_wfctf);
    cudaGetSymbolAddress((void**)&atf,   g_adjtf);

    cudaFuncSetAttribute(attn_warp,
                         cudaFuncAttributeMaxDynamicSharedMemorySize, ATTN_SMEM);

    // K0: pre-round GEMM operands to tf32
    round_tf_kernel<<<(16 * 1024 * 768 / 4 + 255) / 256, 256>>>(x, xtf, 16 * 1024 * 768 / 4);
    round_tf_kernel<<<(4 * 768 * 256 / 4 + 255) / 256, 256>>>(Wfc, wtf, 4 * 768 * 256 / 4);
    round_tf_kernel<<<(4 * 256 * 256 / 4 + 255) / 256, 256>>>(adjw, atf, 4 * 256 * 256 / 4);

    // K1: pre = x @ Wfc + bfc   (per head, tf32)
    mma_gemm<false, false, true, false, false><<<dim3(2, 128, 4), 256>>>(
        xtf, wtf, tmp, bfc, 256, 768,
        (size_t)0, (size_t)768 * 256, (size_t)16384 * 256, (size_t)256);
    // K2: LN + e_src/e_dst (+ rounded h copy)
    ln_esrc_kernel<<<8192, 256>>>(tmp, h, htf, lng, lnb, Watt, esrc, edst);
    // K3: g = h @ adjw (per head, tf32), output rounded (feeds K4 only)
    mma_gemm<false, false, false, true, false><<<dim3(2, 128, 4), 256>>>(
        htf, atf, tmp, nullptr, 256, 256,
        (size_t)16384 * 256, (size_t)256 * 256, (size_t)16384 * 256, (size_t)0);
    // K4: A = sigmoid(g @ h^T) per (head,batch), tf32, fp16 output
    mma_gemm<true, true, false, false, true><<<dim3(8, 8, 64), 256>>>(
        tmp, htf, A, nullptr, 1024, 256,
        (size_t)1024 * 256, (size_t)1024 * 256, (size_t)1024 * 1024, (size_t)0);
    // K5: warp-per-row quantile + masked softmax + sparse alpha@h (fp16 A)
    attn_warp<<<dim3(128, 16, 4), 256, ATTN_SMEM>>>(A, h, esrc, edst, batt, ob);
    // K6: partial mean over L
    mean_kernel<<<dim3(64, 8), 256>>>(ob, meanp);
    // K7: final projections + LN
    final_kernel<<<dim3(16, 3), 256>>>(meanp, Wl, bl, Ws, bs, Wc, bc,
                                       gl, betal, gs, betas, gc, betac, outp);
}

// round 12
// speedup vs baseline: 3.8599x; 1.2563x over previous
#include <cuda_runtime.h>
#include <cuda_fp16.h>
#include <cstdint>
#include <cstddef>

// ---------------- static scratch ----------------
__device__ float  g_h[4 * 16384 * 256];
__device__ __half g_htf[4 * 16384 * 256];
__device__ float  g_tmp[4 * 16384 * 256];
__device__ __half g_g[4 * 16384 * 256];
__device__ __half g_A[4 * 16 * 1024 * 1024];
__device__ float  g_out[4 * 16384 * 256];
__device__ float  g_esrc[4 * 16384];
__device__ float  g_edst[4 * 16384];
__device__ float  g_meanp[64 * 8 * 256];
__device__ __half g_xh[16 * 1024 * 768];
__device__ __half g_wh[4 * 256 * 768];    // Wfc^T per head: N x K
__device__ __half g_ah[4 * 256 * 256];    // adjw^T per head: N x K

__device__ __forceinline__ void mma_f16(float c[4], const uint32_t a[4], const uint32_t b[2]) {
    asm volatile(
        "mma.sync.aligned.m16n8k16.row.col.f32.f16.f16.f32 "
        "{%0,%1,%2,%3}, {%4,%5,%6,%7}, {%8,%9}, {%0,%1,%2,%3};"
        : "+f"(c[0]), "+f"(c[1]), "+f"(c[2]), "+f"(c[3])
        : "r"(a[0]), "r"(a[1]), "r"(a[2]), "r"(a[3]), "r"(b[0]), "r"(b[1]));
}

// ---------------- fp32 -> fp16 elementwise (pairs) ----------------
__global__ void __launch_bounds__(256)
conv_half(const float* __restrict__ src, __half* __restrict__ dst, int n2)
{
    int i = blockIdx.x * blockDim.x + threadIdx.x;
    if (i < n2) {
        float2 v = ((const float2*)src)[i];
        ((half2*)dst)[i] = __floats2half2_rn(v.x, v.y);
    }
}

// ---------------- fp32 KxN -> fp16 NxK transpose (per z) ----------------
__global__ void __launch_bounds__(256)
convT_half(const float* __restrict__ src, __half* __restrict__ dst, int K, int N)
{
    __shared__ float tile[32][33];
    const int k0 = blockIdx.x * 32, n0 = blockIdx.y * 32, z = blockIdx.z;
    src += (size_t)z * K * N;
    dst += (size_t)z * K * N;
    const int tx = threadIdx.x & 31, ty = threadIdx.x >> 5;   // 32 x 8
#pragma unroll
    for (int i = ty; i < 32; i += 8)
        tile[i][tx] = src[(size_t)(k0 + i) * N + n0 + tx];
    __syncthreads();
#pragma unroll
    for (int i = ty; i < 32; i += 8)
        dst[(size_t)(n0 + i) * K + k0 + tx] = __float2half(tile[tx][i]);
}

// =====================================================================
// fp16 tensor-core GEMM (m16n8k16), C = A @ B^T, A: MxK, B: NxK (both
// fp16 row-major). 128x128 tiles, K-chunk 16, double-buffered,
// fragment-major smem: A frag = 1 LDS.128, B frag = 1 LDS.64.
// SIG: sigmoid epilogue. HASBIAS: +bias. HOUT: fp16 output.
// =====================================================================
template<bool SIG, bool HASBIAS, bool HOUT>
__global__ void __launch_bounds__(256, 2)
hgemm(const __half* __restrict__ Ab, const __half* __restrict__ Bb,
      void* __restrict__ Cb, const float* __restrict__ biasb,
      int N, int K, size_t sA, size_t sB, size_t sC, size_t sBias)
{
    const __half* A = Ab + (size_t)blockIdx.z * sA;
    const __half* B = Bb + (size_t)blockIdx.z * sB;
    float* Cf = HOUT ? nullptr : (float*)Cb + (size_t)blockIdx.z * sC;
    __half* Ch = HOUT ? (__half*)Cb + (size_t)blockIdx.z * sC : nullptr;
    const float* bias = HASBIAS ? biasb + (size_t)blockIdx.z * sBias : nullptr;

    __shared__ uint32_t As[2][8 * 132];    // blocks mi 0..7; word = lane*4 + (ks*2+hb)
    __shared__ uint32_t Bs[2][16 * 66];    // blocks nb 0..15; word = lane*2 + ks

    const int tid = threadIdx.x;
    const int row0 = blockIdx.y * 128;
    const int col0 = blockIdx.x * 128;

    const int wid = tid >> 5, lane = tid & 31;
    const int wm = (wid >> 2) * 64;
    const int wn = (wid & 3) * 32;
    const int wmi0 = wm >> 4;               // 0 or 4
    const int wnb0 = wn >> 3;               // 0,4,8,12
    const int g4 = lane >> 2, t4 = lane & 3;

    // staging: warp w5 supplies lane-group g4=w5; rloc spans (mi,hb)/nb; ksS k-half
    const int w5 = tid >> 5;
    const int rloc = (tid & 31) >> 1;       // 0..15
    const int ksS = tid & 1;
    const int kq = ksS * 8;
    const int rA  = rloc * 8 + w5;          // tile-local row/col, bijective
    const int miS = rloc >> 1, hbS = rloc & 1;
    const int nbS = rloc;

    const __half* Abase = A + (size_t)(row0 + rA) * K + kq;
    const __half* Bbase = B + (size_t)(col0 + rA) * K + kq;

    float acc[4][4][4];
#pragma unroll
    for (int mi = 0; mi < 4; mi++)
#pragma unroll
        for (int nj = 0; nj < 4; nj++)
#pragma unroll
            for (int q = 0; q < 4; q++) acc[mi][nj][q] = 0.f;

    uint32_t a_pre[4], b_pre[4];

    auto loadStage = [&](int s) {
        *(uint4*)a_pre = *(const uint4*)(Abase + s * 16);
        *(uint4*)b_pre = *(const uint4*)(Bbase + s * 16);
    };
    auto storeStage = [&](int bf) {
        // A: word = miS*132 + (w5*4 + j)*4 + ksS*2 + hbS   (j = t4 of frag)
        uint32_t* da = &As[bf][miS * 132 + w5 * 16 + ksS * 2 + hbS];
#pragma unroll
        for (int j = 0; j < 4; j++) da[j * 4] = a_pre[j];
        // B: word = nbS*66 + (w5*4 + j)*2 + ksS
        uint32_t* db = &Bs[bf][nbS * 66 + w5 * 8 + ksS];
#pragma unroll
        for (int j = 0; j < 4; j++) db[j * 2] = b_pre[j];
    };

    const int nS = K >> 4;
    loadStage(0);
    storeStage(0);
    __syncthreads();

    int buf = 0;
    for (int s = 0; s < nS; s++) {
        if (s + 1 < nS) loadStage(s + 1);
        uint32_t afr[4][4];
#pragma unroll
        for (int mi = 0; mi < 4; mi++) {
            uint4 v = *(const uint4*)&As[buf][(wmi0 + mi) * 132 + lane * 4];
            afr[mi][0] = v.x; afr[mi][1] = v.y; afr[mi][2] = v.z; afr[mi][3] = v.w;
        }
        uint32_t bfr[4][2];
#pragma unroll
        for (int nj = 0; nj < 4; nj++) {
            uint2 v = *(const uint2*)&Bs[buf][(wnb0 + nj) * 66 + lane * 2];
            bfr[nj][0] = v.x; bfr[nj][1] = v.y;
        }
#pragma unroll
        for (int mi = 0; mi < 4; mi++)
#pragma unroll
            for (int nj = 0; nj < 4; nj++)
                mma_f16(acc[mi][nj], afr[mi], bfr[nj]);
        if (s + 1 < nS) {
            storeStage(buf ^ 1);
            __syncthreads();
            buf ^= 1;
        }
    }

    // ---- epilogue ----
#pragma unroll
    for (int mi = 0; mi < 4; mi++) {
#pragma unroll
        for (int nj = 0; nj < 4; nj++) {
            int rr = row0 + wm + mi * 16 + g4;
            int cn = col0 + wn + nj * 8 + 2 * t4;
            float v0 = acc[mi][nj][0], v1 = acc[mi][nj][1];
            float v2 = acc[mi][nj][2], v3 = acc[mi][nj][3];
            if (HASBIAS) {
                float b0 = bias[cn], b1 = bias[cn + 1];
                v0 += b0; v1 += b1; v2 += b0; v3 += b1;
            }
            if (SIG) {
                v0 = 1.f / (1.f + expf(-v0)); v1 = 1.f / (1.f + expf(-v1));
                v2 = 1.f / (1.f + expf(-v2)); v3 = 1.f / (1.f + expf(-v3));
            }
            if (HOUT) {
                *(half2*)(Ch + (size_t)rr * N + cn)       = __floats2half2_rn(v0, v1);
                *(half2*)(Ch + (size_t)(rr + 8) * N + cn) = __floats2half2_rn(v2, v3);
            } else {
                *(float2*)(Cf + (size_t)rr * N + cn)       = make_float2(v0, v1);
                *(float2*)(Cf + (size_t)(rr + 8) * N + cn) = make_float2(v2, v3);
            }
        }
    }
}

// ---------------- LN over H=256 per row, fused e_src/e_dst GEMVs ----------------
__global__ void __launch_bounds__(256)
ln_esrc_kernel(const float* __restrict__ pre, float* __restrict__ h,
               __half* __restrict__ htf,
               const float* __restrict__ lng, const float* __restrict__ lnb,
               const float* __restrict__ Watt,
               float* __restrict__ esrc, float* __restrict__ edst)
{
    int w = (blockIdx.x * blockDim.x + threadIdx.x) >> 5;
    int lane = threadIdx.x & 31;
    int hd = w >> 14;
    const float* row = pre + (size_t)w * 256;

    float x[8];
    float s = 0.f;
#pragma unroll
    for (int i = 0; i < 8; i++) { x[i] = row[lane + 32 * i]; s += x[i]; }
#pragma unroll
    for (int off = 16; off > 0; off >>= 1) s += __shfl_xor_sync(0xffffffffu, s, off);
    float mu = s * (1.f / 256.f);

    float v = 0.f;
#pragma unroll
    for (int i = 0; i < 8; i++) { float d = x[i] - mu; v += d * d; }
#pragma unroll
    for (int off = 16; off > 0; off >>= 1) v += __shfl_xor_sync(0xffffffffu, v, off);
    float rstd = rsqrtf(v * (1.f / 256.f) + 1e-5f);

    float es = 0.f, ed = 0.f;
    float* hrow = h + (size_t)w * 256;
    __half* trow = htf + (size_t)w * 256;
#pragma unroll
    for (int i = 0; i < 8; i++) {
        int c = lane + 32 * i;
        float y = (x[i] - mu) * rstd * lng[hd * 256 + c] + lnb[hd * 256 + c];
        hrow[c] = y;
        trow[c] = __float2half(y);
        es += y * Watt[hd * 512 + c];
        ed += y * Watt[hd * 512 + 256 + c];
    }
#pragma unroll
    for (int off = 16; off > 0; off >>= 1) {
        es += __shfl_xor_sync(0xffffffffu, es, off);
        ed += __shfl_xor_sync(0xffffffffu, ed, off);
    }
    if (lane == 0) { esrc[w] = es; edst[w] = ed; }
}

// =====================================================================
// Warp-per-row attention on fp16 A: 2-pass radix-select quantile(0.7),
// masked leaky-relu softmax, sparse alpha@h gather.
// =====================================================================
#define ATTN_SMEM 57344
__global__ void __launch_bounds__(256)
attn_warp(const __half* __restrict__ Aprob, const float* __restrict__ h,
          const float* __restrict__ esrc, const float* __restrict__ edst,
          const float* __restrict__ batt, float* __restrict__ out)
{
    extern __shared__ char smemraw[];
    const int tid = threadIdx.x;
    const int w = tid >> 5, lane = tid & 31;
    const int hd = blockIdx.z, b = blockIdx.y;
    const int i_row = blockIdx.x * 8 + w;
    const int rowidx = hd * 16384 + b * 1024;

    unsigned int* hist = (unsigned int*)smemraw + w * 256;
    unsigned short* lst = (unsigned short*)(smemraw + 8192) + w * 1024;
    float* sE = (float*)(smemraw + 24576) + w * 1024;

    const uint32_t* rowp = (const uint32_t*)(Aprob + ((size_t)rowidx + i_row) * 1024);
    uint32_t av[16];
#pragma unroll
    for (int q = 0; q < 16; q++) av[q] = rowp[q * 32 + lane];

    // ---- 2-pass radix select: rank 716 (u16 keys, A>=0 monotonic) ----
    unsigned int prefval = 0u, maskhi = 0u;
    int rank = 716;
#pragma unroll
    for (int shift = 8; shift >= 0; shift -= 8) {
#pragma unroll
        for (int t = 0; t < 8; t++) hist[lane * 8 + t] = 0u;
        __syncwarp();
#pragma unroll
        for (int q = 0; q < 16; q++) {
            unsigned int k0 = av[q] & 0xFFFFu;
            unsigned int k1 = av[q] >> 16;
            if ((k0 & maskhi) == prefval) atomicAdd(&hist[(k0 >> shift) & 255u], 1u);
            if ((k1 & maskhi) == prefval) atomicAdd(&hist[(k1 >> shift) & 255u], 1u);
        }
        __syncwarp();
        unsigned int h8[8]; unsigned int tot = 0u;
#pragma unroll
        for (int t = 0; t < 8; t++) { h8[t] = hist[lane * 8 + t]; tot += h8[t]; }
        unsigned int incl = tot;
#pragma unroll
        for (int off = 1; off < 32; off <<= 1) {
            unsigned int v = __shfl_up_sync(0xffffffffu, incl, off);
            if (lane >= off) incl += v;
        }
        unsigned int base = incl - tot;
        int bin = -1, nr = 0;
        unsigned int run = base;
#pragma unroll
        for (int t = 0; t < 8; t++) {
            unsigned int c = run + h8[t];
            if (bin < 0 && (unsigned int)rank >= run && (unsigned int)rank < c) {
                bin = lane * 8 + t; nr = rank - (int)run;
            }
            run = c;
        }
        unsigned int mball = __ballot_sync(0xffffffffu, bin >= 0);
        int src = __ffs(mball) - 1;
        bin = __shfl_sync(0xffffffffu, bin, src);
        nr  = __shfl_sync(0xffffffffu, nr, src);
        prefval |= ((unsigned int)bin) << shift;
        maskhi  |= 0xFFu << shift;
        rank = nr;
    }
    const float v716 = __half2float(__ushort_as_half((unsigned short)prefval));

    // ---- rank 717: count <= key716 and min-above ----
    int cLE = 0; unsigned int mA = 0xFFFFFFFFu;
#pragma unroll
    for (int q = 0; q < 16; q++) {
        unsigned int k0 = av[q] & 0xFFFFu;
        unsigned int k1 = av[q] >> 16;
        if (k0 <= prefval) cLE++; else mA = (k0 < mA) ? k0 : mA;
        if (k1 <= prefval) cLE++; else mA = (k1 < mA) ? k1 : mA;
    }
#pragma unroll
    for (int off = 16; off > 0; off >>= 1) {
        cLE += __shfl_xor_sync(0xffffffffu, cLE, off);
        unsigned int o = __shfl_xor_sync(0xffffffffu, mA, off);
        mA = (o < mA) ? o : mA;
    }
    const float v717 = (cLE > 717) ? v716
                     : __half2float(__ushort_as_half((unsigned short)mA));
    const float fr = 0.7f * 1023.0f - 716.0f;
    const float delta = v716 + fr * (v717 - v716);

    // ---- mask compaction: count, scan, then write ----
    int cnt = 0;
#pragma unroll
    for (int q = 0; q < 16; q++) {
        float a0 = __half2float(__ushort_as_half((unsigned short)(av[q] & 0xFFFFu)));
        float a1 = __half2float(__ushort_as_half((unsigned short)(av[q] >> 16)));
        int j0 = (q * 32 + lane) * 2, j1 = j0 + 1;
        if (a0 > delta || j0 == i_row) cnt++;
        if (a1 > delta || j1 == i_row) cnt++;
    }
    int incl = cnt;
#pragma unroll
    for (int off = 1; off < 32; off <<= 1) {
        int v = __shfl_up_sync(0xffffffffu, incl, off);
        if (lane >= off) incl += v;
    }
    int pos = incl - cnt;
    int total = __shfl_sync(0xffffffffu, incl, 31);
#pragma unroll
    for (int q = 0; q < 16; q++) {
        float a0 = __half2float(__ushort_as_half((unsigned short)(av[q] & 0xFFFFu)));
        float a1 = __half2float(__ushort_as_half((unsigned short)(av[q] >> 16)));
        int j0 = (q * 32 + lane) * 2, j1 = j0 + 1;
        if (a0 > delta || j0 == i_row) lst[pos++] = (unsigned short)j0;
        if (a1 > delta || j1 == i_row) lst[pos++] = (unsigned short)j1;
    }
    __syncwarp();

    // ---- masked leaky-relu softmax ----
    const float eb = esrc[rowidx + i_row] + batt[hd];
    float lmax = -3.4e38f;
    for (int p = lane; p < total; p += 32) {
        int j = lst[p];
        float e = eb + edst[rowidx + j];
        e = (e >= 0.f) ? e : 0.01f * e;
        sE[p] = e;
        lmax = fmaxf(lmax, e);
    }
#pragma unroll
    for (int off = 16; off > 0; off >>= 1)
        lmax = fmaxf(lmax, __shfl_xor_sync(0xffffffffu, lmax, off));
    __syncwarp();
    float lsum = 0.f;
    for (int p = lane; p < total; p += 32) {
        float a = expf(sE[p] - lmax);
        sE[p] = a;
        lsum += a;
    }
#pragma unroll
    for (int off = 16; off > 0; off >>= 1)
        lsum += __shfl_xor_sync(0xffffffffu, lsum, off);
    const float inv = 1.f / lsum;
    __syncwarp();

    // ---- out[i_row][c] = inv * sum_p alpha_p * h[j_p][c] ----
    float a0 = 0.f, a1 = 0.f, a2 = 0.f, a3 = 0.f;
    float a4 = 0.f, a5 = 0.f, a6 = 0.f, a7 = 0.f;
    const float* hb = h + (size_t)rowidx * 256;
    for (int p = 0; p < total; p++) {
        int j = lst[p];
        float wgt = sE[p];
        const float4* hr = (const float4*)(hb + (size_t)j * 256 + lane * 8);
        float4 x0 = hr[0], x1 = hr[1];
        a0 += wgt * x0.x; a1 += wgt * x0.y; a2 += wgt * x0.z; a3 += wgt * x0.w;
        a4 += wgt * x1.x; a5 += wgt * x1.y; a6 += wgt * x1.z; a7 += wgt * x1.w;
    }
    float* op = out + ((size_t)rowidx + i_row) * 256 + lane * 8;
    *(float4*)(op)     = make_float4(a0 * inv, a1 * inv, a2 * inv, a3 * inv);
    *(float4*)(op + 4) = make_float4(a4 * inv, a5 * inv, a6 * inv, a7 * inv);
}

// ---------------- partial mean over L per (head,batch): 8 chunks of 128 ----------------
__global__ void __launch_bounds__(256)
mean_kernel(const float* __restrict__ o, float* __restrict__ meanp)
{
    int z = blockIdx.x;
    int ch = blockIdx.y;
    int c = threadIdx.x;
    const float* p = o + (size_t)z * 262144 + (size_t)ch * 128 * 256 + c;
    float s = 0.f;
    for (int l = 0; l < 128; l++) s += p[(size_t)l * 256];
    meanp[(z * 8 + ch) * 256 + c] = s;
}

// ---------------- final projections + LN ----------------
__global__ void __launch_bounds__(256)
final_kernel(const float* __restrict__ meanp,
             const float* __restrict__ Wl, const float* __restrict__ bl,
             const float* __restrict__ Ws, const float* __restrict__ bs,
             const float* __restrict__ Wc, const float* __restrict__ bc,
             const float* __restrict__ gl, const float* __restrict__ betal,
             const float* __restrict__ gs, const float* __restrict__ betas,
             const float* __restrict__ gc, const float* __restrict__ betac,
             float* __restrict__ outp)
{
    const int b = blockIdx.x, type = blockIdx.y, tid = threadIdx.x;
    __shared__ float v[1024];
    __shared__ float red[256];

    const float *W, *bias, *g, *beta;
    int K, hbase;
    if (type == 0)      { W = Wl; bias = bl; g = gl; beta = betal; K = 512;  hbase = 0; }
    else if (type == 1) { W = Ws; bias = bs; g = gs; beta = betas; K = 512;  hbase = 2; }
    else                { W = Wc; bias = bc; g = gc; beta = betac; K = 1024; hbase = 0; }

    for (int k = tid; k < K; k += 256) {
        int head = hbase + (k >> 8);
        int c = k & 255;
        float s = 0.f;
#pragma unroll
        for (int c8 = 0; c8 < 8; c8++)
            s += meanp[((head * 16 + b) * 8 + c8) * 256 + c];
        v[k] = s * (1.f / 1024.f);
    }
    __syncthreads();

    float acc[3];
#pragma unroll
    for (int q = 0; q < 3; q++) {
        int c = tid + q * 256;
        float s = bias[c];
        for (int k = 0; k < K; k++) s += v[k] * W[(size_t)k * 768 + c];
        acc[q] = s;
    }

    red[tid] = acc[0] + acc[1] + acc[2];
    __syncthreads();
    for (int off = 128; off > 0; off >>= 1) {
        if (tid < off) red[tid] += red[tid + off];
        __syncthreads();
    }
    float mu = red[0] * (1.f / 768.f);
    __syncthreads();
    float d0 = acc[0] - mu, d1 = acc[1] - mu, d2 = acc[2] - mu;
    red[tid] = d0 * d0 + d1 * d1 + d2 * d2;
    __syncthreads();
    for (int off = 128; off > 0; off >>= 1) {
        if (tid < off) red[tid] += red[tid + off];
        __syncthreads();
    }
    float rstd = rsqrtf(red[0] * (1.f / 768.f) + 1e-5f);
    __syncthreads();

#pragma unroll
    for (int q = 0; q < 3; q++) {
        int c = tid + q * 256;
        outp[(size_t)type * 16 * 768 + (size_t)b * 768 + c] =
            (acc[q] - mu) * rstd * g[c] + beta[c];
    }
}

// ---------------- launch ----------------
extern "C" void kernel_launch(void* const* d_in, const int* in_sizes, int n_in,
                              void* d_out, int out_size)
{
    const float* x      = (const float*)d_in[0];
    const float* Wfc    = (const float*)d_in[1];
    const float* bfc    = (const float*)d_in[2];
    const float* lng    = (const float*)d_in[3];
    const float* lnb    = (const float*)d_in[4];
    const float* adjw   = (const float*)d_in[5];
    const float* Watt   = (const float*)d_in[6];
    const float* batt   = (const float*)d_in[7];
    const float* Wl     = (const float*)d_in[8];
    const float* bl     = (const float*)d_in[9];
    const float* Ws     = (const float*)d_in[10];
    const float* bs     = (const float*)d_in[11];
    const float* Wc     = (const float*)d_in[12];
    const float* bc     = (const float*)d_in[13];
    const float* gl     = (const float*)d_in[14];
    const float* betal  = (const float*)d_in[15];
    const float* gs     = (const float*)d_in[16];
    const float* betas  = (const float*)d_in[17];
    const float* gc     = (const float*)d_in[18];
    const float* betac  = (const float*)d_in[19];
    float* outp = (float*)d_out;

    float *h, *tmp, *ob, *esrc, *edst, *meanp;
    __half *htf, *gg, *A, *xh, *wh, *ah;
    cudaGetSymbolAddress((void**)&h,     g_h);
    cudaGetSymbolAddress((void**)&htf,   g_htf);
    cudaGetSymbolAddress((void**)&tmp,   g_tmp);
    cudaGetSymbolAddress((void**)&gg,    g_g);
    cudaGetSymbolAddress((void**)&A,     g_A);
    cudaGetSymbolAddress((void**)&ob,    g_out);
    cudaGetSymbolAddress((void**)&esrc,  g_esrc);
    cudaGetSymbolAddress((void**)&edst,  g_edst);
    cudaGetSymbolAddress((void**)&meanp, g_meanp);
    cudaGetSymbolAddress((void**)&xh,    g_xh);
    cudaGetSymbolAddress((void**)&wh,    g_wh);
    cudaGetSymbolAddress((void**)&ah,    g_ah);

    cudaFuncSetAttribute(attn_warp,
                         cudaFuncAttributeMaxDynamicSharedMemorySize, ATTN_SMEM);

    // K0: convert operands to fp16 (+ transpose weights to NxK)
    conv_half<<<(16 * 1024 * 768 / 2 + 255) / 256, 256>>>(x, xh, 16 * 1024 * 768 / 2);
    convT_half<<<dim3(24, 8, 4), 256>>>(Wfc, wh, 768, 256);
    convT_half<<<dim3(8, 8, 4), 256>>>(adjw, ah, 256, 256);

    // K1: pre = x @ Wfc + bfc  (fp16 MMA; B = Wfc^T NxK)
    hgemm<false, true, false><<<dim3(2, 128, 4), 256>>>(
        xh, wh, tmp, bfc, 256, 768,
        (size_t)0, (size_t)256 * 768, (size_t)16384 * 256, (size_t)256);
    // K2: LN + e_src/e_dst (+ fp16 h copy)
    ln_esrc_kernel<<<8192, 256>>>(tmp, h, htf, lng, lnb, Watt, esrc, edst);
    // K3: g = h @ adjw  (fp16 MMA; B = adjw^T NxK; fp16 output)
    hgemm<false, false, true><<<dim3(2, 128, 4), 256>>>(
        htf, ah, gg, nullptr, 256, 256,
        (size_t)16384 * 256, (size_t)256 * 256, (size_t)16384 * 256, (size_t)0);
    // K4: A = sigmoid(g @ h^T) per (head,batch), fp16 in/out
    hgemm<true, false, true><<<dim3(8, 8, 64), 256>>>(
        gg, htf, A, nullptr, 1024, 256,
        (size_t)1024 * 256, (size_t)1024 * 256, (size_t)1024 * 1024, (size_t)0);
    // K5: warp-per-row quantile + masked softmax + sparse alpha@h
    attn_warp<<<dim3(128, 16, 4), 256, ATTN_SMEM>>>(A, h, esrc, edst, batt, ob);
    // K6: partial mean over L
    mean_kernel<<<dim3(64, 8), 256>>>(ob, meanp);
    // K7: final projections + LN
    final_kernel<<<dim3(16, 3), 256>>>(meanp, Wl, bl, Ws, bs, Wc, bc,
                                       gl, betal, gs, betas, gc, betac, outp);
}

// round 13
// speedup vs baseline: 4.2658x; 1.1052x over previous
#include <cuda_runtime.h>
#include <cuda_fp16.h>
#include <cstdint>
#include <cstddef>

// ---------------- static scratch ----------------
__device__ float  g_h[4 * 16384 * 256];
__device__ __half g_htf[4 * 16384 * 256];
__device__ float  g_tmp[4 * 16384 * 256];
__device__ __half g_g[4 * 16384 * 256];
__device__ __half g_A[4 * 16 * 1024 * 1024];
__device__ float  g_out[4 * 16384 * 256];
__device__ float  g_esrc[4 * 16384];
__device__ float  g_edst[4 * 16384];
__device__ float  g_meanp[64 * 8 * 256];
__device__ __half g_xh[16 * 1024 * 768];
__device__ __half g_wh[4 * 256 * 768];    // Wfc^T per head: N x K
__device__ __half g_ah[4 * 256 * 256];    // adjw^T per head: N x K

__device__ __forceinline__ void mma_f16(float c[4], const uint32_t a[4], const uint32_t b[2]) {
    asm volatile(
        "mma.sync.aligned.m16n8k16.row.col.f32.f16.f16.f32 "
        "{%0,%1,%2,%3}, {%4,%5,%6,%7}, {%8,%9}, {%0,%1,%2,%3};"
        : "+f"(c[0]), "+f"(c[1]), "+f"(c[2]), "+f"(c[3])
        : "r"(a[0]), "r"(a[1]), "r"(a[2]), "r"(a[3]), "r"(b[0]), "r"(b[1]));
}

// ---------------- fp32 -> fp16 elementwise (pairs) ----------------
__global__ void __launch_bounds__(256)
conv_half(const float* __restrict__ src, __half* __restrict__ dst, int n2)
{
    int i = blockIdx.x * blockDim.x + threadIdx.x;
    if (i < n2) {
        float2 v = ((const float2*)src)[i];
        ((half2*)dst)[i] = __floats2half2_rn(v.x, v.y);
    }
}

// ---------------- fp32 KxN -> fp16 NxK transpose (per z) ----------------
__global__ void __launch_bounds__(256)
convT_half(const float* __restrict__ src, __half* __restrict__ dst, int K, int N)
{
    __shared__ float tile[32][33];
    const int k0 = blockIdx.x * 32, n0 = blockIdx.y * 32, z = blockIdx.z;
    src += (size_t)z * K * N;
    dst += (size_t)z * K * N;
    const int tx = threadIdx.x & 31, ty = threadIdx.x >> 5;   // 32 x 8
#pragma unroll
    for (int i = ty; i < 32; i += 8)
        tile[i][tx] = src[(size_t)(k0 + i) * N + n0 + tx];
    __syncthreads();
#pragma unroll
    for (int i = ty; i < 32; i += 8)
        dst[(size_t)(n0 + i) * K + k0 + tx] = __float2half(tile[tx][i]);
}

// =====================================================================
// fp16 tensor-core GEMM (m16n8k16), C = A @ B^T, A: MxK, B: NxK fp16
// row-major. 128x128 tiles, K-chunk 32, double-buffered, fragment-major
// smem: A frag = 1 LDS.128, B frag = 1 LDS.64. One sync per 32-K.
// =====================================================================
template<bool SIG, bool HASBIAS, bool HOUT>
__global__ void __launch_bounds__(256, 2)
hgemm(const __half* __restrict__ Ab, const __half* __restrict__ Bb,
      void* __restrict__ Cb, const float* __restrict__ biasb,
      int N, int K, size_t sA, size_t sB, size_t sC, size_t sBias)
{
    const __half* A = Ab + (size_t)blockIdx.z * sA;
    const __half* B = Bb + (size_t)blockIdx.z * sB;
    float* Cf = HOUT ? nullptr : (float*)Cb + (size_t)blockIdx.z * sC;
    __half* Ch = HOUT ? (__half*)Cb + (size_t)blockIdx.z * sC : nullptr;
    const float* bias = HASBIAS ? biasb + (size_t)blockIdx.z * sBias : nullptr;

    __shared__ uint32_t As[2][16 * 132];   // blocks (kc*8+mi); word = lane*4+ks*2+hb
    __shared__ uint32_t Bs[2][32 * 66];    // blocks (kc*16+nb); word = lane*2+ks

    const int tid = threadIdx.x;
    const int row0 = blockIdx.y * 128;
    const int col0 = blockIdx.x * 128;

    const int wid = tid >> 5, lane = tid & 31;
    const int wm = (wid >> 2) * 64;
    const int wn = (wid & 3) * 32;
    const int wmi0 = wm >> 4;               // 0 or 4
    const int wnb0 = wn >> 3;               // 0,4,8,12
    const int g4 = lane >> 2, t4 = lane & 3;

    // staging: warp w5 supplies lane-group g4=w5; rloc spans (mi,hb)/nb; ksS k-half
    const int w5 = tid >> 5;
    const int rloc = (tid & 31) >> 1;       // 0..15
    const int ksS = tid & 1;
    const int kq = ksS * 8;
    const int rA  = rloc * 8 + w5;          // tile-local row/col, bijective
    const int miS = rloc >> 1, hbS = rloc & 1;
    const int nbS = rloc;

    const __half* Abase = A + (size_t)(row0 + rA) * K + kq;
    const __half* Bbase = B + (size_t)(col0 + rA) * K + kq;

    float acc[4][4][4];
#pragma unroll
    for (int mi = 0; mi < 4; mi++)
#pragma unroll
        for (int nj = 0; nj < 4; nj++)
#pragma unroll
            for (int q = 0; q < 4; q++) acc[mi][nj][q] = 0.f;

    uint32_t a_pre[8], b_pre[8];

    auto loadStage = [&](int s) {
        *(uint4*)(a_pre)     = *(const uint4*)(Abase + s * 32);
        *(uint4*)(a_pre + 4) = *(const uint4*)(Abase + s * 32 + 16);
        *(uint4*)(b_pre)     = *(const uint4*)(Bbase + s * 32);
        *(uint4*)(b_pre + 4) = *(const uint4*)(Bbase + s * 32 + 16);
    };
    auto storeStage = [&](int bf) {
#pragma unroll
        for (int kc = 0; kc < 2; kc++) {
            uint32_t* da = &As[bf][(kc * 8 + miS) * 132 + w5 * 16 + ksS * 2 + hbS];
#pragma unroll
            for (int j = 0; j < 4; j++) da[j * 4] = a_pre[kc * 4 + j];
            uint32_t* db = &Bs[bf][(kc * 16 + nbS) * 66 + w5 * 8 + ksS];
#pragma unroll
            for (int j = 0; j < 4; j++) db[j * 2] = b_pre[kc * 4 + j];
        }
    };

    const int nS = K >> 5;
    loadStage(0);
    storeStage(0);
    __syncthreads();

    int buf = 0;
    for (int s = 0; s < nS; s++) {
        if (s + 1 < nS) loadStage(s + 1);
#pragma unroll
        for (int kc = 0; kc < 2; kc++) {
            uint32_t afr[4][4];
#pragma unroll
            for (int mi = 0; mi < 4; mi++) {
                uint4 v = *(const uint4*)&As[buf][(kc * 8 + wmi0 + mi) * 132 + lane * 4];
                afr[mi][0] = v.x; afr[mi][1] = v.y; afr[mi][2] = v.z; afr[mi][3] = v.w;
            }
            uint32_t bfr[4][2];
#pragma unroll
            for (int nj = 0; nj < 4; nj++) {
                uint2 v = *(const uint2*)&Bs[buf][(kc * 16 + wnb0 + nj) * 66 + lane * 2];
                bfr[nj][0] = v.x; bfr[nj][1] = v.y;
            }
#pragma unroll
            for (int mi = 0; mi < 4; mi++)
#pragma unroll
                for (int nj = 0; nj < 4; nj++)
                    mma_f16(acc[mi][nj], afr[mi], bfr[nj]);
        }
        if (s + 1 < nS) {
            storeStage(buf ^ 1);
            __syncthreads();
            buf ^= 1;
        }
    }

    // ---- epilogue ----
#pragma unroll
    for (int mi = 0; mi < 4; mi++) {
#pragma unroll
        for (int nj = 0; nj < 4; nj++) {
            int rr = row0 + wm + mi * 16 + g4;
            int cn = col0 + wn + nj * 8 + 2 * t4;
            float v0 = acc[mi][nj][0], v1 = acc[mi][nj][1];
            float v2 = acc[mi][nj][2], v3 = acc[mi][nj][3];
            if (HASBIAS) {
                float b0 = bias[cn], b1 = bias[cn + 1];
                v0 += b0; v1 += b1; v2 += b0; v3 += b1;
            }
            if (SIG) {
                v0 = 1.f / (1.f + expf(-v0)); v1 = 1.f / (1.f + expf(-v1));
                v2 = 1.f / (1.f + expf(-v2)); v3 = 1.f / (1.f + expf(-v3));
            }
            if (HOUT) {
                *(half2*)(Ch + (size_t)rr * N + cn)       = __floats2half2_rn(v0, v1);
                *(half2*)(Ch + (size_t)(rr + 8) * N + cn) = __floats2half2_rn(v2, v3);
            } else {
                *(float2*)(Cf + (size_t)rr * N + cn)       = make_float2(v0, v1);
                *(float2*)(Cf + (size_t)(rr + 8) * N + cn) = make_float2(v2, v3);
            }
        }
    }
}

// ---------------- LN over H=256 per row, fused e_src/e_dst GEMVs ----------------
__global__ void __launch_bounds__(256)
ln_esrc_kernel(const float* __restrict__ pre, float* __restrict__ h,
               __half* __restrict__ htf,
               const float* __restrict__ lng, const float* __restrict__ lnb,
               const float* __restrict__ Watt,
               float* __restrict__ esrc, float* __restrict__ edst)
{
    int w = (blockIdx.x * blockDim.x + threadIdx.x) >> 5;
    int lane = threadIdx.x & 31;
    int hd = w >> 14;
    const float* row = pre + (size_t)w * 256;

    float x[8];
    float s = 0.f;
#pragma unroll
    for (int i = 0; i < 8; i++) { x[i] = row[lane + 32 * i]; s += x[i]; }
#pragma unroll
    for (int off = 16; off > 0; off >>= 1) s += __shfl_xor_sync(0xffffffffu, s, off);
    float mu = s * (1.f / 256.f);

    float v = 0.f;
#pragma unroll
    for (int i = 0; i < 8; i++) { float d = x[i] - mu; v += d * d; }
#pragma unroll
    for (int off = 16; off > 0; off >>= 1) v += __shfl_xor_sync(0xffffffffu, v, off);
    float rstd = rsqrtf(v * (1.f / 256.f) + 1e-5f);

    float es = 0.f, ed = 0.f;
    float* hrow = h + (size_t)w * 256;
    __half* trow = htf + (size_t)w * 256;
#pragma unroll
    for (int i = 0; i < 8; i++) {
        int c = lane + 32 * i;
        float y = (x[i] - mu) * rstd * lng[hd * 256 + c] + lnb[hd * 256 + c];
        hrow[c] = y;
        trow[c] = __float2half(y);
        es += y * Watt[hd * 512 + c];
        ed += y * Watt[hd * 512 + 256 + c];
    }
#pragma unroll
    for (int off = 16; off > 0; off >>= 1) {
        es += __shfl_xor_sync(0xffffffffu, es, off);
        ed += __shfl_xor_sync(0xffffffffu, ed, off);
    }
    if (lane == 0) { esrc[w] = es; edst[w] = ed; }
}

// =====================================================================
// Warp-per-row attention on fp16 A with SATURATION FAST-PATH:
// if ranks 716 & 717 both land in the fp16 1.0-plateau (common case:
// sigmoid saturates), delta = 1.0 exactly -> skip radix select.
// Fallback: 2-pass radix select (exact).
// =====================================================================
#define ATTN_SMEM 57344
__global__ void __launch_bounds__(256)
attn_warp(const __half* __restrict__ Aprob, const float* __restrict__ h,
          const float* __restrict__ esrc, const float* __restrict__ edst,
          const float* __restrict__ batt, float* __restrict__ out)
{
    extern __shared__ char smemraw[];
    const int tid = threadIdx.x;
    const int w = tid >> 5, lane = tid & 31;
    const int hd = blockIdx.z, b = blockIdx.y;
    const int i_row = blockIdx.x * 8 + w;
    const int rowidx = hd * 16384 + b * 1024;

    unsigned int* hist = (unsigned int*)smemraw + w * 256;
    unsigned short* lst = (unsigned short*)(smemraw + 8192) + w * 1024;
    float* sE = (float*)(smemraw + 24576) + w * 1024;

    const uint32_t* rowp = (const uint32_t*)(Aprob + ((size_t)rowidx + i_row) * 1024);
    uint32_t av[16];
#pragma unroll
    for (int q = 0; q < 16; q++) av[q] = rowp[q * 32 + lane];

    // ---- fast-path probe: counts around 1.0 (0x3C00) ----
    const unsigned int ONE = 0x3C00u;
    int cLT1 = 0, cLE1 = 0;
#pragma unroll
    for (int q = 0; q < 16; q++) {
        unsigned int k0 = av[q] & 0xFFFFu;
        unsigned int k1 = av[q] >> 16;
        cLT1 += (k0 < ONE) + (k1 < ONE);
        cLE1 += (k0 <= ONE) + (k1 <= ONE);
    }
#pragma unroll
    for (int off = 16; off > 0; off >>= 1) {
        cLT1 += __shfl_xor_sync(0xffffffffu, cLT1, off);
        cLE1 += __shfl_xor_sync(0xffffffffu, cLE1, off);
    }

    float v716, v717;
    if (cLT1 <= 716 && cLE1 >= 718) {
        // ranks 716 and 717 are both exactly 1.0
        v716 = 1.0f; v717 = 1.0f;
    } else {
        // ---- 2-pass radix select: rank 716 (u16 keys, A>=0 monotonic) ----
        unsigned int prefval = 0u, maskhi = 0u;
        int rank = 716;
#pragma unroll
        for (int shift = 8; shift >= 0; shift -= 8) {
#pragma unroll
            for (int t = 0; t < 8; t++) hist[lane * 8 + t] = 0u;
            __syncwarp();
#pragma unroll
            for (int q = 0; q < 16; q++) {
                unsigned int k0 = av[q] & 0xFFFFu;
                unsigned int k1 = av[q] >> 16;
                if ((k0 & maskhi) == prefval) atomicAdd(&hist[(k0 >> shift) & 255u], 1u);
                if ((k1 & maskhi) == prefval) atomicAdd(&hist[(k1 >> shift) & 255u], 1u);
            }
            __syncwarp();
            unsigned int h8[8]; unsigned int tot = 0u;
#pragma unroll
            for (int t = 0; t < 8; t++) { h8[t] = hist[lane * 8 + t]; tot += h8[t]; }
            unsigned int incl = tot;
#pragma unroll
            for (int off = 1; off < 32; off <<= 1) {
                unsigned int v = __shfl_up_sync(0xffffffffu, incl, off);
                if (lane >= off) incl += v;
            }
            unsigned int base = incl - tot;
            int bin = -1, nr = 0;
            unsigned int run = base;
#pragma unroll
            for (int t = 0; t < 8; t++) {
                unsigned int c = run + h8[t];
                if (bin < 0 && (unsigned int)rank >= run && (unsigned int)rank < c) {
                    bin = lane * 8 + t; nr = rank - (int)run;
                }
                run = c;
            }
            unsigned int mball = __ballot_sync(0xffffffffu, bin >= 0);
            int src = __ffs(mball) - 1;
            bin = __shfl_sync(0xffffffffu, bin, src);
            nr  = __shfl_sync(0xffffffffu, nr, src);
            prefval |= ((unsigned int)bin) << shift;
            maskhi  |= 0xFFu << shift;
            rank = nr;
        }
        v716 = __half2float(__ushort_as_half((unsigned short)prefval));

        // ---- rank 717: count <= key716 and min-above ----
        int cLE = 0; unsigned int mA = 0xFFFFFFFFu;
#pragma unroll
        for (int q = 0; q < 16; q++) {
            unsigned int k0 = av[q] & 0xFFFFu;
            unsigned int k1 = av[q] >> 16;
            if (k0 <= prefval) cLE++; else mA = (k0 < mA) ? k0 : mA;
            if (k1 <= prefval) cLE++; else mA = (k1 < mA) ? k1 : mA;
        }
#pragma unroll
        for (int off = 16; off > 0; off >>= 1) {
            cLE += __shfl_xor_sync(0xffffffffu, cLE, off);
            unsigned int o = __shfl_xor_sync(0xffffffffu, mA, off);
            mA = (o < mA) ? o : mA;
        }
        v717 = (cLE > 717) ? v716
             : __half2float(__ushort_as_half((unsigned short)mA));
    }

    const float fr = 0.7f * 1023.0f - 716.0f;
    const float delta = v716 + fr * (v717 - v716);

    // ---- mask compaction: count, scan, then write ----
    int cnt = 0;
#pragma unroll
    for (int q = 0; q < 16; q++) {
        float a0 = __half2float(__ushort_as_half((unsigned short)(av[q] & 0xFFFFu)));
        float a1 = __half2float(__ushort_as_half((unsigned short)(av[q] >> 16)));
        int j0 = (q * 32 + lane) * 2, j1 = j0 + 1;
        if (a0 > delta || j0 == i_row) cnt++;
        if (a1 > delta || j1 == i_row) cnt++;
    }
    int incl = cnt;
#pragma unroll
    for (int off = 1; off < 32; off <<= 1) {
        int v = __shfl_up_sync(0xffffffffu, incl, off);
        if (lane >= off) incl += v;
    }
    int pos = incl - cnt;
    int total = __shfl_sync(0xffffffffu, incl, 31);
#pragma unroll
    for (int q = 0; q < 16; q++) {
        float a0 = __half2float(__ushort_as_half((unsigned short)(av[q] & 0xFFFFu)));
        float a1 = __half2float(__ushort_as_half((unsigned short)(av[q] >> 16)));
        int j0 = (q * 32 + lane) * 2, j1 = j0 + 1;
        if (a0 > delta || j0 == i_row) lst[pos++] = (unsigned short)j0;
        if (a1 > delta || j1 == i_row) lst[pos++] = (unsigned short)j1;
    }
    __syncwarp();

    // ---- masked leaky-relu softmax ----
    const float eb = esrc[rowidx + i_row] + batt[hd];
    float lmax = -3.4e38f;
    for (int p = lane; p < total; p += 32) {
        int j = lst[p];
        float e = eb + edst[rowidx + j];
        e = (e >= 0.f) ? e : 0.01f * e;
        sE[p] = e;
        lmax = fmaxf(lmax, e);
    }
#pragma unroll
    for (int off = 16; off > 0; off >>= 1)
        lmax = fmaxf(lmax, __shfl_xor_sync(0xffffffffu, lmax, off));
    __syncwarp();
    float lsum = 0.f;
    for (int p = lane; p < total; p += 32) {
        float a = expf(sE[p] - lmax);
        sE[p] = a;
        lsum += a;
    }
#pragma unroll
    for (int off = 16; off > 0; off >>= 1)
        lsum += __shfl_xor_sync(0xffffffffu, lsum, off);
    const float inv = 1.f / lsum;
    __syncwarp();

    // ---- out[i_row][c] = inv * sum_p alpha_p * h[j_p][c] ----
    float a0 = 0.f, a1 = 0.f, a2 = 0.f, a3 = 0.f;
    float a4 = 0.f, a5 = 0.f, a6 = 0.f, a7 = 0.f;
    const float* hb = h + (size_t)rowidx * 256;
    for (int p = 0; p < total; p++) {
        int j = lst[p];
        float wgt = sE[p];
        const float4* hr = (const float4*)(hb + (size_t)j * 256 + lane * 8);
        float4 x0 = hr[0], x1 = hr[1];
        a0 += wgt * x0.x; a1 += wgt * x0.y; a2 += wgt * x0.z; a3 += wgt * x0.w;
        a4 += wgt * x1.x; a5 += wgt * x1.y; a6 += wgt * x1.z; a7 += wgt * x1.w;
    }
    float* op = out + ((size_t)rowidx + i_row) * 256 + lane * 8;
    *(float4*)(op)     = make_float4(a0 * inv, a1 * inv, a2 * inv, a3 * inv);
    *(float4*)(op + 4) = make_float4(a4 * inv, a5 * inv, a6 * inv, a7 * inv);
}

// ---------------- partial mean over L per (head,batch): 8 chunks of 128 ----------------
__global__ void __launch_bounds__(256)
mean_kernel(const float* __restrict__ o, float* __restrict__ meanp)
{
    int z = blockIdx.x;
    int ch = blockIdx.y;
    int c = threadIdx.x;
    const float* p = o + (size_t)z * 262144 + (size_t)ch * 128 * 256 + c;
    float s = 0.f;
    for (int l = 0; l < 128; l++) s += p[(size_t)l * 256];
    meanp[(z * 8 + ch) * 256 + c] = s;
}

// ---------------- final projections + LN ----------------
__global__ void __launch_bounds__(256)
final_kernel(const float* __restrict__ meanp,
             const float* __restrict__ Wl, const float* __restrict__ bl,
             const float* __restrict__ Ws, const float* __restrict__ bs,
             const float* __restrict__ Wc, const float* __restrict__ bc,
             const float* __restrict__ gl, const float* __restrict__ betal,
             const float* __restrict__ gs, const float* __restrict__ betas,
             const float* __restrict__ gc, const float* __restrict__ betac,
             float* __restrict__ outp)
{
    const int b = blockIdx.x, type = blockIdx.y, tid = threadIdx.x;
    __shared__ float v[1024];
    __shared__ float red[256];

    const float *W, *bias, *g, *beta;
    int K, hbase;
    if (type == 0)      { W = Wl; bias = bl; g = gl; beta = betal; K = 512;  hbase = 0; }
    else if (type == 1) { W = Ws; bias = bs; g = gs; beta = betas; K = 512;  hbase = 2; }
    else                { W = Wc; bias = bc; g = gc; beta = betac; K = 1024; hbase = 0; }

    for (int k = tid; k < K; k += 256) {
        int head = hbase + (k >> 8);
        int c = k & 255;
        float s = 0.f;
#pragma unroll
        for (int c8 = 0; c8 < 8; c8++)
            s += meanp[((head * 16 + b) * 8 + c8) * 256 + c];
        v[k] = s * (1.f / 1024.f);
    }
    __syncthreads();

    float acc[3];
#pragma unroll
    for (int q = 0; q < 3; q++) {
        int c = tid + q * 256;
        float s = bias[c];
        for (int k = 0; k < K; k++) s += v[k] * W[(size_t)k * 768 + c];
        acc[q] = s;
    }

    red[tid] = acc[0] + acc[1] + acc[2];
    __syncthreads();
    for (int off = 128; off > 0; off >>= 1) {
        if (tid < off) red[tid] += red[tid + off];
        __syncthreads();
    }
    float mu = red[0] * (1.f / 768.f);
    __syncthreads();
    float d0 = acc[0] - mu, d1 = acc[1] - mu, d2 = acc[2] - mu;
    red[tid] = d0 * d0 + d1 * d1 + d2 * d2;
    __syncthreads();
    for (int off = 128; off > 0; off >>= 1) {
        if (tid < off) red[tid] += red[tid + off];
        __syncthreads();
    }
    float rstd = rsqrtf(red[0] * (1.f / 768.f) + 1e-5f);
    __syncthreads();

#pragma unroll
    for (int q = 0; q < 3; q++) {
        int c = tid + q * 256;
        outp[(size_t)type * 16 * 768 + (size_t)b * 768 + c] =
            (acc[q] - mu) * rstd * g[c] + beta[c];
    }
}

// ---------------- launch ----------------
extern "C" void kernel_launch(void* const* d_in, const int* in_sizes, int n_in,
                              void* d_out, int out_size)
{
    const float* x      = (const float*)d_in[0];
    const float* Wfc    = (const float*)d_in[1];
    const float* bfc    = (const float*)d_in[2];
    const float* lng    = (const float*)d_in[3];
    const float* lnb    = (const float*)d_in[4];
    const float* adjw   = (const float*)d_in[5];
    const float* Watt   = (const float*)d_in[6];
    const float* batt   = (const float*)d_in[7];
    const float* Wl     = (const float*)d_in[8];
    const float* bl     = (const float*)d_in[9];
    const float* Ws     = (const float*)d_in[10];
    const float* bs     = (const float*)d_in[11];
    const float* Wc     = (const float*)d_in[12];
    const float* bc     = (const float*)d_in[13];
    const float* gl     = (const float*)d_in[14];
    const float* betal  = (const float*)d_in[15];
    const float* gs     = (const float*)d_in[16];
    const float* betas  = (const float*)d_in[17];
    const float* gc     = (const float*)d_in[18];
    const float* betac  = (const float*)d_in[19];
    float* outp = (float*)d_out;

    float *h, *tmp, *ob, *esrc, *edst, *meanp;
    __half *htf, *gg, *A, *xh, *wh, *ah;
    cudaGetSymbolAddress((void**)&h,     g_h);
    cudaGetSymbolAddress((void**)&htf,   g_htf);
    cudaGetSymbolAddress((void**)&tmp,   g_tmp);
    cudaGetSymbolAddress((void**)&gg,    g_g);
    cudaGetSymbolAddress((void**)&A,     g_A);
    cudaGetSymbolAddress((void**)&ob,    g_out);
    cudaGetSymbolAddress((void**)&esrc,  g_esrc);
    cudaGetSymbolAddress((void**)&edst,  g_edst);
    cudaGetSymbolAddress((void**)&meanp, g_meanp);
    cudaGetSymbolAddress((void**)&xh,    g_xh);
    cudaGetSymbolAddress((void**)&wh,    g_wh);
    cudaGetSymbolAddress((void**)&ah,    g_ah);

    cudaFuncSetAttribute(attn_warp,
                         cudaFuncAttributeMaxDynamicSharedMemorySize, ATTN_SMEM);

    // K0: convert operands to fp16 (+ transpose weights to NxK)
    conv_half<<<(16 * 1024 * 768 / 2 + 255) / 256, 256>>>(x, xh, 16 * 1024 * 768 / 2);
    convT_half<<<dim3(24, 8, 4), 256>>>(Wfc, wh, 768, 256);
    convT_half<<<dim3(8, 8, 4), 256>>>(adjw, ah, 256, 256);

    // K1: pre = x @ Wfc + bfc  (fp16 MMA; B = Wfc^T NxK)
    hgemm<false, true, false><<<dim3(2, 128, 4), 256>>>(
        xh, wh, tmp, bfc, 256, 768,
        (size_t)0, (size_t)256 * 768, (size_t)16384 * 256, (size_t)256);
    // K2: LN + e_src/e_dst (+ fp16 h copy)
    ln_esrc_kernel<<<8192, 256>>>(tmp, h, htf, lng, lnb, Watt, esrc, edst);
    // K3: g = h @ adjw  (fp16 MMA; B = adjw^T NxK; fp16 output)
    hgemm<false, false, true><<<dim3(2, 128, 4), 256>>>(
        htf, ah, gg, nullptr, 256, 256,
        (size_t)16384 * 256, (size_t)256 * 256, (size_t)16384 * 256, (size_t)0);
    // K4: A = sigmoid(g @ h^T) per (head,batch), fp16 in/out
    hgemm<true, false, true><<<dim3(8, 8, 64), 256>>>(
        gg, htf, A, nullptr, 1024, 256,
        (size_t)1024 * 256, (size_t)1024 * 256, (size_t)1024 * 1024, (size_t)0);
    // K5: warp-per-row quantile (fast-path) + masked softmax + sparse alpha@h
    attn_warp<<<dim3(128, 16, 4), 256, ATTN_SMEM>>>(A, h, esrc, edst, batt, ob);
    // K6: partial mean over L
    mean_kernel<<<dim3(64, 8), 256>>>(ob, meanp);
    // K7: final projections + LN
    final_kernel<<<dim3(16, 3), 256>>>(meanp, Wl, bl, Ws, bs, Wc, bc,
                                       gl, betal, gs, betas, gc, betac, outp);
}

// round 16
// speedup vs baseline: 4.8529x; 1.1376x over previous
#include <cuda_runtime.h>
#include <cuda_fp16.h>
#include <cstdint>
#include <cstddef>

// ---------------- static scratch ----------------
__device__ float  g_h[4 * 16384 * 256];
__device__ __half g_htf[4 * 16384 * 256];
__device__ float  g_tmp[4 * 16384 * 256];
__device__ __half g_g[4 * 16384 * 256];
__device__ __half g_A[4 * 16 * 1024 * 1024];
__device__ __half g_out[4 * 16384 * 256];
__device__ float  g_esrc[4 * 16384];
__device__ float  g_edst[4 * 16384];
__device__ float  g_meanp[64 * 8 * 256];
__device__ __half g_xh[16 * 1024 * 768];
__device__ __half g_wh[4 * 256 * 768];    // Wfc^T per head: N x K
__device__ __half g_ah[4 * 256 * 256];    // adjw^T per head: N x K

__device__ __forceinline__ void mma_f16(float c[4], const uint32_t a[4], const uint32_t b[2]) {
    asm volatile(
        "mma.sync.aligned.m16n8k16.row.col.f32.f16.f16.f32 "
        "{%0,%1,%2,%3}, {%4,%5,%6,%7}, {%8,%9}, {%0,%1,%2,%3};"
        : "+f"(c[0]), "+f"(c[1]), "+f"(c[2]), "+f"(c[3])
        : "r"(a[0]), "r"(a[1]), "r"(a[2]), "r"(a[3]), "r"(b[0]), "r"(b[1]));
}

__device__ __forceinline__ float fast_sigmoid(float v) {
    return __fdividef(1.f, 1.f + __expf(-v));
}

// ---------------- fp32 -> fp16 elementwise (pairs) ----------------
__global__ void __launch_bounds__(256)
conv_half(const float* __restrict__ src, __half* __restrict__ dst, int n2)
{
    int i = blockIdx.x * blockDim.x + threadIdx.x;
    if (i < n2) {
        float2 v = ((const float2*)src)[i];
        ((half2*)dst)[i] = __floats2half2_rn(v.x, v.y);
    }
}

// ---------------- fp32 KxN -> fp16 NxK transpose (per z) ----------------
__global__ void __launch_bounds__(256)
convT_half(const float* __restrict__ src, __half* __restrict__ dst, int K, int N)
{
    __shared__ float tile[32][33];
    const int k0 = blockIdx.x * 32, n0 = blockIdx.y * 32, z = blockIdx.z;
    src += (size_t)z * K * N;
    dst += (size_t)z * K * N;
    const int tx = threadIdx.x & 31, ty = threadIdx.x >> 5;   // 32 x 8
#pragma unroll
    for (int i = ty; i < 32; i += 8)
        tile[i][tx] = src[(size_t)(k0 + i) * N + n0 + tx];
    __syncthreads();
#pragma unroll
    for (int i = ty; i < 32; i += 8)
        dst[(size_t)(n0 + i) * K + k0 + tx] = __float2half(tile[tx][i]);
}

// =====================================================================
// fp16 tensor-core GEMM (m16n8k16), C = A @ B^T, A: MxK, B: NxK fp16
// row-major. 128x128 tiles, K-chunk 32, double-buffered, fragment-major
// smem: A frag = 1 LDS.128, B frag = 1 LDS.64. One sync per 32-K.
// =====================================================================
template<bool SIG, bool HASBIAS, bool HOUT>
__global__ void __launch_bounds__(256, 2)
hgemm(const __half* __restrict__ Ab, const __half* __restrict__ Bb,
      void* __restrict__ Cb, const float* __restrict__ biasb,
      int N, int K, size_t sA, size_t sB, size_t sC, size_t sBias)
{
    const __half* A = Ab + (size_t)blockIdx.z * sA;
    const __half* B = Bb + (size_t)blockIdx.z * sB;
    float* Cf = HOUT ? nullptr : (float*)Cb + (size_t)blockIdx.z * sC;
    __half* Ch = HOUT ? (__half*)Cb + (size_t)blockIdx.z * sC : nullptr;
    const float* bias = HASBIAS ? biasb + (size_t)blockIdx.z * sBias : nullptr;

    __shared__ uint32_t As[2][16 * 132];   // blocks (kc*8+mi); word = lane*4+ks*2+hb
    __shared__ uint32_t Bs[2][32 * 66];    // blocks (kc*16+nb); word = lane*2+ks

    const int tid = threadIdx.x;
    const int row0 = blockIdx.y * 128;
    const int col0 = blockIdx.x * 128;

    const int wid = tid >> 5, lane = tid & 31;
    const int wm = (wid >> 2) * 64;
    const int wn = (wid & 3) * 32;
    const int wmi0 = wm >> 4;               // 0 or 4
    const int wnb0 = wn >> 3;               // 0,4,8,12
    const int g4 = lane >> 2, t4 = lane & 3;

    const int w5 = tid >> 5;
    const int rloc = (tid & 31) >> 1;       // 0..15
    const int ksS = tid & 1;
    const int kq = ksS * 8;
    const int rA  = rloc * 8 + w5;          // tile-local row/col, bijective
    const int miS = rloc >> 1, hbS = rloc & 1;
    const int nbS = rloc;

    const __half* Abase = A + (size_t)(row0 + rA) * K + kq;
    const __half* Bbase = B + (size_t)(col0 + rA) * K + kq;

    float acc[4][4][4];
#pragma unroll
    for (int mi = 0; mi < 4; mi++)
#pragma unroll
        for (int nj = 0; nj < 4; nj++)
#pragma unroll
            for (int q = 0; q < 4; q++) acc[mi][nj][q] = 0.f;

    uint32_t a_pre[8], b_pre[8];

    auto loadStage = [&](int s) {
        *(uint4*)(a_pre)     = *(const uint4*)(Abase + s * 32);
        *(uint4*)(a_pre + 4) = *(const uint4*)(Abase + s * 32 + 16);
        *(uint4*)(b_pre)     = *(const uint4*)(Bbase + s * 32);
        *(uint4*)(b_pre + 4) = *(const uint4*)(Bbase + s * 32 + 16);
    };
    auto storeStage = [&](int bf) {
#pragma unroll
        for (int kc = 0; kc < 2; kc++) {
            uint32_t* da = &As[bf][(kc * 8 + miS) * 132 + w5 * 16 + ksS * 2 + hbS];
#pragma unroll
            for (int j = 0; j < 4; j++) da[j * 4] = a_pre[kc * 4 + j];
            uint32_t* db = &Bs[bf][(kc * 16 + nbS) * 66 + w5 * 8 + ksS];
#pragma unroll
            for (int j = 0; j < 4; j++) db[j * 2] = b_pre[kc * 4 + j];
        }
    };

    const int nS = K >> 5;
    loadStage(0);
    storeStage(0);
    __syncthreads();

    int buf = 0;
    for (int s = 0; s < nS; s++) {
        if (s + 1 < nS) loadStage(s + 1);
#pragma unroll
        for (int kc = 0; kc < 2; kc++) {
            uint32_t afr[4][4];
#pragma unroll
            for (int mi = 0; mi < 4; mi++) {
                uint4 v = *(const uint4*)&As[buf][(kc * 8 + wmi0 + mi) * 132 + lane * 4];
                afr[mi][0] = v.x; afr[mi][1] = v.y; afr[mi][2] = v.z; afr[mi][3] = v.w;
            }
            uint32_t bfr[4][2];
#pragma unroll
            for (int nj = 0; nj < 4; nj++) {
                uint2 v = *(const uint2*)&Bs[buf][(kc * 16 + wnb0 + nj) * 66 + lane * 2];
                bfr[nj][0] = v.x; bfr[nj][1] = v.y;
            }
#pragma unroll
            for (int mi = 0; mi < 4; mi++)
#pragma unroll
                for (int nj = 0; nj < 4; nj++)
                    mma_f16(acc[mi][nj], afr[mi], bfr[nj]);
        }
        if (s + 1 < nS) {
            storeStage(buf ^ 1);
            __syncthreads();
            buf ^= 1;
        }
    }

    // ---- epilogue ----
#pragma unroll
    for (int mi = 0; mi < 4; mi++) {
#pragma unroll
        for (int nj = 0; nj < 4; nj++) {
            int rr = row0 + wm + mi * 16 + g4;
            int cn = col0 + wn + nj * 8 + 2 * t4;
            float v0 = acc[mi][nj][0], v1 = acc[mi][nj][1];
            float v2 = acc[mi][nj][2], v3 = acc[mi][nj][3];
            if (HASBIAS) {
                float b0 = bias[cn], b1 = bias[cn + 1];
                v0 += b0; v1 += b1; v2 += b0; v3 += b1;
            }
            if (SIG) {
                v0 = fast_sigmoid(v0); v1 = fast_sigmoid(v1);
                v2 = fast_sigmoid(v2); v3 = fast_sigmoid(v3);
            }
            if (HOUT) {
                *(half2*)(Ch + (size_t)rr * N + cn)       = __floats2half2_rn(v0, v1);
                *(half2*)(Ch + (size_t)(rr + 8) * N + cn) = __floats2half2_rn(v2, v3);
            } else {
                *(float2*)(Cf + (size_t)rr * N + cn)       = make_float2(v0, v1);
                *(float2*)(Cf + (size_t)(rr + 8) * N + cn) = make_float2(v2, v3);
            }
        }
    }
}

// ---------------- LN over H=256 per row, fused e_src/e_dst GEMVs ----------------
__global__ void __launch_bounds__(256)
ln_esrc_kernel(const float* __restrict__ pre, float* __restrict__ h,
               __half* __restrict__ htf,
               const float* __restrict__ lng, const float* __restrict__ lnb,
               const float* __restrict__ Watt,
               float* __restrict__ esrc, float* __restrict__ edst)
{
    int w = (blockIdx.x * blockDim.x + threadIdx.x) >> 5;
    int lane = threadIdx.x & 31;
    int hd = w >> 14;
    const float* row = pre + (size_t)w * 256;

    float x[8];
    float s = 0.f;
#pragma unroll
    for (int i = 0; i < 8; i++) { x[i] = row[lane + 32 * i]; s += x[i]; }
#pragma unroll
    for (int off = 16; off > 0; off >>= 1) s += __shfl_xor_sync(0xffffffffu, s, off);
    float mu = s * (1.f / 256.f);

    float v = 0.f;
#pragma unroll
    for (int i = 0; i < 8; i++) { float d = x[i] - mu; v += d * d; }
#pragma unroll
    for (int off = 16; off > 0; off >>= 1) v += __shfl_xor_sync(0xffffffffu, v, off);
    float rstd = rsqrtf(v * (1.f / 256.f) + 1e-5f);

    float es = 0.f, ed = 0.f;
    float* hrow = h + (size_t)w * 256;
    __half* trow = htf + (size_t)w * 256;
#pragma unroll
    for (int i = 0; i < 8; i++) {
        int c = lane + 32 * i;
        float y = (x[i] - mu) * rstd * lng[hd * 256 + c] + lnb[hd * 256 + c];
        hrow[c] = y;
        trow[c] = __float2half(y);
        es += y * Watt[hd * 512 + c];
        ed += y * Watt[hd * 512 + 256 + c];
    }
#pragma unroll
    for (int off = 16; off > 0; off >>= 1) {
        es += __shfl_xor_sync(0xffffffffu, es, off);
        ed += __shfl_xor_sync(0xffffffffu, ed, off);
    }
    if (lane == 0) { esrc[w] = es; edst[w] = ed; }
}

// =====================================================================
// Warp-per-row attention on fp16 A with saturation fast-path.
// =====================================================================
#define ATTN_SMEM 57344
__global__ void __launch_bounds__(256)
attn_warp(const __half* __restrict__ Aprob, const float* __restrict__ h,
          const float* __restrict__ esrc, const float* __restrict__ edst,
          const float* __restrict__ batt, __half* __restrict__ out)
{
    extern __shared__ char smemraw[];
    const int tid = threadIdx.x;
    const int w = tid >> 5, lane = tid & 31;
    const int hd = blockIdx.z, b = blockIdx.y;
    const int i_row = blockIdx.x * 8 + w;
    const int rowidx = hd * 16384 + b * 1024;

    unsigned int* hist = (unsigned int*)smemraw + w * 256;
    unsigned short* lst = (unsigned short*)(smemraw + 8192) + w * 1024;
    float* sE = (float*)(smemraw + 24576) + w * 1024;

    const uint32_t* rowp = (const uint32_t*)(Aprob + ((size_t)rowidx + i_row) * 1024);
    uint32_t av[16];
#pragma unroll
    for (int q = 0; q < 16; q++) av[q] = rowp[q * 32 + lane];

    // ---- fast-path probe: counts around 1.0 (0x3C00) ----
    const unsigned int ONE = 0x3C00u;
    int cLT1 = 0, cLE1 = 0;
#pragma unroll
    for (int q = 0; q < 16; q++) {
        unsigned int k0 = av[q] & 0xFFFFu;
        unsigned int k1 = av[q] >> 16;
        cLT1 += (k0 < ONE) + (k1 < ONE);
        cLE1 += (k0 <= ONE) + (k1 <= ONE);
    }
#pragma unroll
    for (int off = 16; off > 0; off >>= 1) {
        cLT1 += __shfl_xor_sync(0xffffffffu, cLT1, off);
        cLE1 += __shfl_xor_sync(0xffffffffu, cLE1, off);
    }

    float v716, v717;
    if (cLT1 <= 716 && cLE1 >= 718) {
        v716 = 1.0f; v717 = 1.0f;
    } else {
        // ---- 2-pass radix select: rank 716 ----
        unsigned int prefval = 0u, maskhi = 0u;
        int rank = 716;
#pragma unroll
        for (int shift = 8; shift >= 0; shift -= 8) {
#pragma unroll
            for (int t = 0; t < 8; t++) hist[lane * 8 + t] = 0u;
            __syncwarp();
#pragma unroll
            for (int q = 0; q < 16; q++) {
                unsigned int k0 = av[q] & 0xFFFFu;
                unsigned int k1 = av[q] >> 16;
                if ((k0 & maskhi) == prefval) atomicAdd(&hist[(k0 >> shift) & 255u], 1u);
                if ((k1 & maskhi) == prefval) atomicAdd(&hist[(k1 >> shift) & 255u], 1u);
            }
            __syncwarp();
            unsigned int h8[8]; unsigned int tot = 0u;
#pragma unroll
            for (int t = 0; t < 8; t++) { h8[t] = hist[lane * 8 + t]; tot += h8[t]; }
            unsigned int incl = tot;
#pragma unroll
            for (int off = 1; off < 32; off <<= 1) {
                unsigned int v = __shfl_up_sync(0xffffffffu, incl, off);
                if (lane >= off) incl += v;
            }
            unsigned int base = incl - tot;
            int bin = -1, nr = 0;
            unsigned int run = base;
#pragma unroll
            for (int t = 0; t < 8; t++) {
                unsigned int c = run + h8[t];
                if (bin < 0 && (unsigned int)rank >= run && (unsigned int)rank < c) {
                    bin = lane * 8 + t; nr = rank - (int)run;
                }
                run = c;
            }
            unsigned int mball = __ballot_sync(0xffffffffu, bin >= 0);
            int src = __ffs(mball) - 1;
            bin = __shfl_sync(0xffffffffu, bin, src);
            nr  = __shfl_sync(0xffffffffu, nr, src);
            prefval |= ((unsigned int)bin) << shift;
            maskhi  |= 0xFFu << shift;
            rank = nr;
        }
        v716 = __half2float(__ushort_as_half((unsigned short)prefval));

        int cLE = 0; unsigned int mA = 0xFFFFFFFFu;
#pragma unroll
        for (int q = 0; q < 16; q++) {
            unsigned int k0 = av[q] & 0xFFFFu;
            unsigned int k1 = av[q] >> 16;
            if (k0 <= prefval) cLE++; else mA = (k0 < mA) ? k0 : mA;
            if (k1 <= prefval) cLE++; else mA = (k1 < mA) ? k1 : mA;
        }
#pragma unroll
        for (int off = 16; off > 0; off >>= 1) {
            cLE += __shfl_xor_sync(0xffffffffu, cLE, off);
            unsigned int o = __shfl_xor_sync(0xffffffffu, mA, off);
            mA = (o < mA) ? o : mA;
        }
        v717 = (cLE > 717) ? v716
             : __half2float(__ushort_as_half((unsigned short)mA));
    }

    const float fr = 0.7f * 1023.0f - 716.0f;
    const float delta = v716 + fr * (v717 - v716);

    // ---- mask compaction: count, scan, then write ----
    int cnt = 0;
#pragma unroll
    for (int q = 0; q < 16; q++) {
        float a0 = __half2float(__ushort_as_half((unsigned short)(av[q] & 0xFFFFu)));
        float a1 = __half2float(__ushort_as_half((unsigned short)(av[q] >> 16)));
        int j0 = (q * 32 + lane) * 2, j1 = j0 + 1;
        if (a0 > delta || j0 == i_row) cnt++;
        if (a1 > delta || j1 == i_row) cnt++;
    }
    int incl = cnt;
#pragma unroll
    for (int off = 1; off < 32; off <<= 1) {
        int v = __shfl_up_sync(0xffffffffu, incl, off);
        if (lane >= off) incl += v;
    }
    int pos = incl - cnt;
    int total = __shfl_sync(0xffffffffu, incl, 31);
#pragma unroll
    for (int q = 0; q < 16; q++) {
        float a0 = __half2float(__ushort_as_half((unsigned short)(av[q] & 0xFFFFu)));
        float a1 = __half2float(__ushort_as_half((unsigned short)(av[q] >> 16)));
        int j0 = (q * 32 + lane) * 2, j1 = j0 + 1;
        if (a0 > delta || j0 == i_row) lst[pos++] = (unsigned short)j0;
        if (a1 > delta || j1 == i_row) lst[pos++] = (unsigned short)j1;
    }
    __syncwarp();

    // ---- masked leaky-relu softmax ----
    const float eb = esrc[rowidx + i_row] + batt[hd];
    float lmax = -3.4e38f;
    for (int p = lane; p < total; p += 32) {
        int j = lst[p];
        float e = eb + edst[rowidx + j];
        e = (e >= 0.f) ? e : 0.01f * e;
        sE[p] = e;
        lmax = fmaxf(lmax, e);
    }
#pragma unroll
    for (int off = 16; off > 0; off >>= 1)
        lmax = fmaxf(lmax, __shfl_xor_sync(0xffffffffu, lmax, off));
    __syncwarp();
    float lsum = 0.f;
    for (int p = lane; p < total; p += 32) {
        float a = __expf(sE[p] - lmax);
        sE[p] = a;
        lsum += a;
    }
#pragma unroll
    for (int off = 16; off > 0; off >>= 1)
        lsum += __shfl_xor_sync(0xffffffffu, lsum, off);
    const float inv = 1.f / lsum;
    __syncwarp();

    // ---- out[i_row][c] = inv * sum_p alpha_p * h[j_p][c] ----
    float a0 = 0.f, a1 = 0.f, a2 = 0.f, a3 = 0.f;
    float a4 = 0.f, a5 = 0.f, a6 = 0.f, a7 = 0.f;
    const float* hb = h + (size_t)rowidx * 256;
    for (int p = 0; p < total; p++) {
        int j = lst[p];
        float wgt = sE[p];
        const float4* hr = (const float4*)(hb + (size_t)j * 256 + lane * 8);
        float4 x0 = hr[0], x1 = hr[1];
        a0 += wgt * x0.x; a1 += wgt * x0.y; a2 += wgt * x0.z; a3 += wgt * x0.w;
        a4 += wgt * x1.x; a5 += wgt * x1.y; a6 += wgt * x1.z; a7 += wgt * x1.w;
    }
    __half* op = out + ((size_t)rowidx + i_row) * 256 + lane * 8;
    ((half2*)op)[0] = __floats2half2_rn(a0 * inv, a1 * inv);
    ((half2*)op)[1] = __floats2half2_rn(a2 * inv, a3 * inv);
    ((half2*)op)[2] = __floats2half2_rn(a4 * inv, a5 * inv);
    ((half2*)op)[3] = __floats2half2_rn(a6 * inv, a7 * inv);
}

// ---------------- partial mean over L per (head,batch): 8 chunks of 128 ----------------
__global__ void __launch_bounds__(256)
mean_kernel(const __half* __restrict__ o, float* __restrict__ meanp)
{
    int z = blockIdx.x;
    int ch = blockIdx.y;
    int c = threadIdx.x;
    const __half* p = o + (size_t)z * 262144 + (size_t)ch * 128 * 256 + c;
    float s = 0.f;
    for (int l = 0; l < 128; l++) s += __half2float(p[(size_t)l * 256]);
    meanp[(z * 8 + ch) * 256 + c] = s;
}

// ---------------- final projections + LN ----------------
__global__ void __launch_bounds__(256)
final_kernel(const float* __restrict__ meanp,
             const float* __restrict__ Wl, const float* __restrict__ bl,
             const float* __restrict__ Ws, const float* __restrict__ bs,
             const float* __restrict__ Wc, const float* __restrict__ bc,
             const float* __restrict__ gl, const float* __restrict__ betal,
             const float* __restrict__ gs, const float* __restrict__ betas,
             const float* __restrict__ gc, const float* __restrict__ betac,
             float* __restrict__ outp)
{
    const int b = blockIdx.x, type = blockIdx.y, tid = threadIdx.x;
    __shared__ float v[1024];
    __shared__ float red[256];

    const float *W, *bias, *g, *beta;
    int K, hbase;
    if (type == 0)      { W = Wl; bias = bl; g = gl; beta = betal; K = 512;  hbase = 0; }
    else if (type == 1) { W = Ws; bias = bs; g = gs; beta = betas; K = 512;  hbase = 2; }
    else                { W = Wc; bias = bc; g = gc; beta = betac; K = 1024; hbase = 0; }

    for (int k = tid; k < K; k += 256) {
        int head = hbase + (k >> 8);
        int c = k & 255;
        float s = 0.f;
#pragma unroll
        for (int c8 = 0; c8 < 8; c8++)
            s += meanp[((head * 16 + b) * 8 + c8) * 256 + c];
        v[k] = s * (1.f / 1024.f);
    }
    __syncthreads();

    float acc[3];
#pragma unroll
    for (int q = 0; q < 3; q++) {
        int c = tid + q * 256;
        float s = bias[c];
        for (int k = 0; k < K; k++) s += v[k] * W[(size_t)k * 768 + c];
        acc[q] = s;
    }

    red[tid] = acc[0] + acc[1] + acc[2];
    __syncthreads();
    for (int off = 128; off > 0; off >>= 1) {
        if (tid < off) red[tid] += red[tid + off];
        __syncthreads();
    }
    float mu = red[0] * (1.f / 768.f);
    __syncthreads();
    float d0 = acc[0] - mu, d1 = acc[1] - mu, d2 = acc[2] - mu;
    red[tid] = d0 * d0 + d1 * d1 + d2 * d2;
    __syncthreads();
    for (int off = 128; off > 0; off >>= 1) {
        if (tid < off) red[tid] += red[tid + off];
        __syncthreads();
    }
    float rstd = rsqrtf(red[0] * (1.f / 768.f) + 1e-5f);
    __syncthreads();

#pragma unroll
    for (int q = 0; q < 3; q++) {
        int c = tid + q * 256;
        outp[(size_t)type * 16 * 768 + (size_t)b * 768 + c] =
            (acc[q] - mu) * rstd * g[c] + beta[c];
    }
}

// ---------------- launch ----------------
extern "C" void kernel_launch(void* const* d_in, const int* in_sizes, int n_in,
                              void* d_out, int out_size)
{
    const float* x      = (const float*)d_in[0];
    const float* Wfc    = (const float*)d_in[1];
    const float* bfc    = (const float*)d_in[2];
    const float* lng    = (const float*)d_in[3];
    const float* lnb    = (const float*)d_in[4];
    const float* adjw   = (const float*)d_in[5];
    const float* Watt   = (const float*)d_in[6];
    const float* batt   = (const float*)d_in[7];
    const float* Wl     = (const float*)d_in[8];
    const float* bl     = (const float*)d_in[9];
    const float* Ws     = (const float*)d_in[10];
    const float* bs     = (const float*)d_in[11];
    const float* Wc     = (const float*)d_in[12];
    const float* bc     = (const float*)d_in[13];
    const float* gl     = (const float*)d_in[14];
    const float* betal  = (const float*)d_in[15];
    const float* gs     = (const float*)d_in[16];
    const float* betas  = (const float*)d_in[17];
    const float* gc     = (const float*)d_in[18];
    const float* betac  = (const float*)d_in[19];
    float* outp = (float*)d_out;

    float *h, *tmp, *esrc, *edst, *meanp;
    __half *htf, *gg, *A, *ob, *xh, *wh, *ah;
    cudaGetSymbolAddress((void**)&h,     g_h);
    cudaGetSymbolAddress((void**)&htf,   g_htf);
    cudaGetSymbolAddress((void**)&tmp,   g_tmp);
    cudaGetSymbolAddress((void**)&gg,    g_g);
    cudaGetSymbolAddress((void**)&A,     g_A);
    cudaGetSymbolAddress((void**)&ob,    g_out);
    cudaGetSymbolAddress((void**)&esrc,  g_esrc);
    cudaGetSymbolAddress((void**)&edst,  g_edst);
    cudaGetSymbolAddress((void**)&meanp, g_meanp);
    cudaGetSymbolAddress((void**)&xh,    g_xh);
    cudaGetSymbolAddress((void**)&wh,    g_wh);
    cudaGetSymbolAddress((void**)&ah,    g_ah);

    cudaFuncSetAttribute(attn_warp,
                         cudaFuncAttributeMaxDynamicSharedMemorySize, ATTN_SMEM);

    // K0: convert operands to fp16 (+ transpose weights to NxK)
    conv_half<<<(16 * 1024 * 768 / 2 + 255) / 256, 256>>>(x, xh, 16 * 1024 * 768 / 2);
    convT_half<<<dim3(24, 8, 4), 256>>>(Wfc, wh, 768, 256);
    convT_half<<<dim3(8, 8, 4), 256>>>(adjw, ah, 256, 256);

    // K1: pre = x @ Wfc + bfc  (fp16 MMA; B = Wfc^T NxK)
    hgemm<false, true, false><<<dim3(2, 128, 4), 256>>>(
        xh, wh, tmp, bfc, 256, 768,
        (size_t)0, (size_t)256 * 768, (size_t)16384 * 256, (size_t)256);
    // K2: LN + e_src/e_dst (+ fp16 h copy)
    ln_esrc_kernel<<<8192, 256>>>(tmp, h, htf, lng, lnb, Watt, esrc, edst);
    // K3: g = h @ adjw  (fp16 MMA; B = adjw^T NxK; fp16 output)
    hgemm<false, false, true><<<dim3(2, 128, 4), 256>>>(
        htf, ah, gg, nullptr, 256, 256,
        (size_t)16384 * 256, (size_t)256 * 256, (size_t)16384 * 256, (size_t)0);
    // K4: A = sigmoid(g @ h^T) per (head,batch), fp16 in/out, fast sigmoid
    hgemm<true, false, true><<<dim3(8, 8, 64), 256>>>(
        gg, htf, A, nullptr, 1024, 256,
        (size_t)1024 * 256, (size_t)1024 * 256, (size_t)1024 * 1024, (size_t)0);
    // K5: warp-per-row quantile (fast-path) + masked softmax + sparse alpha@h
    attn_warp<<<dim3(128, 16, 4), 256, ATTN_SMEM>>>(A, h, esrc, edst, batt, ob);
    // K6: partial mean over L (fp16 input)
    mean_kernel<<<dim3(64, 8), 256>>>(ob, meanp);
    // K7: final projections + LN
    final_kernel<<<dim3(16, 3), 256>>>(meanp, Wl, bl, Ws, bs, Wc, bc,
                                       gl, betal, gs, betas, gc, betac, outp);
}